// round 6
// baseline (speedup 1.0000x reference)
#include <cuda_runtime.h>
#include <cstdint>

#define TT 2048
#define DD 1024
#define HH 16
#define HSZ 64
#define DFF 4096

// ---------------- scratch (no allocs allowed) ----------------
__device__ float g_h[TT * DD];            // LN output (tf32-rounded)
__device__ float g_wqkvT[3 * DD * DD];    // QKV weights, [3D][D] K-major (tf32)
__device__ float g_WoT[DD * DD];          // Wo^T  [D][D] (tf32)
__device__ float g_W1T[DD * DFF];         // W1^T  [DFF][D] (tf32)
__device__ float g_W2T[DFF * DD];         // W2^T  [D][DFF] (tf32)
__device__ float g_qkv[TT * 3 * DD];      // QKV activations [T, 3D] (tf32)
__device__ float g_att[TT * DD];          // attention output [T, D] (tf32)
__device__ float g_x2[TT * DD];           // residual after attention (fp32)
__device__ float g_ff[TT * DFF];          // FFN hidden (tf32)

// ---------------- helpers ----------------
__device__ __forceinline__ uint32_t smem_u32(const void* p) {
    return (uint32_t)__cvta_generic_to_shared(p);
}
__device__ __forceinline__ float f2tf32(float x) {
    uint32_t r;
    asm("cvt.rna.tf32.f32 %0, %1;" : "=r"(r) : "f"(x));
    return __uint_as_float(r);
}
__device__ __forceinline__ uint32_t swz(uint32_t off) {   // SW128 swizzle
    return off ^ ((off >> 3) & 0x70);
}
__device__ __forceinline__ void mma_tf32(
    float& d0, float& d1, float& d2, float& d3,
    uint32_t a0, uint32_t a1, uint32_t a2, uint32_t a3,
    uint32_t b0, uint32_t b1)
{
    asm volatile(
        "mma.sync.aligned.m16n8k8.row.col.f32.tf32.tf32.f32 "
        "{%0,%1,%2,%3}, {%4,%5,%6,%7}, {%8,%9}, {%0,%1,%2,%3};\n"
        : "+f"(d0), "+f"(d1), "+f"(d2), "+f"(d3)
        : "r"(a0), "r"(a1), "r"(a2), "r"(a3), "r"(b0), "r"(b1));
}
__device__ __forceinline__ void ldmx4(
    uint32_t& r0, uint32_t& r1, uint32_t& r2, uint32_t& r3, uint32_t addr)
{
    asm volatile("ldmatrix.sync.aligned.m8n8.x4.shared.b16 {%0,%1,%2,%3}, [%4];"
                 : "=r"(r0), "=r"(r1), "=r"(r2), "=r"(r3) : "r"(addr));
}
__device__ __forceinline__ void cpasync16(uint32_t saddr, const void* gaddr) {
    asm volatile("cp.async.cg.shared.global [%0], [%1], 16;" :: "r"(saddr), "l"(gaddr));
}
#define CP_COMMIT() asm volatile("cp.async.commit_group;" ::: "memory")
#define CP_WAIT(n)  asm volatile("cp.async.wait_group %0;" :: "n"(n) : "memory")

// ---------------- LayerNorm (emits tf32-rounded values) ----------------
__global__ __launch_bounds__(256) void ln_kernel(
    const float* __restrict__ x, const float* __restrict__ g,
    const float* __restrict__ b, float* __restrict__ y)
{
    int row = blockIdx.x;
    int tid = threadIdx.x;
    float4 v = reinterpret_cast<const float4*>(x + (size_t)row * DD)[tid];
    float s  = v.x + v.y + v.z + v.w;
    float ss = v.x * v.x + v.y * v.y + v.z * v.z + v.w * v.w;
    #pragma unroll
    for (int o = 16; o > 0; o >>= 1) {
        s  += __shfl_xor_sync(0xffffffffu, s, o);
        ss += __shfl_xor_sync(0xffffffffu, ss, o);
    }
    __shared__ float sb[8], ssb[8], stats[2];
    int wid = tid >> 5, lane = tid & 31;
    if (lane == 0) { sb[wid] = s; ssb[wid] = ss; }
    __syncthreads();
    if (tid == 0) {
        float a = 0.f, c = 0.f;
        #pragma unroll
        for (int i = 0; i < 8; i++) { a += sb[i]; c += ssb[i]; }
        float mean = a * (1.0f / DD);
        float var  = c * (1.0f / DD) - mean * mean;
        stats[0] = mean;
        stats[1] = rsqrtf(var + 1e-6f);
    }
    __syncthreads();
    float mean = stats[0], rstd = stats[1];
    float4 gg = reinterpret_cast<const float4*>(g)[tid];
    float4 bb = reinterpret_cast<const float4*>(b)[tid];
    float4 o;
    o.x = f2tf32((v.x - mean) * rstd * gg.x + bb.x);
    o.y = f2tf32((v.y - mean) * rstd * gg.y + bb.y);
    o.z = f2tf32((v.z - mean) * rstd * gg.z + bb.z);
    o.w = f2tf32((v.w - mean) * rstd * gg.w + bb.w);
    reinterpret_cast<float4*>(y + (size_t)row * DD)[tid] = o;
}

// ---------------- 32x32 tiled transpose (emits tf32-rounded) ----------------
__global__ __launch_bounds__(256) void transpose32(
    const float* __restrict__ in, float* __restrict__ out, int R, int C,
    int inChunkStride, int outChunkStride)
{
    __shared__ float t[32][33];
    const float* ip = in + (size_t)blockIdx.z * inChunkStride;
    float* op = out + (size_t)blockIdx.z * outChunkStride;
    int bx = blockIdx.x * 32;
    int by = blockIdx.y * 32;
    int x = threadIdx.x, y = threadIdx.y;
    #pragma unroll
    for (int j = 0; j < 32; j += 8)
        t[y + j][x] = ip[(size_t)(by + y + j) * C + bx + x];
    __syncthreads();
    #pragma unroll
    for (int j = 0; j < 32; j += 8)
        op[(size_t)(bx + y + j) * R + by + x] = f2tf32(t[x][y + j]);
}

// ---------------- tf32 mma.sync GEMM, cp.async 3-stage + ldmatrix ----------------
// C[M,N] = epi( A[M,K] row-major  x  Bt[N,K] K-major ^T )
// CTA 128x256, BK=32, 8 warps (2m x 4n), warp tile 64x64.
// stage: A 16KB + B 32KB = 48KB. 3 stages = 144KB.
// EPI: 0 = none+round, 1 = +bias+resid (fp32 out), 2 = relu(+bias)+round
#define TG_STAGE 49152
#define TG_SMEM  (3 * TG_STAGE)

template <int EPI>
__global__ __launch_bounds__(256, 1) void tg2(
    int M, int N, int K,
    const float* __restrict__ A, const float* __restrict__ Bt,
    const float* __restrict__ bias, const float* __restrict__ resid,
    float* __restrict__ C)
{
    extern __shared__ float dynsm[];
    const int tid  = threadIdx.x;
    const int warp = tid >> 5, lane = tid & 31;
    const int wm = warp & 1, wn = warp >> 1;
    const int g = lane >> 2, tg = lane & 3;
    const int brow = blockIdx.y, bcol = blockIdx.x;

    const uint32_t sbase = smem_u32(dynsm);
    const int r0 = tid >> 3;      // 0..31
    const int ck = tid & 7;       // 16B chunk 0..7
    const float* Ab = A  + (size_t)(brow * 128) * K + ck * 4;
    const float* Bb = Bt + (size_t)(bcol * 256) * K + ck * 4;
    const int KT = K >> 5;

    // ldmatrix lane offsets (validated pattern from R5)
    const int aRow = (lane & 7) + ((lane >> 3) & 1) * 8;
    const int aChk = (lane >> 4);
    const int bRow = (lane & 7) + (lane >> 4) * 8;
    const int bChk = (lane >> 3) & 1;

    float acc[4][8][4];
    #pragma unroll
    for (int mt = 0; mt < 4; mt++)
        #pragma unroll
        for (int nt = 0; nt < 8; nt++)
            #pragma unroll
            for (int i = 0; i < 4; i++) acc[mt][nt][i] = 0.f;

    auto load_stage = [&](int kt, int s) {
        const uint32_t sA = sbase + s * TG_STAGE;
        const uint32_t sB = sA + 16384;
        const int k0 = kt * 32;
        #pragma unroll
        for (int j = 0; j < 4; ++j) {
            const int r = j * 32 + r0;
            const uint32_t off = swz((uint32_t)(r * 128 + ck * 16));
            cpasync16(sA + off, Ab + (size_t)r * K + k0);
        }
        #pragma unroll
        for (int j = 0; j < 8; ++j) {
            const int r = j * 32 + r0;
            const uint32_t off = swz((uint32_t)(r * 128 + ck * 16));
            cpasync16(sB + off, Bb + (size_t)r * K + k0);
        }
        CP_COMMIT();
    };

    load_stage(0, 0);
    load_stage(1, 1);

    for (int kt = 0; kt < KT; ++kt) {
        if (kt + 1 < KT) CP_WAIT(1); else CP_WAIT(0);
        __syncthreads();
        if (kt + 2 < KT) load_stage(kt + 2, (kt + 2) % 3);

        const uint32_t sA = sbase + (kt % 3) * TG_STAGE;
        const uint32_t sB = sA + 16384;

        #pragma unroll
        for (int ks = 0; ks < 4; ++ks) {
            const int chunkA = ks * 2;
            uint32_t af[4][4];
            #pragma unroll
            for (int mt = 0; mt < 4; ++mt) {
                const int row = wm * 64 + mt * 16 + aRow;
                const uint32_t ad = sA + swz((uint32_t)(row * 128 + (chunkA + aChk) * 16));
                ldmx4(af[mt][0], af[mt][1], af[mt][2], af[mt][3], ad);
            }
            uint32_t bf[8][2];
            #pragma unroll
            for (int np = 0; np < 4; ++np) {
                const int nrow = wn * 64 + np * 16 + bRow;
                const uint32_t bd = sB + swz((uint32_t)(nrow * 128 + (chunkA + bChk) * 16));
                uint32_t t0, t1, t2, t3;
                ldmx4(t0, t1, t2, t3, bd);
                bf[np * 2][0] = t0;     bf[np * 2][1] = t1;
                bf[np * 2 + 1][0] = t2; bf[np * 2 + 1][1] = t3;
            }
            #pragma unroll
            for (int mt = 0; mt < 4; ++mt)
                #pragma unroll
                for (int nt = 0; nt < 8; ++nt)
                    mma_tf32(acc[mt][nt][0], acc[mt][nt][1],
                             acc[mt][nt][2], acc[mt][nt][3],
                             af[mt][0], af[mt][1], af[mt][2], af[mt][3],
                             bf[nt][0], bf[nt][1]);
        }
    }

    // ---------------- epilogue ----------------
    #pragma unroll
    for (int mt = 0; mt < 4; mt++) {
        const int r0g = brow * 128 + wm * 64 + mt * 16 + g;
        const int r1g = r0g + 8;
        #pragma unroll
        for (int nt = 0; nt < 8; nt++) {
            const int c = bcol * 256 + wn * 64 + nt * 8 + tg * 2;
            float2 o0 = make_float2(acc[mt][nt][0], acc[mt][nt][1]);
            float2 o1 = make_float2(acc[mt][nt][2], acc[mt][nt][3]);
            if constexpr (EPI >= 1) {
                float2 bv = *reinterpret_cast<const float2*>(bias + c);
                o0.x += bv.x; o0.y += bv.y;
                o1.x += bv.x; o1.y += bv.y;
            }
            if constexpr (EPI == 1) {
                float2 rv0 = *reinterpret_cast<const float2*>(resid + (size_t)r0g * N + c);
                float2 rv1 = *reinterpret_cast<const float2*>(resid + (size_t)r1g * N + c);
                o0.x += rv0.x; o0.y += rv0.y;
                o1.x += rv1.x; o1.y += rv1.y;
            }
            if constexpr (EPI == 2) {
                o0.x = fmaxf(o0.x, 0.f); o0.y = fmaxf(o0.y, 0.f);
                o1.x = fmaxf(o1.x, 0.f); o1.y = fmaxf(o1.y, 0.f);
            }
            if constexpr (EPI == 0 || EPI == 2) {   // feeds another GEMM: round to tf32
                o0.x = f2tf32(o0.x); o0.y = f2tf32(o0.y);
                o1.x = f2tf32(o1.x); o1.y = f2tf32(o1.y);
            }
            *reinterpret_cast<float2*>(C + (size_t)r0g * N + c) = o0;
            *reinterpret_cast<float2*>(C + (size_t)r1g * N + c) = o1;
        }
    }
}

// ---------------- fast exp2 (fma pipe) ----------------
__device__ __forceinline__ float fexp2(float x) {
    x = fmaxf(x, -120.f);
    float k  = __fadd_rn(x, 12582912.f);
    int   sc = __float_as_int(k) << 23;
    float f  = __fsub_rn(x, __fsub_rn(k, 12582912.f));
    float p  = 0.0013333558f;
    p = fmaf(p, f, 0.0096181291f);
    p = fmaf(p, f, 0.0555041087f);
    p = fmaf(p, f, 0.2402265070f);
    p = fmaf(p, f, 0.6931471806f);
    p = fmaf(p, f, 1.0f);
    return __int_as_float(__float_as_int(p) + sc);
}

// ---------------- tensor-core flash attention ----------------
#define QS_S 68
#define KS_S 68
#define VS_S 72
#define PS_S 68
#define FA_SMEM ((128*QS_S + 64*KS_S + 64*VS_S + 128*PS_S) * 4)

__global__ __launch_bounds__(256, 2) void flash_tc(
    const float* __restrict__ qkv, float* __restrict__ out)
{
    extern __shared__ float sm[];
    float* Qs = sm;
    float* Ks = Qs + 128 * QS_S;
    float* Vs = Ks + 64 * KS_S;
    float* Ps = Vs + 64 * VS_S;

    const int tid  = threadIdx.x;
    const int warp = tid >> 5;
    const int lane = tid & 31;
    const int g    = lane >> 2;
    const int tg   = lane & 3;
    const int qb   = gridDim.x - 1 - blockIdx.x;
    const int h    = blockIdx.y;
    const int q0   = qb * 128;
    const int w16  = warp * 16;

    const float* qp = qkv + h * HSZ;
    const float* kp = qkv + DD + h * HSZ;
    const float* vp = qkv + 2 * DD + h * HSZ;

    for (int i = tid; i < 128 * 64; i += 256) {
        int r = i >> 6, d = i & 63;
        Qs[r * QS_S + d] = qp[(size_t)(q0 + r) * (3 * DD) + d];
    }

    float O[8][4];
    #pragma unroll
    for (int nt = 0; nt < 8; nt++)
        #pragma unroll
        for (int i = 0; i < 4; i++) O[nt][i] = 0.f;
    float m0 = -1e30f, m1 = -1e30f, l0 = 0.f, l1 = 0.f;

    const int row0 = q0 + w16 + g;
    const int row1 = row0 + 8;
    const float SC = 0.18033688011112042f;
    const int nkt = 2 * qb + 2;

    for (int kt = 0; kt < nkt; ++kt) {
        __syncthreads();
        for (int i = tid; i < 64 * 64; i += 256) {
            int r = i >> 6, d = i & 63;
            size_t gi = (size_t)(kt * 64 + r) * (3 * DD) + d;
            Ks[r * KS_S + d] = kp[gi];
            Vs[r * VS_S + d] = vp[gi];
        }
        __syncthreads();

        float s[8][4];
        #pragma unroll
        for (int nt = 0; nt < 8; nt++)
            #pragma unroll
            for (int i = 0; i < 4; i++) s[nt][i] = 0.f;

        #pragma unroll
        for (int kk = 0; kk < 8; ++kk) {
            const float* qr = &Qs[(w16 + g) * QS_S + kk * 8];
            uint32_t a0 = __float_as_uint(qr[tg]);
            uint32_t a1 = __float_as_uint(qr[8 * QS_S + tg]);
            uint32_t a2 = __float_as_uint(qr[tg + 4]);
            uint32_t a3 = __float_as_uint(qr[8 * QS_S + tg + 4]);
            #pragma unroll
            for (int nt = 0; nt < 8; ++nt) {
                const float* kr = &Ks[(nt * 8 + g) * KS_S + kk * 8];
                uint32_t b0 = __float_as_uint(kr[tg]);
                uint32_t b1 = __float_as_uint(kr[tg + 4]);
                mma_tf32(s[nt][0], s[nt][1], s[nt][2], s[nt][3],
                         a0, a1, a2, a3, b0, b1);
            }
        }

        float mb0 = -1e30f, mb1 = -1e30f;
        #pragma unroll
        for (int nt = 0; nt < 8; ++nt) {
            int c0 = kt * 64 + nt * 8 + 2 * tg;
            float z0 = (c0     > row0) ? -1e30f : s[nt][0] * SC;
            float z1 = (c0 + 1 > row0) ? -1e30f : s[nt][1] * SC;
            float z2 = (c0     > row1) ? -1e30f : s[nt][2] * SC;
            float z3 = (c0 + 1 > row1) ? -1e30f : s[nt][3] * SC;
            s[nt][0] = z0; s[nt][1] = z1; s[nt][2] = z2; s[nt][3] = z3;
            mb0 = fmaxf(mb0, fmaxf(z0, z1));
            mb1 = fmaxf(mb1, fmaxf(z2, z3));
        }
        mb0 = fmaxf(mb0, __shfl_xor_sync(0xffffffffu, mb0, 1));
        mb0 = fmaxf(mb0, __shfl_xor_sync(0xffffffffu, mb0, 2));
        mb1 = fmaxf(mb1, __shfl_xor_sync(0xffffffffu, mb1, 1));
        mb1 = fmaxf(mb1, __shfl_xor_sync(0xffffffffu, mb1, 2));

        float mn0 = fmaxf(m0, mb0), mn1 = fmaxf(m1, mb1);
        float al0 = fexp2(m0 - mn0), al1 = fexp2(m1 - mn1);
        m0 = mn0; m1 = mn1;

        float rs0 = 0.f, rs1 = 0.f;
        float* pw = &Ps[(w16 + g) * PS_S];
        #pragma unroll
        for (int nt = 0; nt < 8; ++nt) {
            float p0 = fexp2(s[nt][0] - mn0);
            float p1 = fexp2(s[nt][1] - mn0);
            float p2 = fexp2(s[nt][2] - mn1);
            float p3 = fexp2(s[nt][3] - mn1);
            rs0 += p0 + p1; rs1 += p2 + p3;
            pw[nt * 8 + 2 * tg]              = f2tf32(p0);
            pw[nt * 8 + 2 * tg + 1]          = f2tf32(p1);
            pw[8 * PS_S + nt * 8 + 2 * tg]     = f2tf32(p2);
            pw[8 * PS_S + nt * 8 + 2 * tg + 1] = f2tf32(p3);
        }
        rs0 += __shfl_xor_sync(0xffffffffu, rs0, 1);
        rs0 += __shfl_xor_sync(0xffffffffu, rs0, 2);
        rs1 += __shfl_xor_sync(0xffffffffu, rs1, 1);
        rs1 += __shfl_xor_sync(0xffffffffu, rs1, 2);
        l0 = l0 * al0 + rs0;
        l1 = l1 * al1 + rs1;

        #pragma unroll
        for (int nt = 0; nt < 8; ++nt) {
            O[nt][0] *= al0; O[nt][1] *= al0;
            O[nt][2] *= al1; O[nt][3] *= al1;
        }
        __syncwarp();

        #pragma unroll
        for (int kk = 0; kk < 8; ++kk) {
            const float* pr = &Ps[(w16 + g) * PS_S + kk * 8];
            uint32_t a0 = __float_as_uint(pr[tg]);
            uint32_t a1 = __float_as_uint(pr[8 * PS_S + tg]);
            uint32_t a2 = __float_as_uint(pr[tg + 4]);
            uint32_t a3 = __float_as_uint(pr[8 * PS_S + tg + 4]);
            #pragma unroll
            for (int nt = 0; nt < 8; ++nt) {
                uint32_t b0 = __float_as_uint(Vs[(kk * 8 + tg) * VS_S + nt * 8 + g]);
                uint32_t b1 = __float_as_uint(Vs[(kk * 8 + tg + 4) * VS_S + nt * 8 + g]);
                mma_tf32(O[nt][0], O[nt][1], O[nt][2], O[nt][3],
                         a0, a1, a2, a3, b0, b1);
            }
        }
    }

    // normalize + round to tf32 (feeds Wo GEMM) + write
    float inv0 = 1.0f / l0, inv1 = 1.0f / l1;
    #pragma unroll
    for (int nt = 0; nt < 8; ++nt) {
        int c = h * HSZ + nt * 8 + 2 * tg;
        float2 o0 = make_float2(f2tf32(O[nt][0] * inv0), f2tf32(O[nt][1] * inv0));
        float2 o1 = make_float2(f2tf32(O[nt][2] * inv1), f2tf32(O[nt][3] * inv1));
        *reinterpret_cast<float2*>(out + (size_t)row0 * DD + c) = o0;
        *reinterpret_cast<float2*>(out + (size_t)row1 * DD + c) = o1;
    }
}

// ---------------- launch ----------------
extern "C" void kernel_launch(void* const* d_in, const int* in_sizes, int n_in,
                              void* d_out, int out_size)
{
    const float* x    = (const float*)d_in[0];
    const float* Wq   = (const float*)d_in[1];
    const float* Wk   = (const float*)d_in[2];
    const float* Wv   = (const float*)d_in[3];
    const float* Wo   = (const float*)d_in[4];
    const float* bo   = (const float*)d_in[5];
    const float* W1   = (const float*)d_in[6];
    const float* b1   = (const float*)d_in[7];
    const float* W2   = (const float*)d_in[8];
    const float* b2   = (const float*)d_in[9];
    const float* ln1s = (const float*)d_in[10];
    const float* ln1b = (const float*)d_in[11];
    const float* ln2s = (const float*)d_in[12];
    const float* ln2b = (const float*)d_in[13];
    float* out = (float*)d_out;

    float *h, *wqkvT, *woT, *w1T, *w2T, *qkv, *att, *x2, *ff;
    cudaGetSymbolAddress((void**)&h,     g_h);
    cudaGetSymbolAddress((void**)&wqkvT, g_wqkvT);
    cudaGetSymbolAddress((void**)&woT,   g_WoT);
    cudaGetSymbolAddress((void**)&w1T,   g_W1T);
    cudaGetSymbolAddress((void**)&w2T,   g_W2T);
    cudaGetSymbolAddress((void**)&qkv,   g_qkv);
    cudaGetSymbolAddress((void**)&att,   g_att);
    cudaGetSymbolAddress((void**)&x2,    g_x2);
    cudaGetSymbolAddress((void**)&ff,    g_ff);

    cudaFuncSetAttribute(flash_tc, cudaFuncAttributeMaxDynamicSharedMemorySize, FA_SMEM);
    cudaFuncSetAttribute(tg2<0>, cudaFuncAttributeMaxDynamicSharedMemorySize, TG_SMEM);
    cudaFuncSetAttribute(tg2<1>, cudaFuncAttributeMaxDynamicSharedMemorySize, TG_SMEM);
    cudaFuncSetAttribute(tg2<2>, cudaFuncAttributeMaxDynamicSharedMemorySize, TG_SMEM);

    dim3 tb(32, 8);

    // 1. LN1
    ln_kernel<<<TT, 256>>>(x, ln1s, ln1b, h);
    // 2. weight transposes -> K-major tf32 B operands
    transpose32<<<dim3(2, 32, 16), tb>>>(Wq, wqkvT,           DD, HSZ, DD*HSZ, HSZ*DD);
    transpose32<<<dim3(2, 32, 16), tb>>>(Wk, wqkvT + DD*DD,   DD, HSZ, DD*HSZ, HSZ*DD);
    transpose32<<<dim3(2, 32, 16), tb>>>(Wv, wqkvT + 2*DD*DD, DD, HSZ, DD*HSZ, HSZ*DD);
    transpose32<<<dim3(32, 32, 1),  tb>>>(Wo, woT, DD, DD, 0, 0);
    transpose32<<<dim3(128, 32, 1), tb>>>(W1, w1T, DD, DFF, 0, 0);
    transpose32<<<dim3(32, 128, 1), tb>>>(W2, w2T, DFF, DD, 0, 0);
    // 3. QKV GEMM: [T,D] x [D,3D] -> [T,3D]  (rounded output)
    tg2<0><<<dim3(3 * DD / 256, TT / 128), 256, TG_SMEM>>>(
        TT, 3 * DD, DD, h, wqkvT, nullptr, nullptr, qkv);
    // 4. causal flash attention -> [T,D] (rounded output)
    flash_tc<<<dim3(TT / 128, HH), 256, FA_SMEM>>>(qkv, att);
    // 5. output proj + bias + residual (fp32 output)
    tg2<1><<<dim3(DD / 256, TT / 128), 256, TG_SMEM>>>(
        TT, DD, DD, att, woT, bo, x, x2);
    // 6. LN2
    ln_kernel<<<TT, 256>>>(x2, ln2s, ln2b, h);
    // 7. FFN1 (rounded output)
    tg2<2><<<dim3(DFF / 256, TT / 128), 256, TG_SMEM>>>(
        TT, DFF, DD, h, w1T, b1, nullptr, ff);
    // 8. FFN2 (fp32 output)
    tg2<1><<<dim3(DD / 256, TT / 128), 256, TG_SMEM>>>(
        TT, DD, DFF, ff, w2T, b2, x2, out);
}

// round 7
// speedup vs baseline: 1.1342x; 1.1342x over previous
#include <cuda_runtime.h>
#include <cstdint>

#define TT 2048
#define DD 1024
#define HH 16
#define HSZ 64
#define DFF 4096

// ---------------- scratch (no allocs allowed) ----------------
__device__ float g_h[TT * DD];            // LN output (tf32-rounded)
__device__ float g_wqkvT[3 * DD * DD];    // QKV weights, [3D][D] K-major (tf32)
__device__ float g_WoT[DD * DD];          // Wo^T  [D][D] (tf32)
__device__ float g_W1T[DD * DFF];         // W1^T  [DFF][D] (tf32)
__device__ float g_W2T[DFF * DD];         // W2^T  [D][DFF] (tf32)
__device__ float g_qkv[TT * 3 * DD];      // QKV activations [T, 3D] (tf32)
__device__ float g_att[TT * DD];          // attention output [T, D] (tf32)
__device__ float g_x2[TT * DD];           // residual after attention (fp32)
__device__ float g_ff[TT * DFF];          // FFN hidden (tf32)

// ---------------- helpers ----------------
__device__ __forceinline__ uint32_t smem_u32(const void* p) {
    return (uint32_t)__cvta_generic_to_shared(p);
}
__device__ __forceinline__ float f2tf32(float x) {
    uint32_t r;
    asm("cvt.rna.tf32.f32 %0, %1;" : "=r"(r) : "f"(x));
    return __uint_as_float(r);
}
__device__ __forceinline__ uint32_t swz(uint32_t off) {   // SW128 swizzle
    return off ^ ((off >> 3) & 0x70);
}
__device__ __forceinline__ void mma_tf32(
    float& d0, float& d1, float& d2, float& d3,
    uint32_t a0, uint32_t a1, uint32_t a2, uint32_t a3,
    uint32_t b0, uint32_t b1)
{
    asm volatile(
        "mma.sync.aligned.m16n8k8.row.col.f32.tf32.tf32.f32 "
        "{%0,%1,%2,%3}, {%4,%5,%6,%7}, {%8,%9}, {%0,%1,%2,%3};\n"
        : "+f"(d0), "+f"(d1), "+f"(d2), "+f"(d3)
        : "r"(a0), "r"(a1), "r"(a2), "r"(a3), "r"(b0), "r"(b1));
}
__device__ __forceinline__ void ldmx4(
    uint32_t& r0, uint32_t& r1, uint32_t& r2, uint32_t& r3, uint32_t addr)
{
    asm volatile("ldmatrix.sync.aligned.m8n8.x4.shared.b16 {%0,%1,%2,%3}, [%4];"
                 : "=r"(r0), "=r"(r1), "=r"(r2), "=r"(r3) : "r"(addr) : "memory");
}
__device__ __forceinline__ void cpasync16(uint32_t saddr, const void* gaddr) {
    asm volatile("cp.async.cg.shared.global [%0], [%1], 16;" :: "r"(saddr), "l"(gaddr));
}
#define CP_COMMIT() asm volatile("cp.async.commit_group;" ::: "memory")
#define CP_WAIT(n)  asm volatile("cp.async.wait_group %0;" :: "n"(n) : "memory")

// ---------------- LayerNorm (emits tf32-rounded values) ----------------
__global__ __launch_bounds__(256) void ln_kernel(
    const float* __restrict__ x, const float* __restrict__ g,
    const float* __restrict__ b, float* __restrict__ y)
{
    int row = blockIdx.x;
    int tid = threadIdx.x;
    float4 v = reinterpret_cast<const float4*>(x + (size_t)row * DD)[tid];
    float s  = v.x + v.y + v.z + v.w;
    float ss = v.x * v.x + v.y * v.y + v.z * v.z + v.w * v.w;
    #pragma unroll
    for (int o = 16; o > 0; o >>= 1) {
        s  += __shfl_xor_sync(0xffffffffu, s, o);
        ss += __shfl_xor_sync(0xffffffffu, ss, o);
    }
    __shared__ float sb[8], ssb[8], stats[2];
    int wid = tid >> 5, lane = tid & 31;
    if (lane == 0) { sb[wid] = s; ssb[wid] = ss; }
    __syncthreads();
    if (tid == 0) {
        float a = 0.f, c = 0.f;
        #pragma unroll
        for (int i = 0; i < 8; i++) { a += sb[i]; c += ssb[i]; }
        float mean = a * (1.0f / DD);
        float var  = c * (1.0f / DD) - mean * mean;
        stats[0] = mean;
        stats[1] = rsqrtf(var + 1e-6f);
    }
    __syncthreads();
    float mean = stats[0], rstd = stats[1];
    float4 gg = reinterpret_cast<const float4*>(g)[tid];
    float4 bb = reinterpret_cast<const float4*>(b)[tid];
    float4 o;
    o.x = f2tf32((v.x - mean) * rstd * gg.x + bb.x);
    o.y = f2tf32((v.y - mean) * rstd * gg.y + bb.y);
    o.z = f2tf32((v.z - mean) * rstd * gg.z + bb.z);
    o.w = f2tf32((v.w - mean) * rstd * gg.w + bb.w);
    reinterpret_cast<float4*>(y + (size_t)row * DD)[tid] = o;
}

// ---------------- 32x32 tiled transpose (emits tf32-rounded) ----------------
__global__ __launch_bounds__(256) void transpose32(
    const float* __restrict__ in, float* __restrict__ out, int R, int C,
    int inChunkStride, int outChunkStride)
{
    __shared__ float t[32][33];
    const float* ip = in + (size_t)blockIdx.z * inChunkStride;
    float* op = out + (size_t)blockIdx.z * outChunkStride;
    int bx = blockIdx.x * 32;
    int by = blockIdx.y * 32;
    int x = threadIdx.x, y = threadIdx.y;
    #pragma unroll
    for (int j = 0; j < 32; j += 8)
        t[y + j][x] = ip[(size_t)(by + y + j) * C + bx + x];
    __syncthreads();
    #pragma unroll
    for (int j = 0; j < 32; j += 8)
        op[(size_t)(bx + y + j) * R + by + x] = f2tf32(t[x][y + j]);
}

// ---------------- tf32 mma.sync GEMM (R5 geometry + rounding epilogue) ----------------
// CTA 128x128, BK=32, 8 warps (2x4), warp tile 64x32. 3 stages x 32KB = 96KB.
#define TG_STAGE 32768
#define TG_SMEM  (3 * TG_STAGE)

template <int EPI>
__global__ __launch_bounds__(256, 1) void tg2(
    int M, int N, int K,
    const float* __restrict__ A, const float* __restrict__ Bt,
    const float* __restrict__ bias, const float* __restrict__ resid,
    float* __restrict__ C)
{
    extern __shared__ float dynsm[];
    const int tid  = threadIdx.x;
    const int warp = tid >> 5, lane = tid & 31;
    const int wm = warp & 1, wn = warp >> 1;
    const int g = lane >> 2, tg = lane & 3;
    const int brow = blockIdx.y, bcol = blockIdx.x;

    const uint32_t sbase = smem_u32(dynsm);
    const int r0 = tid >> 3;
    const int ck = tid & 7;
    const float* Ab = A  + (size_t)(brow * 128) * K + ck * 4;
    const float* Bb = Bt + (size_t)(bcol * 128) * K + ck * 4;
    const int KT = K >> 5;

    const int aRow = (lane & 7) + ((lane >> 3) & 1) * 8;
    const int aChk = (lane >> 4);
    const int bRow = (lane & 7) + (lane >> 4) * 8;
    const int bChk = (lane >> 3) & 1;

    float acc[4][4][4];
    #pragma unroll
    for (int mt = 0; mt < 4; mt++)
        #pragma unroll
        for (int nt = 0; nt < 4; nt++)
            #pragma unroll
            for (int i = 0; i < 4; i++) acc[mt][nt][i] = 0.f;

    auto load_stage = [&](int kt, int s) {
        const uint32_t sA = sbase + s * TG_STAGE;
        const uint32_t sB = sA + 16384;
        const int k0 = kt * 32;
        #pragma unroll
        for (int j = 0; j < 4; ++j) {
            const int r = j * 32 + r0;
            const uint32_t off = swz((uint32_t)(r * 128 + ck * 16));
            cpasync16(sA + off, Ab + (size_t)r * K + k0);
            cpasync16(sB + off, Bb + (size_t)r * K + k0);
        }
        CP_COMMIT();
    };

    load_stage(0, 0);
    load_stage(1, 1);

    for (int kt = 0; kt < KT; ++kt) {
        if (kt + 1 < KT) CP_WAIT(1); else CP_WAIT(0);
        __syncthreads();
        if (kt + 2 < KT) load_stage(kt + 2, (kt + 2) % 3);

        const uint32_t sA = sbase + (kt % 3) * TG_STAGE;
        const uint32_t sB = sA + 16384;

        #pragma unroll
        for (int ks = 0; ks < 4; ++ks) {
            const int chunkA = ks * 2;
            uint32_t af[4][4];
            #pragma unroll
            for (int mt = 0; mt < 4; ++mt) {
                const int row = wm * 64 + mt * 16 + aRow;
                const uint32_t ad = sA + swz((uint32_t)(row * 128 + (chunkA + aChk) * 16));
                ldmx4(af[mt][0], af[mt][1], af[mt][2], af[mt][3], ad);
            }
            uint32_t bf[4][2];
            #pragma unroll
            for (int np = 0; np < 2; ++np) {
                const int nrow = wn * 32 + np * 16 + bRow;
                const uint32_t bd = sB + swz((uint32_t)(nrow * 128 + (chunkA + bChk) * 16));
                uint32_t t0, t1, t2, t3;
                ldmx4(t0, t1, t2, t3, bd);
                bf[np * 2][0] = t0;     bf[np * 2][1] = t1;
                bf[np * 2 + 1][0] = t2; bf[np * 2 + 1][1] = t3;
            }
            #pragma unroll
            for (int mt = 0; mt < 4; ++mt)
                #pragma unroll
                for (int nt = 0; nt < 4; ++nt)
                    mma_tf32(acc[mt][nt][0], acc[mt][nt][1],
                             acc[mt][nt][2], acc[mt][nt][3],
                             af[mt][0], af[mt][1], af[mt][2], af[mt][3],
                             bf[nt][0], bf[nt][1]);
        }
    }

    #pragma unroll
    for (int mt = 0; mt < 4; mt++) {
        const int r0g = brow * 128 + wm * 64 + mt * 16 + g;
        const int r1g = r0g + 8;
        #pragma unroll
        for (int nt = 0; nt < 4; nt++) {
            const int c = bcol * 128 + wn * 32 + nt * 8 + tg * 2;
            float2 o0 = make_float2(acc[mt][nt][0], acc[mt][nt][1]);
            float2 o1 = make_float2(acc[mt][nt][2], acc[mt][nt][3]);
            if constexpr (EPI >= 1) {
                float2 bv = *reinterpret_cast<const float2*>(bias + c);
                o0.x += bv.x; o0.y += bv.y;
                o1.x += bv.x; o1.y += bv.y;
            }
            if constexpr (EPI == 1) {
                float2 rv0 = *reinterpret_cast<const float2*>(resid + (size_t)r0g * N + c);
                float2 rv1 = *reinterpret_cast<const float2*>(resid + (size_t)r1g * N + c);
                o0.x += rv0.x; o0.y += rv0.y;
                o1.x += rv1.x; o1.y += rv1.y;
            }
            if constexpr (EPI == 2) {
                o0.x = fmaxf(o0.x, 0.f); o0.y = fmaxf(o0.y, 0.f);
                o1.x = fmaxf(o1.x, 0.f); o1.y = fmaxf(o1.y, 0.f);
            }
            if constexpr (EPI == 0 || EPI == 2) {   // feeds another GEMM
                o0.x = f2tf32(o0.x); o0.y = f2tf32(o0.y);
                o1.x = f2tf32(o1.x); o1.y = f2tf32(o1.y);
            }
            *reinterpret_cast<float2*>(C + (size_t)r0g * N + c) = o0;
            *reinterpret_cast<float2*>(C + (size_t)r1g * N + c) = o1;
        }
    }
}

// ---------------- fast exp2 (fma pipe) ----------------
__device__ __forceinline__ float fexp2(float x) {
    x = fmaxf(x, -120.f);
    float k  = __fadd_rn(x, 12582912.f);
    int   sc = __float_as_int(k) << 23;
    float f  = __fsub_rn(x, __fsub_rn(k, 12582912.f));
    float p  = 0.0013333558f;
    p = fmaf(p, f, 0.0096181291f);
    p = fmaf(p, f, 0.0555041087f);
    p = fmaf(p, f, 0.2402265070f);
    p = fmaf(p, f, 0.6931471806f);
    p = fmaf(p, f, 1.0f);
    return __int_as_float(__float_as_int(p) + sc);
}

// ---------------- flash attention v2: ldmatrix everywhere ----------------
// 128 q x 64 k tiles, 8 warps. All arrays stride FS=68 floats (272B, 16B-multiple).
// Qs [128][d], Ks [64 key][d], Vt [64 d][key] (transposed!), Ps [128][key].
#define FS 68
#define FA_SMEM (384 * FS * 4)

__global__ __launch_bounds__(256, 2) void flash_tc(
    const float* __restrict__ qkv, float* __restrict__ out)
{
    extern __shared__ float sm[];
    float* Qs = sm;
    float* Ks = Qs + 128 * FS;
    float* Vt = Ks + 64 * FS;
    float* Ps = Vt + 64 * FS;

    const int tid  = threadIdx.x;
    const int warp = tid >> 5;
    const int lane = tid & 31;
    const int g    = lane >> 2;
    const int tg   = lane & 3;
    const int qb   = gridDim.x - 1 - blockIdx.x;
    const int h    = blockIdx.y;
    const int q0   = qb * 128;
    const int w16  = warp * 16;

    const int aRow = (lane & 7) + ((lane >> 3) & 1) * 8;
    const int aChk = lane >> 4;
    const int bRow = (lane & 7) + (lane >> 4) * 8;
    const int bChk = (lane >> 3) & 1;

    const float* qp = qkv + h * HSZ;
    const float* kp = qkv + DD + h * HSZ;
    const float* vp = qkv + 2 * DD + h * HSZ;

    // load Q tile (float4)
    for (int i = tid; i < 128 * 16; i += 256) {
        int r = i >> 4, c4 = i & 15;
        float4 v = *reinterpret_cast<const float4*>(qp + (size_t)(q0 + r) * (3 * DD) + c4 * 4);
        *reinterpret_cast<float4*>(Qs + r * FS + c4 * 4) = v;
    }

    float O[8][4];
    #pragma unroll
    for (int nt = 0; nt < 8; nt++)
        #pragma unroll
        for (int i = 0; i < 4; i++) O[nt][i] = 0.f;
    float m0 = -1e30f, m1 = -1e30f, l0 = 0.f, l1 = 0.f;

    const int row0 = q0 + w16 + g;
    const int row1 = row0 + 8;
    const float SC = 0.18033688011112042f;   // (1/8) * log2(e)
    const int nkt = 2 * qb + 2;

    // frag base addresses
    const uint32_t qbase = smem_u32(Qs) + (uint32_t)((w16 + aRow) * FS * 4 + aChk * 16);
    const uint32_t kbase = smem_u32(Ks) + (uint32_t)(bRow * FS * 4 + bChk * 16);
    const uint32_t pbase = smem_u32(Ps) + (uint32_t)((w16 + aRow) * FS * 4 + aChk * 16);
    const uint32_t vbase = smem_u32(Vt) + (uint32_t)(bRow * FS * 4 + bChk * 16);

    for (int kt = 0; kt < nkt; ++kt) {
        __syncthreads();
        // K tile (float4), V tile transposed (scalar STS, 4-way ok)
        for (int i = tid; i < 64 * 16; i += 256) {
            int r = i >> 4, c4 = i & 15;
            float4 v = *reinterpret_cast<const float4*>(kp + (size_t)(kt * 64 + r) * (3 * DD) + c4 * 4);
            *reinterpret_cast<float4*>(Ks + r * FS + c4 * 4) = v;
        }
        for (int i = tid; i < 64 * 64; i += 256) {
            int r = i >> 6, d = i & 63;
            Vt[d * FS + r] = vp[(size_t)(kt * 64 + r) * (3 * DD) + d];
        }
        __syncthreads();

        // ---- S = Q K^T via ldmatrix frags ----
        float s[8][4];
        #pragma unroll
        for (int nt = 0; nt < 8; nt++)
            #pragma unroll
            for (int i = 0; i < 4; i++) s[nt][i] = 0.f;

        #pragma unroll
        for (int kk = 0; kk < 8; ++kk) {
            uint32_t a0, a1, a2, a3;
            ldmx4(a0, a1, a2, a3, qbase + kk * 32);
            uint32_t bf[8][2];
            #pragma unroll
            for (int n16 = 0; n16 < 4; ++n16) {
                uint32_t t0, t1, t2, t3;
                ldmx4(t0, t1, t2, t3, kbase + (uint32_t)(n16 * 16 * FS * 4) + kk * 32);
                bf[n16 * 2][0] = t0;     bf[n16 * 2][1] = t1;
                bf[n16 * 2 + 1][0] = t2; bf[n16 * 2 + 1][1] = t3;
            }
            #pragma unroll
            for (int nt = 0; nt < 8; ++nt)
                mma_tf32(s[nt][0], s[nt][1], s[nt][2], s[nt][3],
                         a0, a1, a2, a3, bf[nt][0], bf[nt][1]);
        }

        // ---- softmax (log2 domain), causal mask ----
        float mb0 = -1e30f, mb1 = -1e30f;
        #pragma unroll
        for (int nt = 0; nt < 8; ++nt) {
            int c0 = kt * 64 + nt * 8 + 2 * tg;
            float z0 = (c0     > row0) ? -1e30f : s[nt][0] * SC;
            float z1 = (c0 + 1 > row0) ? -1e30f : s[nt][1] * SC;
            float z2 = (c0     > row1) ? -1e30f : s[nt][2] * SC;
            float z3 = (c0 + 1 > row1) ? -1e30f : s[nt][3] * SC;
            s[nt][0] = z0; s[nt][1] = z1; s[nt][2] = z2; s[nt][3] = z3;
            mb0 = fmaxf(mb0, fmaxf(z0, z1));
            mb1 = fmaxf(mb1, fmaxf(z2, z3));
        }
        mb0 = fmaxf(mb0, __shfl_xor_sync(0xffffffffu, mb0, 1));
        mb0 = fmaxf(mb0, __shfl_xor_sync(0xffffffffu, mb0, 2));
        mb1 = fmaxf(mb1, __shfl_xor_sync(0xffffffffu, mb1, 1));
        mb1 = fmaxf(mb1, __shfl_xor_sync(0xffffffffu, mb1, 2));

        float mn0 = fmaxf(m0, mb0), mn1 = fmaxf(m1, mb1);
        float al0 = fexp2(m0 - mn0), al1 = fexp2(m1 - mn1);
        m0 = mn0; m1 = mn1;

        float rs0 = 0.f, rs1 = 0.f;
        float* pw = &Ps[(w16 + g) * FS];
        #pragma unroll
        for (int nt = 0; nt < 8; ++nt) {
            float p0 = fexp2(s[nt][0] - mn0);
            float p1 = fexp2(s[nt][1] - mn0);
            float p2 = fexp2(s[nt][2] - mn1);
            float p3 = fexp2(s[nt][3] - mn1);
            rs0 += p0 + p1; rs1 += p2 + p3;
            pw[nt * 8 + 2 * tg]            = f2tf32(p0);
            pw[nt * 8 + 2 * tg + 1]        = f2tf32(p1);
            pw[8 * FS + nt * 8 + 2 * tg]     = f2tf32(p2);
            pw[8 * FS + nt * 8 + 2 * tg + 1] = f2tf32(p3);
        }
        rs0 += __shfl_xor_sync(0xffffffffu, rs0, 1);
        rs0 += __shfl_xor_sync(0xffffffffu, rs0, 2);
        rs1 += __shfl_xor_sync(0xffffffffu, rs1, 1);
        rs1 += __shfl_xor_sync(0xffffffffu, rs1, 2);
        l0 = l0 * al0 + rs0;
        l1 = l1 * al1 + rs1;

        #pragma unroll
        for (int nt = 0; nt < 8; ++nt) {
            O[nt][0] *= al0; O[nt][1] *= al0;
            O[nt][2] *= al1; O[nt][3] *= al1;
        }
        __syncwarp();

        // ---- O += P V via ldmatrix frags (Vt is [d][key] = Bt layout) ----
        #pragma unroll
        for (int kk = 0; kk < 8; ++kk) {
            uint32_t a0, a1, a2, a3;
            ldmx4(a0, a1, a2, a3, pbase + kk * 32);
            uint32_t bf[8][2];
            #pragma unroll
            for (int n16 = 0; n16 < 4; ++n16) {
                uint32_t t0, t1, t2, t3;
                ldmx4(t0, t1, t2, t3, vbase + (uint32_t)(n16 * 16 * FS * 4) + kk * 32);
                bf[n16 * 2][0] = t0;     bf[n16 * 2][1] = t1;
                bf[n16 * 2 + 1][0] = t2; bf[n16 * 2 + 1][1] = t3;
            }
            #pragma unroll
            for (int nt = 0; nt < 8; ++nt)
                mma_tf32(O[nt][0], O[nt][1], O[nt][2], O[nt][3],
                         a0, a1, a2, a3, bf[nt][0], bf[nt][1]);
        }
    }

    // normalize + round to tf32 (feeds Wo GEMM) + write
    float inv0 = 1.0f / l0, inv1 = 1.0f / l1;
    #pragma unroll
    for (int nt = 0; nt < 8; ++nt) {
        int c = h * HSZ + nt * 8 + 2 * tg;
        float2 o0 = make_float2(f2tf32(O[nt][0] * inv0), f2tf32(O[nt][1] * inv0));
        float2 o1 = make_float2(f2tf32(O[nt][2] * inv1), f2tf32(O[nt][3] * inv1));
        *reinterpret_cast<float2*>(out + (size_t)row0 * DD + c) = o0;
        *reinterpret_cast<float2*>(out + (size_t)row1 * DD + c) = o1;
    }
}

// ---------------- launch ----------------
extern "C" void kernel_launch(void* const* d_in, const int* in_sizes, int n_in,
                              void* d_out, int out_size)
{
    const float* x    = (const float*)d_in[0];
    const float* Wq   = (const float*)d_in[1];
    const float* Wk   = (const float*)d_in[2];
    const float* Wv   = (const float*)d_in[3];
    const float* Wo   = (const float*)d_in[4];
    const float* bo   = (const float*)d_in[5];
    const float* W1   = (const float*)d_in[6];
    const float* b1   = (const float*)d_in[7];
    const float* W2   = (const float*)d_in[8];
    const float* b2   = (const float*)d_in[9];
    const float* ln1s = (const float*)d_in[10];
    const float* ln1b = (const float*)d_in[11];
    const float* ln2s = (const float*)d_in[12];
    const float* ln2b = (const float*)d_in[13];
    float* out = (float*)d_out;

    float *h, *wqkvT, *woT, *w1T, *w2T, *qkv, *att, *x2, *ff;
    cudaGetSymbolAddress((void**)&h,     g_h);
    cudaGetSymbolAddress((void**)&wqkvT, g_wqkvT);
    cudaGetSymbolAddress((void**)&woT,   g_WoT);
    cudaGetSymbolAddress((void**)&w1T,   g_W1T);
    cudaGetSymbolAddress((void**)&w2T,   g_W2T);
    cudaGetSymbolAddress((void**)&qkv,   g_qkv);
    cudaGetSymbolAddress((void**)&att,   g_att);
    cudaGetSymbolAddress((void**)&x2,    g_x2);
    cudaGetSymbolAddress((void**)&ff,    g_ff);

    cudaFuncSetAttribute(flash_tc, cudaFuncAttributeMaxDynamicSharedMemorySize, FA_SMEM);
    cudaFuncSetAttribute(tg2<0>, cudaFuncAttributeMaxDynamicSharedMemorySize, TG_SMEM);
    cudaFuncSetAttribute(tg2<1>, cudaFuncAttributeMaxDynamicSharedMemorySize, TG_SMEM);
    cudaFuncSetAttribute(tg2<2>, cudaFuncAttributeMaxDynamicSharedMemorySize, TG_SMEM);

    dim3 tb(32, 8);

    // 1. LN1
    ln_kernel<<<TT, 256>>>(x, ln1s, ln1b, h);
    // 2. weight transposes -> K-major tf32 B operands
    transpose32<<<dim3(2, 32, 16), tb>>>(Wq, wqkvT,           DD, HSZ, DD*HSZ, HSZ*DD);
    transpose32<<<dim3(2, 32, 16), tb>>>(Wk, wqkvT + DD*DD,   DD, HSZ, DD*HSZ, HSZ*DD);
    transpose32<<<dim3(2, 32, 16), tb>>>(Wv, wqkvT + 2*DD*DD, DD, HSZ, DD*HSZ, HSZ*DD);
    transpose32<<<dim3(32, 32, 1),  tb>>>(Wo, woT, DD, DD, 0, 0);
    transpose32<<<dim3(128, 32, 1), tb>>>(W1, w1T, DD, DFF, 0, 0);
    transpose32<<<dim3(32, 128, 1), tb>>>(W2, w2T, DFF, DD, 0, 0);
    // 3. QKV GEMM (rounded output)
    tg2<0><<<dim3(3 * DD / 128, TT / 128), 256, TG_SMEM>>>(
        TT, 3 * DD, DD, h, wqkvT, nullptr, nullptr, qkv);
    // 4. causal flash attention (rounded output)
    flash_tc<<<dim3(TT / 128, HH), 256, FA_SMEM>>>(qkv, att);
    // 5. output proj + bias + residual (fp32 output)
    tg2<1><<<dim3(DD / 128, TT / 128), 256, TG_SMEM>>>(
        TT, DD, DD, att, woT, bo, x, x2);
    // 6. LN2
    ln_kernel<<<TT, 256>>>(x2, ln2s, ln2b, h);
    // 7. FFN1 (rounded output)
    tg2<2><<<dim3(DFF / 128, TT / 128), 256, TG_SMEM>>>(
        TT, DFF, DD, h, w1T, b1, nullptr, ff);
    // 8. FFN2 (fp32 output)
    tg2<1><<<dim3(DD / 128, TT / 128), 256, TG_SMEM>>>(
        TT, DD, DFF, ff, w2T, b2, x2, out);
}

// round 8
// speedup vs baseline: 1.2072x; 1.0644x over previous
#include <cuda_runtime.h>
#include <cstdint>

#define TT 2048
#define DD 1024
#define HH 16
#define HSZ 64
#define DFF 4096

// ---------------- scratch (no allocs allowed) ----------------
__device__ float g_h[TT * DD];            // LN output (tf32-rounded)
__device__ float g_wqkvT[3 * DD * DD];    // QKV weights, [3D][D] K-major (tf32)
__device__ float g_WoT[DD * DD];          // Wo^T  [D][D] (tf32)
__device__ float g_W1T[DD * DFF];         // W1^T  [DFF][D] (tf32)
__device__ float g_W2T[DFF * DD];         // W2^T  [D][DFF] (tf32)
__device__ float g_qkv[TT * 3 * DD];      // QKV activations [T, 3D] (tf32)
__device__ float g_att[TT * DD];          // attention output [T, D] (tf32)
__device__ float g_x2[TT * DD];           // residual after attention (fp32)
__device__ float g_ff[TT * DFF];          // FFN hidden (tf32)

// ---------------- helpers ----------------
__device__ __forceinline__ uint32_t smem_u32(const void* p) {
    return (uint32_t)__cvta_generic_to_shared(p);
}
__device__ __forceinline__ float f2tf32(float x) {
    uint32_t r;
    asm("cvt.rna.tf32.f32 %0, %1;" : "=r"(r) : "f"(x));
    return __uint_as_float(r);
}
__device__ __forceinline__ uint32_t swz(uint32_t off) {   // SW128 swizzle
    return off ^ ((off >> 3) & 0x70);
}
__device__ __forceinline__ void mma_tf32(
    float& d0, float& d1, float& d2, float& d3,
    uint32_t a0, uint32_t a1, uint32_t a2, uint32_t a3,
    uint32_t b0, uint32_t b1)
{
    asm volatile(
        "mma.sync.aligned.m16n8k8.row.col.f32.tf32.tf32.f32 "
        "{%0,%1,%2,%3}, {%4,%5,%6,%7}, {%8,%9}, {%0,%1,%2,%3};\n"
        : "+f"(d0), "+f"(d1), "+f"(d2), "+f"(d3)
        : "r"(a0), "r"(a1), "r"(a2), "r"(a3), "r"(b0), "r"(b1));
}
__device__ __forceinline__ void ldmx4(
    uint32_t& r0, uint32_t& r1, uint32_t& r2, uint32_t& r3, uint32_t addr)
{
    asm volatile("ldmatrix.sync.aligned.m8n8.x4.shared.b16 {%0,%1,%2,%3}, [%4];"
                 : "=r"(r0), "=r"(r1), "=r"(r2), "=r"(r3) : "r"(addr) : "memory");
}
__device__ __forceinline__ void cpasync16(uint32_t saddr, const void* gaddr) {
    asm volatile("cp.async.cg.shared.global [%0], [%1], 16;" :: "r"(saddr), "l"(gaddr));
}
#define CP_COMMIT() asm volatile("cp.async.commit_group;" ::: "memory")
#define CP_WAIT(n)  asm volatile("cp.async.wait_group %0;" :: "n"(n) : "memory")

// ---------------- LayerNorm (emits tf32-rounded values) ----------------
__global__ __launch_bounds__(256) void ln_kernel(
    const float* __restrict__ x, const float* __restrict__ g,
    const float* __restrict__ b, float* __restrict__ y)
{
    int row = blockIdx.x;
    int tid = threadIdx.x;
    float4 v = reinterpret_cast<const float4*>(x + (size_t)row * DD)[tid];
    float s  = v.x + v.y + v.z + v.w;
    float ss = v.x * v.x + v.y * v.y + v.z * v.z + v.w * v.w;
    #pragma unroll
    for (int o = 16; o > 0; o >>= 1) {
        s  += __shfl_xor_sync(0xffffffffu, s, o);
        ss += __shfl_xor_sync(0xffffffffu, ss, o);
    }
    __shared__ float sb[8], ssb[8], stats[2];
    int wid = tid >> 5, lane = tid & 31;
    if (lane == 0) { sb[wid] = s; ssb[wid] = ss; }
    __syncthreads();
    if (tid == 0) {
        float a = 0.f, c = 0.f;
        #pragma unroll
        for (int i = 0; i < 8; i++) { a += sb[i]; c += ssb[i]; }
        float mean = a * (1.0f / DD);
        float var  = c * (1.0f / DD) - mean * mean;
        stats[0] = mean;
        stats[1] = rsqrtf(var + 1e-6f);
    }
    __syncthreads();
    float mean = stats[0], rstd = stats[1];
    float4 gg = reinterpret_cast<const float4*>(g)[tid];
    float4 bb = reinterpret_cast<const float4*>(b)[tid];
    float4 o;
    o.x = f2tf32((v.x - mean) * rstd * gg.x + bb.x);
    o.y = f2tf32((v.y - mean) * rstd * gg.y + bb.y);
    o.z = f2tf32((v.z - mean) * rstd * gg.z + bb.z);
    o.w = f2tf32((v.w - mean) * rstd * gg.w + bb.w);
    reinterpret_cast<float4*>(y + (size_t)row * DD)[tid] = o;
}

// ---------------- ALL weight transposes in one launch ----------------
// 12288 blocks of 32x32 tiles:
//   [0,3072)     Wq/Wk/Wv per-head [D][64] -> [64][D]   (64 tiles/head, 16 heads, 3 weights)
//   [3072,4096)  Wo   [D][D]    -> [D][D]
//   [4096,8192)  W1   [D][DFF]  -> [DFF][D]
//   [8192,12288) W2   [DFF][D]  -> [D][DFF]
__global__ __launch_bounds__(256) void transpose_all(
    const float* __restrict__ Wq, const float* __restrict__ Wk,
    const float* __restrict__ Wv, const float* __restrict__ Wo,
    const float* __restrict__ W1, const float* __restrict__ W2,
    float* __restrict__ wqkvT, float* __restrict__ woT,
    float* __restrict__ w1T, float* __restrict__ w2T)
{
    __shared__ float t[32][33];
    const int b = blockIdx.x;
    const float* ip; float* op;
    int R, C, bx, by;
    if (b < 3072) {
        const int w = b >> 10;               // 0=Wq 1=Wk 2=Wv
        const int r = b & 1023;
        const int head = r >> 6;
        const int rr = r & 63;
        bx = (rr & 1) * 32;                  // C = 64 -> 2 tiles
        by = (rr >> 1) * 32;                 // R = 1024 -> 32 tiles
        ip = (w == 0 ? Wq : (w == 1 ? Wk : Wv)) + (size_t)head * DD * HSZ;
        op = wqkvT + (size_t)w * DD * DD + (size_t)head * HSZ * DD;
        R = DD; C = HSZ;
    } else if (b < 4096) {
        const int r = b - 3072;
        bx = (r & 31) * 32; by = (r >> 5) * 32;
        ip = Wo; op = woT; R = DD; C = DD;
    } else if (b < 8192) {
        const int r = b - 4096;
        bx = (r & 127) * 32; by = (r >> 7) * 32;
        ip = W1; op = w1T; R = DD; C = DFF;
    } else {
        const int r = b - 8192;
        bx = (r & 31) * 32; by = (r >> 5) * 32;
        ip = W2; op = w2T; R = DFF; C = DD;
    }
    const int x = threadIdx.x, y = threadIdx.y;
    #pragma unroll
    for (int j = 0; j < 32; j += 8)
        t[y + j][x] = ip[(size_t)(by + y + j) * C + bx + x];
    __syncthreads();
    #pragma unroll
    for (int j = 0; j < 32; j += 8)
        op[(size_t)(bx + y + j) * R + by + x] = f2tf32(t[x][y + j]);
}

// ---------------- tf32 mma.sync GEMM (R5 geometry + rounding epilogue) ----------------
#define TG_STAGE 32768
#define TG_SMEM  (3 * TG_STAGE)

template <int EPI>
__global__ __launch_bounds__(256, 1) void tg2(
    int M, int N, int K,
    const float* __restrict__ A, const float* __restrict__ Bt,
    const float* __restrict__ bias, const float* __restrict__ resid,
    float* __restrict__ C)
{
    extern __shared__ float dynsm[];
    const int tid  = threadIdx.x;
    const int warp = tid >> 5, lane = tid & 31;
    const int wm = warp & 1, wn = warp >> 1;
    const int g = lane >> 2, tg = lane & 3;
    const int brow = blockIdx.y, bcol = blockIdx.x;

    const uint32_t sbase = smem_u32(dynsm);
    const int r0 = tid >> 3;
    const int ck = tid & 7;
    const float* Ab = A  + (size_t)(brow * 128) * K + ck * 4;
    const float* Bb = Bt + (size_t)(bcol * 128) * K + ck * 4;
    const int KT = K >> 5;

    const int aRow = (lane & 7) + ((lane >> 3) & 1) * 8;
    const int aChk = (lane >> 4);
    const int bRow = (lane & 7) + (lane >> 4) * 8;
    const int bChk = (lane >> 3) & 1;

    float acc[4][4][4];
    #pragma unroll
    for (int mt = 0; mt < 4; mt++)
        #pragma unroll
        for (int nt = 0; nt < 4; nt++)
            #pragma unroll
            for (int i = 0; i < 4; i++) acc[mt][nt][i] = 0.f;

    auto load_stage = [&](int kt, int s) {
        const uint32_t sA = sbase + s * TG_STAGE;
        const uint32_t sB = sA + 16384;
        const int k0 = kt * 32;
        #pragma unroll
        for (int j = 0; j < 4; ++j) {
            const int r = j * 32 + r0;
            const uint32_t off = swz((uint32_t)(r * 128 + ck * 16));
            cpasync16(sA + off, Ab + (size_t)r * K + k0);
            cpasync16(sB + off, Bb + (size_t)r * K + k0);
        }
        CP_COMMIT();
    };

    load_stage(0, 0);
    load_stage(1, 1);

    for (int kt = 0; kt < KT; ++kt) {
        if (kt + 1 < KT) CP_WAIT(1); else CP_WAIT(0);
        __syncthreads();
        if (kt + 2 < KT) load_stage(kt + 2, (kt + 2) % 3);

        const uint32_t sA = sbase + (kt % 3) * TG_STAGE;
        const uint32_t sB = sA + 16384;

        #pragma unroll
        for (int ks = 0; ks < 4; ++ks) {
            const int chunkA = ks * 2;
            uint32_t af[4][4];
            #pragma unroll
            for (int mt = 0; mt < 4; ++mt) {
                const int row = wm * 64 + mt * 16 + aRow;
                const uint32_t ad = sA + swz((uint32_t)(row * 128 + (chunkA + aChk) * 16));
                ldmx4(af[mt][0], af[mt][1], af[mt][2], af[mt][3], ad);
            }
            uint32_t bf[4][2];
            #pragma unroll
            for (int np = 0; np < 2; ++np) {
                const int nrow = wn * 32 + np * 16 + bRow;
                const uint32_t bd = sB + swz((uint32_t)(nrow * 128 + (chunkA + bChk) * 16));
                uint32_t t0, t1, t2, t3;
                ldmx4(t0, t1, t2, t3, bd);
                bf[np * 2][0] = t0;     bf[np * 2][1] = t1;
                bf[np * 2 + 1][0] = t2; bf[np * 2 + 1][1] = t3;
            }
            #pragma unroll
            for (int mt = 0; mt < 4; ++mt)
                #pragma unroll
                for (int nt = 0; nt < 4; ++nt)
                    mma_tf32(acc[mt][nt][0], acc[mt][nt][1],
                             acc[mt][nt][2], acc[mt][nt][3],
                             af[mt][0], af[mt][1], af[mt][2], af[mt][3],
                             bf[nt][0], bf[nt][1]);
        }
    }

    #pragma unroll
    for (int mt = 0; mt < 4; mt++) {
        const int r0g = brow * 128 + wm * 64 + mt * 16 + g;
        const int r1g = r0g + 8;
        #pragma unroll
        for (int nt = 0; nt < 4; nt++) {
            const int c = bcol * 128 + wn * 32 + nt * 8 + tg * 2;
            float2 o0 = make_float2(acc[mt][nt][0], acc[mt][nt][1]);
            float2 o1 = make_float2(acc[mt][nt][2], acc[mt][nt][3]);
            if constexpr (EPI >= 1) {
                float2 bv = *reinterpret_cast<const float2*>(bias + c);
                o0.x += bv.x; o0.y += bv.y;
                o1.x += bv.x; o1.y += bv.y;
            }
            if constexpr (EPI == 1) {
                float2 rv0 = *reinterpret_cast<const float2*>(resid + (size_t)r0g * N + c);
                float2 rv1 = *reinterpret_cast<const float2*>(resid + (size_t)r1g * N + c);
                o0.x += rv0.x; o0.y += rv0.y;
                o1.x += rv1.x; o1.y += rv1.y;
            }
            if constexpr (EPI == 2) {
                o0.x = fmaxf(o0.x, 0.f); o0.y = fmaxf(o0.y, 0.f);
                o1.x = fmaxf(o1.x, 0.f); o1.y = fmaxf(o1.y, 0.f);
            }
            if constexpr (EPI == 0 || EPI == 2) {
                o0.x = f2tf32(o0.x); o0.y = f2tf32(o0.y);
                o1.x = f2tf32(o1.x); o1.y = f2tf32(o1.y);
            }
            *reinterpret_cast<float2*>(C + (size_t)r0g * N + c) = o0;
            *reinterpret_cast<float2*>(C + (size_t)r1g * N + c) = o1;
        }
    }
}

// ---------------- fast exp2 (fma pipe) ----------------
__device__ __forceinline__ float fexp2(float x) {
    x = fmaxf(x, -120.f);
    float k  = __fadd_rn(x, 12582912.f);
    int   sc = __float_as_int(k) << 23;
    float f  = __fsub_rn(x, __fsub_rn(k, 12582912.f));
    float p  = 0.0013333558f;
    p = fmaf(p, f, 0.0096181291f);
    p = fmaf(p, f, 0.0555041087f);
    p = fmaf(p, f, 0.2402265070f);
    p = fmaf(p, f, 0.6931471806f);
    p = fmaf(p, f, 1.0f);
    return __int_as_float(__float_as_int(p) + sc);
}

// ---------------- flash attention v3 ----------------
// ldmatrix Q/K/P; V kept [key][d] (stride 72, conflict-free scalar B-frags).
#define FS   68
#define VS_S 72
#define FA_SMEM ((128*FS + 64*FS + 64*VS_S + 128*FS) * 4)

__global__ __launch_bounds__(256, 2) void flash_tc(
    const float* __restrict__ qkv, float* __restrict__ out)
{
    extern __shared__ float sm[];
    float* Qs = sm;                 // [128][68]
    float* Ks = Qs + 128 * FS;      // [64][68]
    float* Vs = Ks + 64 * FS;       // [64][72]  (key-major, NOT transposed)
    float* Ps = Vs + 64 * VS_S;     // [128][68]

    const int tid  = threadIdx.x;
    const int warp = tid >> 5;
    const int lane = tid & 31;
    const int g    = lane >> 2;
    const int tg   = lane & 3;
    const int qb   = gridDim.x - 1 - blockIdx.x;
    const int h    = blockIdx.y;
    const int q0   = qb * 128;
    const int w16  = warp * 16;

    const int aRow = (lane & 7) + ((lane >> 3) & 1) * 8;
    const int aChk = lane >> 4;
    const int bRow = (lane & 7) + (lane >> 4) * 8;
    const int bChk = (lane >> 3) & 1;

    const float* qp = qkv + h * HSZ;
    const float* kp = qkv + DD + h * HSZ;
    const float* vp = qkv + 2 * DD + h * HSZ;

    for (int i = tid; i < 128 * 16; i += 256) {
        int r = i >> 4, c4 = i & 15;
        float4 v = *reinterpret_cast<const float4*>(qp + (size_t)(q0 + r) * (3 * DD) + c4 * 4);
        *reinterpret_cast<float4*>(Qs + r * FS + c4 * 4) = v;
    }

    float O[8][4];
    #pragma unroll
    for (int nt = 0; nt < 8; nt++)
        #pragma unroll
        for (int i = 0; i < 4; i++) O[nt][i] = 0.f;
    float m0 = -1e30f, m1 = -1e30f, l0 = 0.f, l1 = 0.f;

    const int row0 = q0 + w16 + g;
    const int row1 = row0 + 8;
    const float SC = 0.18033688011112042f;   // (1/8) * log2(e)
    const int nkt = 2 * qb + 2;

    const uint32_t qbase = smem_u32(Qs) + (uint32_t)((w16 + aRow) * FS * 4 + aChk * 16);
    const uint32_t kbase = smem_u32(Ks) + (uint32_t)(bRow * FS * 4 + bChk * 16);
    const uint32_t pbase = smem_u32(Ps) + (uint32_t)((w16 + aRow) * FS * 4 + aChk * 16);

    for (int kt = 0; kt < nkt; ++kt) {
        __syncthreads();
        for (int i = tid; i < 64 * 16; i += 256) {
            int r = i >> 4, c4 = i & 15;
            size_t gi = (size_t)(kt * 64 + r) * (3 * DD) + c4 * 4;
            float4 kv = *reinterpret_cast<const float4*>(kp + gi);
            float4 vv = *reinterpret_cast<const float4*>(vp + gi);
            *reinterpret_cast<float4*>(Ks + r * FS + c4 * 4) = kv;
            *reinterpret_cast<float4*>(Vs + r * VS_S + c4 * 4) = vv;
        }
        __syncthreads();

        // ---- S = Q K^T (ldmatrix frags) ----
        float s[8][4];
        #pragma unroll
        for (int nt = 0; nt < 8; nt++)
            #pragma unroll
            for (int i = 0; i < 4; i++) s[nt][i] = 0.f;

        #pragma unroll
        for (int kk = 0; kk < 8; ++kk) {
            uint32_t a0, a1, a2, a3;
            ldmx4(a0, a1, a2, a3, qbase + kk * 32);
            uint32_t bf[8][2];
            #pragma unroll
            for (int n16 = 0; n16 < 4; ++n16) {
                uint32_t t0, t1, t2, t3;
                ldmx4(t0, t1, t2, t3, kbase + (uint32_t)(n16 * 16 * FS * 4) + kk * 32);
                bf[n16 * 2][0] = t0;     bf[n16 * 2][1] = t1;
                bf[n16 * 2 + 1][0] = t2; bf[n16 * 2 + 1][1] = t3;
            }
            #pragma unroll
            for (int nt = 0; nt < 8; ++nt)
                mma_tf32(s[nt][0], s[nt][1], s[nt][2], s[nt][3],
                         a0, a1, a2, a3, bf[nt][0], bf[nt][1]);
        }

        // ---- softmax (log2 domain), causal mask ----
        float mb0 = -1e30f, mb1 = -1e30f;
        #pragma unroll
        for (int nt = 0; nt < 8; ++nt) {
            int c0 = kt * 64 + nt * 8 + 2 * tg;
            float z0 = (c0     > row0) ? -1e30f : s[nt][0] * SC;
            float z1 = (c0 + 1 > row0) ? -1e30f : s[nt][1] * SC;
            float z2 = (c0     > row1) ? -1e30f : s[nt][2] * SC;
            float z3 = (c0 + 1 > row1) ? -1e30f : s[nt][3] * SC;
            s[nt][0] = z0; s[nt][1] = z1; s[nt][2] = z2; s[nt][3] = z3;
            mb0 = fmaxf(mb0, fmaxf(z0, z1));
            mb1 = fmaxf(mb1, fmaxf(z2, z3));
        }
        mb0 = fmaxf(mb0, __shfl_xor_sync(0xffffffffu, mb0, 1));
        mb0 = fmaxf(mb0, __shfl_xor_sync(0xffffffffu, mb0, 2));
        mb1 = fmaxf(mb1, __shfl_xor_sync(0xffffffffu, mb1, 1));
        mb1 = fmaxf(mb1, __shfl_xor_sync(0xffffffffu, mb1, 2));

        float mn0 = fmaxf(m0, mb0), mn1 = fmaxf(m1, mb1);
        float al0 = fexp2(m0 - mn0), al1 = fexp2(m1 - mn1);
        m0 = mn0; m1 = mn1;

        float rs0 = 0.f, rs1 = 0.f;
        float* pw = &Ps[(w16 + g) * FS];
        #pragma unroll
        for (int nt = 0; nt < 8; ++nt) {
            float p0 = fexp2(s[nt][0] - mn0);
            float p1 = fexp2(s[nt][1] - mn0);
            float p2 = fexp2(s[nt][2] - mn1);
            float p3 = fexp2(s[nt][3] - mn1);
            rs0 += p0 + p1; rs1 += p2 + p3;
            pw[nt * 8 + 2 * tg]            = f2tf32(p0);
            pw[nt * 8 + 2 * tg + 1]        = f2tf32(p1);
            pw[8 * FS + nt * 8 + 2 * tg]     = f2tf32(p2);
            pw[8 * FS + nt * 8 + 2 * tg + 1] = f2tf32(p3);
        }
        rs0 += __shfl_xor_sync(0xffffffffu, rs0, 1);
        rs0 += __shfl_xor_sync(0xffffffffu, rs0, 2);
        rs1 += __shfl_xor_sync(0xffffffffu, rs1, 1);
        rs1 += __shfl_xor_sync(0xffffffffu, rs1, 2);
        l0 = l0 * al0 + rs0;
        l1 = l1 * al1 + rs1;

        #pragma unroll
        for (int nt = 0; nt < 8; ++nt) {
            O[nt][0] *= al0; O[nt][1] *= al0;
            O[nt][2] *= al1; O[nt][3] *= al1;
        }
        __syncwarp();

        // ---- O += P V : P via ldmatrix, V B-frags via scalar LDS ----
        #pragma unroll
        for (int kk = 0; kk < 8; ++kk) {
            uint32_t a0, a1, a2, a3;
            ldmx4(a0, a1, a2, a3, pbase + kk * 32);
            #pragma unroll
            for (int nt = 0; nt < 8; ++nt) {
                uint32_t b0 = __float_as_uint(Vs[(kk * 8 + tg) * VS_S + nt * 8 + g]);
                uint32_t b1 = __float_as_uint(Vs[(kk * 8 + tg + 4) * VS_S + nt * 8 + g]);
                mma_tf32(O[nt][0], O[nt][1], O[nt][2], O[nt][3],
                         a0, a1, a2, a3, b0, b1);
            }
        }
    }

    // normalize + round to tf32 (feeds Wo GEMM) + write
    float inv0 = 1.0f / l0, inv1 = 1.0f / l1;
    #pragma unroll
    for (int nt = 0; nt < 8; ++nt) {
        int c = h * HSZ + nt * 8 + 2 * tg;
        float2 o0 = make_float2(f2tf32(O[nt][0] * inv0), f2tf32(O[nt][1] * inv0));
        float2 o1 = make_float2(f2tf32(O[nt][2] * inv1), f2tf32(O[nt][3] * inv1));
        *reinterpret_cast<float2*>(out + (size_t)row0 * DD + c) = o0;
        *reinterpret_cast<float2*>(out + (size_t)row1 * DD + c) = o1;
    }
}

// ---------------- launch ----------------
extern "C" void kernel_launch(void* const* d_in, const int* in_sizes, int n_in,
                              void* d_out, int out_size)
{
    const float* x    = (const float*)d_in[0];
    const float* Wq   = (const float*)d_in[1];
    const float* Wk   = (const float*)d_in[2];
    const float* Wv   = (const float*)d_in[3];
    const float* Wo   = (const float*)d_in[4];
    const float* bo   = (const float*)d_in[5];
    const float* W1   = (const float*)d_in[6];
    const float* b1   = (const float*)d_in[7];
    const float* W2   = (const float*)d_in[8];
    const float* b2   = (const float*)d_in[9];
    const float* ln1s = (const float*)d_in[10];
    const float* ln1b = (const float*)d_in[11];
    const float* ln2s = (const float*)d_in[12];
    const float* ln2b = (const float*)d_in[13];
    float* out = (float*)d_out;

    float *h, *wqkvT, *woT, *w1T, *w2T, *qkv, *att, *x2, *ff;
    cudaGetSymbolAddress((void**)&h,     g_h);
    cudaGetSymbolAddress((void**)&wqkvT, g_wqkvT);
    cudaGetSymbolAddress((void**)&woT,   g_WoT);
    cudaGetSymbolAddress((void**)&w1T,   g_W1T);
    cudaGetSymbolAddress((void**)&w2T,   g_W2T);
    cudaGetSymbolAddress((void**)&qkv,   g_qkv);
    cudaGetSymbolAddress((void**)&att,   g_att);
    cudaGetSymbolAddress((void**)&x2,    g_x2);
    cudaGetSymbolAddress((void**)&ff,    g_ff);

    cudaFuncSetAttribute(flash_tc, cudaFuncAttributeMaxDynamicSharedMemorySize, FA_SMEM);
    cudaFuncSetAttribute(tg2<0>, cudaFuncAttributeMaxDynamicSharedMemorySize, TG_SMEM);
    cudaFuncSetAttribute(tg2<1>, cudaFuncAttributeMaxDynamicSharedMemorySize, TG_SMEM);
    cudaFuncSetAttribute(tg2<2>, cudaFuncAttributeMaxDynamicSharedMemorySize, TG_SMEM);

    // 1. LN1
    ln_kernel<<<TT, 256>>>(x, ln1s, ln1b, h);
    // 2. ALL weight transposes in one launch
    transpose_all<<<12288, dim3(32, 8)>>>(Wq, Wk, Wv, Wo, W1, W2,
                                          wqkvT, woT, w1T, w2T);
    // 3. QKV GEMM (rounded output)
    tg2<0><<<dim3(3 * DD / 128, TT / 128), 256, TG_SMEM>>>(
        TT, 3 * DD, DD, h, wqkvT, nullptr, nullptr, qkv);
    // 4. causal flash attention (rounded output)
    flash_tc<<<dim3(TT / 128, HH), 256, FA_SMEM>>>(qkv, att);
    // 5. output proj + bias + residual (fp32 output)
    tg2<1><<<dim3(DD / 128, TT / 128), 256, TG_SMEM>>>(
        TT, DD, DD, att, woT, bo, x, x2);
    // 6. LN2
    ln_kernel<<<TT, 256>>>(x2, ln2s, ln2b, h);
    // 7. FFN1 (rounded output)
    tg2<2><<<dim3(DFF / 128, TT / 128), 256, TG_SMEM>>>(
        TT, DFF, DD, h, w1T, b1, nullptr, ff);
    // 8. FFN2 (fp32 output)
    tg2<1><<<dim3(DD / 128, TT / 128), 256, TG_SMEM>>>(
        TT, DD, DFF, ff, w2T, b2, x2, out);
}

// round 9
// speedup vs baseline: 1.3172x; 1.0911x over previous
#include <cuda_runtime.h>
#include <cstdint>

#define TT 2048
#define DD 1024
#define HH 16
#define HSZ 64
#define DFF 4096

// ---------------- scratch (no allocs allowed) ----------------
__device__ float g_h[TT * DD];            // LN output (tf32-rounded)
__device__ float g_wqkvT[3 * DD * DD];    // QKV weights, [3D][D] K-major (tf32)
__device__ float g_WoT[DD * DD];          // Wo^T  [D][D] (tf32)
__device__ float g_W1T[DD * DFF];         // W1^T  [DFF][D] (tf32)
__device__ float g_W2T[DFF * DD];         // W2^T  [D][DFF] (tf32)
__device__ float g_qkv[TT * 3 * DD];      // QKV activations [T, 3D] (tf32)
__device__ float g_att[TT * DD];          // attention output [T, D] (tf32)
__device__ float g_x2[TT * DD];           // residual after attention (fp32)
__device__ float g_ff[TT * DFF];          // FFN hidden (tf32)

// ---------------- helpers ----------------
__device__ __forceinline__ uint32_t smem_u32(const void* p) {
    return (uint32_t)__cvta_generic_to_shared(p);
}
__device__ __forceinline__ float f2tf32(float x) {
    uint32_t r;
    asm("cvt.rna.tf32.f32 %0, %1;" : "=r"(r) : "f"(x));
    return __uint_as_float(r);
}
__device__ __forceinline__ uint32_t swz(uint32_t off) {   // SW128 swizzle
    return off ^ ((off >> 3) & 0x70);
}
__device__ __forceinline__ void mma_tf32(
    float& d0, float& d1, float& d2, float& d3,
    uint32_t a0, uint32_t a1, uint32_t a2, uint32_t a3,
    uint32_t b0, uint32_t b1)
{
    asm volatile(
        "mma.sync.aligned.m16n8k8.row.col.f32.tf32.tf32.f32 "
        "{%0,%1,%2,%3}, {%4,%5,%6,%7}, {%8,%9}, {%0,%1,%2,%3};\n"
        : "+f"(d0), "+f"(d1), "+f"(d2), "+f"(d3)
        : "r"(a0), "r"(a1), "r"(a2), "r"(a3), "r"(b0), "r"(b1));
}
__device__ __forceinline__ void ldmx4(
    uint32_t& r0, uint32_t& r1, uint32_t& r2, uint32_t& r3, uint32_t addr)
{
    asm volatile("ldmatrix.sync.aligned.m8n8.x4.shared.b16 {%0,%1,%2,%3}, [%4];"
                 : "=r"(r0), "=r"(r1), "=r"(r2), "=r"(r3) : "r"(addr) : "memory");
}
__device__ __forceinline__ void cpasync16(uint32_t saddr, const void* gaddr) {
    asm volatile("cp.async.cg.shared.global [%0], [%1], 16;" :: "r"(saddr), "l"(gaddr));
}
#define CP_COMMIT() asm volatile("cp.async.commit_group;" ::: "memory")
#define CP_WAIT(n)  asm volatile("cp.async.wait_group %0;" :: "n"(n) : "memory")

// ---------------- LayerNorm (emits tf32-rounded values) ----------------
__global__ __launch_bounds__(256) void ln_kernel(
    const float* __restrict__ x, const float* __restrict__ g,
    const float* __restrict__ b, float* __restrict__ y)
{
    int row = blockIdx.x;
    int tid = threadIdx.x;
    float4 v = reinterpret_cast<const float4*>(x + (size_t)row * DD)[tid];
    float s  = v.x + v.y + v.z + v.w;
    float ss = v.x * v.x + v.y * v.y + v.z * v.z + v.w * v.w;
    #pragma unroll
    for (int o = 16; o > 0; o >>= 1) {
        s  += __shfl_xor_sync(0xffffffffu, s, o);
        ss += __shfl_xor_sync(0xffffffffu, ss, o);
    }
    __shared__ float sb[8], ssb[8], stats[2];
    int wid = tid >> 5, lane = tid & 31;
    if (lane == 0) { sb[wid] = s; ssb[wid] = ss; }
    __syncthreads();
    if (tid == 0) {
        float a = 0.f, c = 0.f;
        #pragma unroll
        for (int i = 0; i < 8; i++) { a += sb[i]; c += ssb[i]; }
        float mean = a * (1.0f / DD);
        float var  = c * (1.0f / DD) - mean * mean;
        stats[0] = mean;
        stats[1] = rsqrtf(var + 1e-6f);
    }
    __syncthreads();
    float mean = stats[0], rstd = stats[1];
    float4 gg = reinterpret_cast<const float4*>(g)[tid];
    float4 bb = reinterpret_cast<const float4*>(b)[tid];
    float4 o;
    o.x = f2tf32((v.x - mean) * rstd * gg.x + bb.x);
    o.y = f2tf32((v.y - mean) * rstd * gg.y + bb.y);
    o.z = f2tf32((v.z - mean) * rstd * gg.z + bb.z);
    o.w = f2tf32((v.w - mean) * rstd * gg.w + bb.w);
    reinterpret_cast<float4*>(y + (size_t)row * DD)[tid] = o;
}

// ---------------- ALL weight transposes in one launch ----------------
__global__ __launch_bounds__(256) void transpose_all(
    const float* __restrict__ Wq, const float* __restrict__ Wk,
    const float* __restrict__ Wv, const float* __restrict__ Wo,
    const float* __restrict__ W1, const float* __restrict__ W2,
    float* __restrict__ wqkvT, float* __restrict__ woT,
    float* __restrict__ w1T, float* __restrict__ w2T)
{
    __shared__ float t[32][33];
    const int b = blockIdx.x;
    const float* ip; float* op;
    int R, C, bx, by;
    if (b < 3072) {
        const int w = b >> 10;
        const int r = b & 1023;
        const int head = r >> 6;
        const int rr = r & 63;
        bx = (rr & 1) * 32;
        by = (rr >> 1) * 32;
        ip = (w == 0 ? Wq : (w == 1 ? Wk : Wv)) + (size_t)head * DD * HSZ;
        op = wqkvT + (size_t)w * DD * DD + (size_t)head * HSZ * DD;
        R = DD; C = HSZ;
    } else if (b < 4096) {
        const int r = b - 3072;
        bx = (r & 31) * 32; by = (r >> 5) * 32;
        ip = Wo; op = woT; R = DD; C = DD;
    } else if (b < 8192) {
        const int r = b - 4096;
        bx = (r & 127) * 32; by = (r >> 7) * 32;
        ip = W1; op = w1T; R = DD; C = DFF;
    } else {
        const int r = b - 8192;
        bx = (r & 31) * 32; by = (r >> 5) * 32;
        ip = W2; op = w2T; R = DFF; C = DD;
    }
    const int x = threadIdx.x, y = threadIdx.y;
    #pragma unroll
    for (int j = 0; j < 32; j += 8)
        t[y + j][x] = ip[(size_t)(by + y + j) * C + bx + x];
    __syncthreads();
    #pragma unroll
    for (int j = 0; j < 32; j += 8)
        op[(size_t)(bx + y + j) * R + by + x] = f2tf32(t[x][y + j]);
}

// ---------------- tf32 mma.sync GEMM (R5/R8 geometry, frozen) ----------------
#define TG_STAGE 32768
#define TG_SMEM  (3 * TG_STAGE)

template <int EPI>
__global__ __launch_bounds__(256, 1) void tg2(
    int M, int N, int K,
    const float* __restrict__ A, const float* __restrict__ Bt,
    const float* __restrict__ bias, const float* __restrict__ resid,
    float* __restrict__ C)
{
    extern __shared__ float dynsm[];
    const int tid  = threadIdx.x;
    const int warp = tid >> 5, lane = tid & 31;
    const int wm = warp & 1, wn = warp >> 1;
    const int g = lane >> 2, tg = lane & 3;
    const int brow = blockIdx.y, bcol = blockIdx.x;

    const uint32_t sbase = smem_u32(dynsm);
    const int r0 = tid >> 3;
    const int ck = tid & 7;
    const float* Ab = A  + (size_t)(brow * 128) * K + ck * 4;
    const float* Bb = Bt + (size_t)(bcol * 128) * K + ck * 4;
    const int KT = K >> 5;

    const int aRow = (lane & 7) + ((lane >> 3) & 1) * 8;
    const int aChk = (lane >> 4);
    const int bRow = (lane & 7) + (lane >> 4) * 8;
    const int bChk = (lane >> 3) & 1;

    float acc[4][4][4];
    #pragma unroll
    for (int mt = 0; mt < 4; mt++)
        #pragma unroll
        for (int nt = 0; nt < 4; nt++)
            #pragma unroll
            for (int i = 0; i < 4; i++) acc[mt][nt][i] = 0.f;

    auto load_stage = [&](int kt, int s) {
        const uint32_t sA = sbase + s * TG_STAGE;
        const uint32_t sB = sA + 16384;
        const int k0 = kt * 32;
        #pragma unroll
        for (int j = 0; j < 4; ++j) {
            const int r = j * 32 + r0;
            const uint32_t off = swz((uint32_t)(r * 128 + ck * 16));
            cpasync16(sA + off, Ab + (size_t)r * K + k0);
            cpasync16(sB + off, Bb + (size_t)r * K + k0);
        }
        CP_COMMIT();
    };

    load_stage(0, 0);
    load_stage(1, 1);

    for (int kt = 0; kt < KT; ++kt) {
        if (kt + 1 < KT) CP_WAIT(1); else CP_WAIT(0);
        __syncthreads();
        if (kt + 2 < KT) load_stage(kt + 2, (kt + 2) % 3);

        const uint32_t sA = sbase + (kt % 3) * TG_STAGE;
        const uint32_t sB = sA + 16384;

        #pragma unroll
        for (int ks = 0; ks < 4; ++ks) {
            const int chunkA = ks * 2;
            uint32_t af[4][4];
            #pragma unroll
            for (int mt = 0; mt < 4; ++mt) {
                const int row = wm * 64 + mt * 16 + aRow;
                const uint32_t ad = sA + swz((uint32_t)(row * 128 + (chunkA + aChk) * 16));
                ldmx4(af[mt][0], af[mt][1], af[mt][2], af[mt][3], ad);
            }
            uint32_t bf[4][2];
            #pragma unroll
            for (int np = 0; np < 2; ++np) {
                const int nrow = wn * 32 + np * 16 + bRow;
                const uint32_t bd = sB + swz((uint32_t)(nrow * 128 + (chunkA + bChk) * 16));
                uint32_t t0, t1, t2, t3;
                ldmx4(t0, t1, t2, t3, bd);
                bf[np * 2][0] = t0;     bf[np * 2][1] = t1;
                bf[np * 2 + 1][0] = t2; bf[np * 2 + 1][1] = t3;
            }
            #pragma unroll
            for (int mt = 0; mt < 4; ++mt)
                #pragma unroll
                for (int nt = 0; nt < 4; ++nt)
                    mma_tf32(acc[mt][nt][0], acc[mt][nt][1],
                             acc[mt][nt][2], acc[mt][nt][3],
                             af[mt][0], af[mt][1], af[mt][2], af[mt][3],
                             bf[nt][0], bf[nt][1]);
        }
    }

    #pragma unroll
    for (int mt = 0; mt < 4; mt++) {
        const int r0g = brow * 128 + wm * 64 + mt * 16 + g;
        const int r1g = r0g + 8;
        #pragma unroll
        for (int nt = 0; nt < 4; nt++) {
            const int c = bcol * 128 + wn * 32 + nt * 8 + tg * 2;
            float2 o0 = make_float2(acc[mt][nt][0], acc[mt][nt][1]);
            float2 o1 = make_float2(acc[mt][nt][2], acc[mt][nt][3]);
            if constexpr (EPI >= 1) {
                float2 bv = *reinterpret_cast<const float2*>(bias + c);
                o0.x += bv.x; o0.y += bv.y;
                o1.x += bv.x; o1.y += bv.y;
            }
            if constexpr (EPI == 1) {
                float2 rv0 = *reinterpret_cast<const float2*>(resid + (size_t)r0g * N + c);
                float2 rv1 = *reinterpret_cast<const float2*>(resid + (size_t)r1g * N + c);
                o0.x += rv0.x; o0.y += rv0.y;
                o1.x += rv1.x; o1.y += rv1.y;
            }
            if constexpr (EPI == 2) {
                o0.x = fmaxf(o0.x, 0.f); o0.y = fmaxf(o0.y, 0.f);
                o1.x = fmaxf(o1.x, 0.f); o1.y = fmaxf(o1.y, 0.f);
            }
            if constexpr (EPI == 0 || EPI == 2) {
                o0.x = f2tf32(o0.x); o0.y = f2tf32(o0.y);
                o1.x = f2tf32(o1.x); o1.y = f2tf32(o1.y);
            }
            *reinterpret_cast<float2*>(C + (size_t)r0g * N + c) = o0;
            *reinterpret_cast<float2*>(C + (size_t)r1g * N + c) = o1;
        }
    }
}

// ---------------- fast exp2 (fma pipe) ----------------
__device__ __forceinline__ float fexp2(float x) {
    x = fmaxf(x, -120.f);
    float k  = __fadd_rn(x, 12582912.f);
    int   sc = __float_as_int(k) << 23;
    float f  = __fsub_rn(x, __fsub_rn(k, 12582912.f));
    float p  = 0.0013333558f;
    p = fmaf(p, f, 0.0096181291f);
    p = fmaf(p, f, 0.0555041087f);
    p = fmaf(p, f, 0.2402265070f);
    p = fmaf(p, f, 0.6931471806f);
    p = fmaf(p, f, 1.0f);
    return __int_as_float(__float_as_int(p) + sc);
}

// ---------------- flash attention v4 ----------------
// 64-q x 64-k tiles, 128 threads (4 warps x 16 rows), 4 CTAs/SM.
// ldmatrix Q/K; V [key][d] stride 72 scalar B-frags; P via register shfl (no smem).
#define FS   68
#define VS_S 72
#define FA_SMEM ((64*FS + 64*FS + 64*VS_S) * 4)

__global__ __launch_bounds__(128, 4) void flash_tc(
    const float* __restrict__ qkv, float* __restrict__ out)
{
    extern __shared__ float sm[];
    float* Qs = sm;                 // [64][68]
    float* Ks = Qs + 64 * FS;       // [64][68]
    float* Vs = Ks + 64 * FS;       // [64][72]

    const int tid  = threadIdx.x;
    const int warp = tid >> 5;
    const int lane = tid & 31;
    const int g    = lane >> 2;
    const int tg   = lane & 3;
    const int qb   = gridDim.x - 1 - blockIdx.x;   // heavy blocks first
    const int h    = blockIdx.y;
    const int q0   = qb * 64;
    const int w16  = warp * 16;

    const int aRow = (lane & 7) + ((lane >> 3) & 1) * 8;
    const int aChk = lane >> 4;
    const int bRow = (lane & 7) + (lane >> 4) * 8;
    const int bChk = (lane >> 3) & 1;

    const float* qp = qkv + h * HSZ;
    const float* kp = qkv + DD + h * HSZ;
    const float* vp = qkv + 2 * DD + h * HSZ;

    // load Q tile via cp.async (64 rows x 16 chunks / 128 thr = 8 each)
    {
        const uint32_t qsb = smem_u32(Qs);
        #pragma unroll
        for (int j = 0; j < 8; ++j) {
            int idx = j * 128 + tid;
            int r = idx >> 4, c4 = idx & 15;
            cpasync16(qsb + (uint32_t)((r * FS + c4 * 4) * 4),
                      qp + (size_t)(q0 + r) * (3 * DD) + c4 * 4);
        }
        CP_COMMIT();
    }

    float O[8][4];
    #pragma unroll
    for (int nt = 0; nt < 8; nt++)
        #pragma unroll
        for (int i = 0; i < 4; i++) O[nt][i] = 0.f;
    float m0 = -1e30f, m1 = -1e30f, l0 = 0.f, l1 = 0.f;

    const int row0 = q0 + w16 + g;
    const int row1 = row0 + 8;
    const float SC = 0.18033688011112042f;   // (1/8) * log2(e)
    const int nkt = qb + 1;

    const uint32_t qbase = smem_u32(Qs) + (uint32_t)((w16 + aRow) * FS * 4 + aChk * 16);
    const uint32_t kbase = smem_u32(Ks) + (uint32_t)(bRow * FS * 4 + bChk * 16);
    const uint32_t ksb = smem_u32(Ks);
    const uint32_t vsb = smem_u32(Vs);

    const int srcL  = (g << 2) + (tg >> 1);      // shfl src for cols tg
    const int srcH  = srcL + 2;                  // shfl src for cols tg+4
    const bool odd  = (tg & 1) != 0;

    for (int kt = 0; kt < nkt; ++kt) {
        __syncthreads();    // previous tile's compute done; buffers free
        {
            #pragma unroll
            for (int j = 0; j < 8; ++j) {
                int idx = j * 128 + tid;
                int r = idx >> 4, c4 = idx & 15;
                size_t gi = (size_t)(kt * 64 + r) * (3 * DD) + c4 * 4;
                cpasync16(ksb + (uint32_t)((r * FS + c4 * 4) * 4), kp + gi);
                cpasync16(vsb + (uint32_t)((r * VS_S + c4 * 4) * 4), vp + gi);
            }
            CP_COMMIT();
        }
        CP_WAIT(0);
        __syncthreads();

        // ---- S = Q K^T (ldmatrix frags) ----
        float s[8][4];
        #pragma unroll
        for (int nt = 0; nt < 8; nt++)
            #pragma unroll
            for (int i = 0; i < 4; i++) s[nt][i] = 0.f;

        #pragma unroll
        for (int kk = 0; kk < 8; ++kk) {
            uint32_t a0, a1, a2, a3;
            ldmx4(a0, a1, a2, a3, qbase + kk * 32);
            uint32_t bf[8][2];
            #pragma unroll
            for (int n16 = 0; n16 < 4; ++n16) {
                uint32_t t0, t1, t2, t3;
                ldmx4(t0, t1, t2, t3, kbase + (uint32_t)(n16 * 16 * FS * 4) + kk * 32);
                bf[n16 * 2][0] = t0;     bf[n16 * 2][1] = t1;
                bf[n16 * 2 + 1][0] = t2; bf[n16 * 2 + 1][1] = t3;
            }
            #pragma unroll
            for (int nt = 0; nt < 8; ++nt)
                mma_tf32(s[nt][0], s[nt][1], s[nt][2], s[nt][3],
                         a0, a1, a2, a3, bf[nt][0], bf[nt][1]);
        }

        // ---- softmax (log2 domain), causal mask; P kept in regs (tf32-rounded) ----
        float mb0 = -1e30f, mb1 = -1e30f;
        #pragma unroll
        for (int nt = 0; nt < 8; ++nt) {
            int c0 = kt * 64 + nt * 8 + 2 * tg;
            float z0 = (c0     > row0) ? -1e30f : s[nt][0] * SC;
            float z1 = (c0 + 1 > row0) ? -1e30f : s[nt][1] * SC;
            float z2 = (c0     > row1) ? -1e30f : s[nt][2] * SC;
            float z3 = (c0 + 1 > row1) ? -1e30f : s[nt][3] * SC;
            s[nt][0] = z0; s[nt][1] = z1; s[nt][2] = z2; s[nt][3] = z3;
            mb0 = fmaxf(mb0, fmaxf(z0, z1));
            mb1 = fmaxf(mb1, fmaxf(z2, z3));
        }
        mb0 = fmaxf(mb0, __shfl_xor_sync(0xffffffffu, mb0, 1));
        mb0 = fmaxf(mb0, __shfl_xor_sync(0xffffffffu, mb0, 2));
        mb1 = fmaxf(mb1, __shfl_xor_sync(0xffffffffu, mb1, 1));
        mb1 = fmaxf(mb1, __shfl_xor_sync(0xffffffffu, mb1, 2));

        float mn0 = fmaxf(m0, mb0), mn1 = fmaxf(m1, mb1);
        float al0 = fexp2(m0 - mn0), al1 = fexp2(m1 - mn1);
        m0 = mn0; m1 = mn1;

        float rs0 = 0.f, rs1 = 0.f;
        #pragma unroll
        for (int nt = 0; nt < 8; ++nt) {
            float p0 = fexp2(s[nt][0] - mn0);
            float p1 = fexp2(s[nt][1] - mn0);
            float p2 = fexp2(s[nt][2] - mn1);
            float p3 = fexp2(s[nt][3] - mn1);
            rs0 += p0 + p1; rs1 += p2 + p3;
            s[nt][0] = f2tf32(p0);
            s[nt][1] = f2tf32(p1);
            s[nt][2] = f2tf32(p2);
            s[nt][3] = f2tf32(p3);
        }
        rs0 += __shfl_xor_sync(0xffffffffu, rs0, 1);
        rs0 += __shfl_xor_sync(0xffffffffu, rs0, 2);
        rs1 += __shfl_xor_sync(0xffffffffu, rs1, 1);
        rs1 += __shfl_xor_sync(0xffffffffu, rs1, 2);
        l0 = l0 * al0 + rs0;
        l1 = l1 * al1 + rs1;

        #pragma unroll
        for (int nt = 0; nt < 8; ++nt) {
            O[nt][0] *= al0; O[nt][1] *= al0;
            O[nt][2] *= al1; O[nt][3] *= al1;
        }

        // ---- O += P V : P A-frags via register shfl; V B-frags via scalar LDS ----
        #pragma unroll
        for (int kk = 0; kk < 8; ++kk) {
            float v00 = __shfl_sync(0xffffffffu, s[kk][0], srcL);
            float v01 = __shfl_sync(0xffffffffu, s[kk][1], srcL);
            float v10 = __shfl_sync(0xffffffffu, s[kk][2], srcL);
            float v11 = __shfl_sync(0xffffffffu, s[kk][3], srcL);
            float v20 = __shfl_sync(0xffffffffu, s[kk][0], srcH);
            float v21 = __shfl_sync(0xffffffffu, s[kk][1], srcH);
            float v30 = __shfl_sync(0xffffffffu, s[kk][2], srcH);
            float v31 = __shfl_sync(0xffffffffu, s[kk][3], srcH);
            uint32_t a0 = __float_as_uint(odd ? v01 : v00);
            uint32_t a1 = __float_as_uint(odd ? v11 : v10);
            uint32_t a2 = __float_as_uint(odd ? v21 : v20);
            uint32_t a3 = __float_as_uint(odd ? v31 : v30);
            #pragma unroll
            for (int nt = 0; nt < 8; ++nt) {
                uint32_t b0 = __float_as_uint(Vs[(kk * 8 + tg) * VS_S + nt * 8 + g]);
                uint32_t b1 = __float_as_uint(Vs[(kk * 8 + tg + 4) * VS_S + nt * 8 + g]);
                mma_tf32(O[nt][0], O[nt][1], O[nt][2], O[nt][3],
                         a0, a1, a2, a3, b0, b1);
            }
        }
    }

    // normalize + round to tf32 (feeds Wo GEMM) + write
    float inv0 = 1.0f / l0, inv1 = 1.0f / l1;
    #pragma unroll
    for (int nt = 0; nt < 8; ++nt) {
        int c = h * HSZ + nt * 8 + 2 * tg;
        float2 o0 = make_float2(f2tf32(O[nt][0] * inv0), f2tf32(O[nt][1] * inv0));
        float2 o1 = make_float2(f2tf32(O[nt][2] * inv1), f2tf32(O[nt][3] * inv1));
        *reinterpret_cast<float2*>(out + (size_t)row0 * DD + c) = o0;
        *reinterpret_cast<float2*>(out + (size_t)row1 * DD + c) = o1;
    }
}

// ---------------- launch ----------------
extern "C" void kernel_launch(void* const* d_in, const int* in_sizes, int n_in,
                              void* d_out, int out_size)
{
    const float* x    = (const float*)d_in[0];
    const float* Wq   = (const float*)d_in[1];
    const float* Wk   = (const float*)d_in[2];
    const float* Wv   = (const float*)d_in[3];
    const float* Wo   = (const float*)d_in[4];
    const float* bo   = (const float*)d_in[5];
    const float* W1   = (const float*)d_in[6];
    const float* b1   = (const float*)d_in[7];
    const float* W2   = (const float*)d_in[8];
    const float* b2   = (const float*)d_in[9];
    const float* ln1s = (const float*)d_in[10];
    const float* ln1b = (const float*)d_in[11];
    const float* ln2s = (const float*)d_in[12];
    const float* ln2b = (const float*)d_in[13];
    float* out = (float*)d_out;

    float *h, *wqkvT, *woT, *w1T, *w2T, *qkv, *att, *x2, *ff;
    cudaGetSymbolAddress((void**)&h,     g_h);
    cudaGetSymbolAddress((void**)&wqkvT, g_wqkvT);
    cudaGetSymbolAddress((void**)&woT,   g_WoT);
    cudaGetSymbolAddress((void**)&w1T,   g_W1T);
    cudaGetSymbolAddress((void**)&w2T,   g_W2T);
    cudaGetSymbolAddress((void**)&qkv,   g_qkv);
    cudaGetSymbolAddress((void**)&att,   g_att);
    cudaGetSymbolAddress((void**)&x2,    g_x2);
    cudaGetSymbolAddress((void**)&ff,    g_ff);

    cudaFuncSetAttribute(flash_tc, cudaFuncAttributeMaxDynamicSharedMemorySize, FA_SMEM);
    cudaFuncSetAttribute(tg2<0>, cudaFuncAttributeMaxDynamicSharedMemorySize, TG_SMEM);
    cudaFuncSetAttribute(tg2<1>, cudaFuncAttributeMaxDynamicSharedMemorySize, TG_SMEM);
    cudaFuncSetAttribute(tg2<2>, cudaFuncAttributeMaxDynamicSharedMemorySize, TG_SMEM);

    // 1. LN1
    ln_kernel<<<TT, 256>>>(x, ln1s, ln1b, h);
    // 2. ALL weight transposes in one launch
    transpose_all<<<12288, dim3(32, 8)>>>(Wq, Wk, Wv, Wo, W1, W2,
                                          wqkvT, woT, w1T, w2T);
    // 3. QKV GEMM (rounded output)
    tg2<0><<<dim3(3 * DD / 128, TT / 128), 256, TG_SMEM>>>(
        TT, 3 * DD, DD, h, wqkvT, nullptr, nullptr, qkv);
    // 4. causal flash attention (rounded output), 64-q blocks
    flash_tc<<<dim3(TT / 64, HH), 128, FA_SMEM>>>(qkv, att);
    // 5. output proj + bias + residual (fp32 output)
    tg2<1><<<dim3(DD / 128, TT / 128), 256, TG_SMEM>>>(
        TT, DD, DD, att, woT, bo, x, x2);
    // 6. LN2
    ln_kernel<<<TT, 256>>>(x2, ln2s, ln2b, h);
    // 7. FFN1 (rounded output)
    tg2<2><<<dim3(DFF / 128, TT / 128), 256, TG_SMEM>>>(
        TT, DFF, DD, h, w1T, b1, nullptr, ff);
    // 8. FFN2 (fp32 output)
    tg2<1><<<dim3(DD / 128, TT / 128), 256, TG_SMEM>>>(
        TT, DD, DFF, ff, w2T, b2, x2, out);
}

// round 10
// speedup vs baseline: 1.3989x; 1.0620x over previous
#include <cuda_runtime.h>
#include <cstdint>

#define TT 2048
#define DD 1024
#define HH 16
#define HSZ 64
#define DFF 4096

// ---------------- scratch (no allocs allowed) ----------------
__device__ float g_h[TT * DD];            // LN output (tf32-rounded)
__device__ float g_wqkvT[3 * DD * DD];    // QKV weights, [3D][D] K-major (tf32)
__device__ float g_WoT[DD * DD];          // Wo^T
__device__ float g_W1T[DD * DFF];         // W1^T
__device__ float g_W2T[DFF * DD];         // W2^T
__device__ float g_qkv[TT * 3 * DD];      // QKV activations [T, 3D] (tf32)
__device__ float g_att[TT * DD];          // attention output [T, D] (tf32)
__device__ float g_x2[TT * DD];           // residual after attention (fp32)
__device__ float g_ff[TT * DFF];          // FFN hidden (tf32)
// split-K partials: h(16) x qb16(16) x seg(2) x 64 rows x 64 cols
__device__ float g_pO[16 * 16 * 2 * 64 * 64];    // 8 MB
__device__ float g_pml[16 * 16 * 2 * 64 * 2];    // per-row (m, l)

// ---------------- helpers ----------------
__device__ __forceinline__ uint32_t smem_u32(const void* p) {
    return (uint32_t)__cvta_generic_to_shared(p);
}
__device__ __forceinline__ float f2tf32(float x) {
    uint32_t r;
    asm("cvt.rna.tf32.f32 %0, %1;" : "=r"(r) : "f"(x));
    return __uint_as_float(r);
}
__device__ __forceinline__ uint32_t swz(uint32_t off) {
    return off ^ ((off >> 3) & 0x70);
}
__device__ __forceinline__ void mma_tf32(
    float& d0, float& d1, float& d2, float& d3,
    uint32_t a0, uint32_t a1, uint32_t a2, uint32_t a3,
    uint32_t b0, uint32_t b1)
{
    asm volatile(
        "mma.sync.aligned.m16n8k8.row.col.f32.tf32.tf32.f32 "
        "{%0,%1,%2,%3}, {%4,%5,%6,%7}, {%8,%9}, {%0,%1,%2,%3};\n"
        : "+f"(d0), "+f"(d1), "+f"(d2), "+f"(d3)
        : "r"(a0), "r"(a1), "r"(a2), "r"(a3), "r"(b0), "r"(b1));
}
__device__ __forceinline__ void ldmx4(
    uint32_t& r0, uint32_t& r1, uint32_t& r2, uint32_t& r3, uint32_t addr)
{
    asm volatile("ldmatrix.sync.aligned.m8n8.x4.shared.b16 {%0,%1,%2,%3}, [%4];"
                 : "=r"(r0), "=r"(r1), "=r"(r2), "=r"(r3) : "r"(addr) : "memory");
}
__device__ __forceinline__ void cpasync16(uint32_t saddr, const void* gaddr) {
    asm volatile("cp.async.cg.shared.global [%0], [%1], 16;" :: "r"(saddr), "l"(gaddr));
}
#define CP_COMMIT() asm volatile("cp.async.commit_group;" ::: "memory")
#define CP_WAIT(n)  asm volatile("cp.async.wait_group %0;" :: "n"(n) : "memory")

// ---------------- LayerNorm (emits tf32-rounded values) ----------------
__global__ __launch_bounds__(256) void ln_kernel(
    const float* __restrict__ x, const float* __restrict__ g,
    const float* __restrict__ b, float* __restrict__ y)
{
    int row = blockIdx.x;
    int tid = threadIdx.x;
    float4 v = reinterpret_cast<const float4*>(x + (size_t)row * DD)[tid];
    float s  = v.x + v.y + v.z + v.w;
    float ss = v.x * v.x + v.y * v.y + v.z * v.z + v.w * v.w;
    #pragma unroll
    for (int o = 16; o > 0; o >>= 1) {
        s  += __shfl_xor_sync(0xffffffffu, s, o);
        ss += __shfl_xor_sync(0xffffffffu, ss, o);
    }
    __shared__ float sb[8], ssb[8], stats[2];
    int wid = tid >> 5, lane = tid & 31;
    if (lane == 0) { sb[wid] = s; ssb[wid] = ss; }
    __syncthreads();
    if (tid == 0) {
        float a = 0.f, c = 0.f;
        #pragma unroll
        for (int i = 0; i < 8; i++) { a += sb[i]; c += ssb[i]; }
        float mean = a * (1.0f / DD);
        float var  = c * (1.0f / DD) - mean * mean;
        stats[0] = mean;
        stats[1] = rsqrtf(var + 1e-6f);
    }
    __syncthreads();
    float mean = stats[0], rstd = stats[1];
    float4 gg = reinterpret_cast<const float4*>(g)[tid];
    float4 bb = reinterpret_cast<const float4*>(b)[tid];
    float4 o;
    o.x = f2tf32((v.x - mean) * rstd * gg.x + bb.x);
    o.y = f2tf32((v.y - mean) * rstd * gg.y + bb.y);
    o.z = f2tf32((v.z - mean) * rstd * gg.z + bb.z);
    o.w = f2tf32((v.w - mean) * rstd * gg.w + bb.w);
    reinterpret_cast<float4*>(y + (size_t)row * DD)[tid] = o;
}

// ---------------- ALL weight transposes in one launch ----------------
__global__ __launch_bounds__(256) void transpose_all(
    const float* __restrict__ Wq, const float* __restrict__ Wk,
    const float* __restrict__ Wv, const float* __restrict__ Wo,
    const float* __restrict__ W1, const float* __restrict__ W2,
    float* __restrict__ wqkvT, float* __restrict__ woT,
    float* __restrict__ w1T, float* __restrict__ w2T)
{
    __shared__ float t[32][33];
    const int b = blockIdx.x;
    const float* ip; float* op;
    int R, C, bx, by;
    if (b < 3072) {
        const int w = b >> 10;
        const int r = b & 1023;
        const int head = r >> 6;
        const int rr = r & 63;
        bx = (rr & 1) * 32;
        by = (rr >> 1) * 32;
        ip = (w == 0 ? Wq : (w == 1 ? Wk : Wv)) + (size_t)head * DD * HSZ;
        op = wqkvT + (size_t)w * DD * DD + (size_t)head * HSZ * DD;
        R = DD; C = HSZ;
    } else if (b < 4096) {
        const int r = b - 3072;
        bx = (r & 31) * 32; by = (r >> 5) * 32;
        ip = Wo; op = woT; R = DD; C = DD;
    } else if (b < 8192) {
        const int r = b - 4096;
        bx = (r & 127) * 32; by = (r >> 7) * 32;
        ip = W1; op = w1T; R = DD; C = DFF;
    } else {
        const int r = b - 8192;
        bx = (r & 31) * 32; by = (r >> 5) * 32;
        ip = W2; op = w2T; R = DFF; C = DD;
    }
    const int x = threadIdx.x, y = threadIdx.y;
    #pragma unroll
    for (int j = 0; j < 32; j += 8)
        t[y + j][x] = ip[(size_t)(by + y + j) * C + bx + x];
    __syncthreads();
    #pragma unroll
    for (int j = 0; j < 32; j += 8)
        op[(size_t)(bx + y + j) * R + by + x] = f2tf32(t[x][y + j]);
}

// ---------------- tf32 mma.sync GEMM (frozen) ----------------
#define TG_STAGE 32768
#define TG_SMEM  (3 * TG_STAGE)

template <int EPI>
__global__ __launch_bounds__(256, 1) void tg2(
    int M, int N, int K,
    const float* __restrict__ A, const float* __restrict__ Bt,
    const float* __restrict__ bias, const float* __restrict__ resid,
    float* __restrict__ C)
{
    extern __shared__ float dynsm[];
    const int tid  = threadIdx.x;
    const int warp = tid >> 5, lane = tid & 31;
    const int wm = warp & 1, wn = warp >> 1;
    const int g = lane >> 2, tg = lane & 3;
    const int brow = blockIdx.y, bcol = blockIdx.x;

    const uint32_t sbase = smem_u32(dynsm);
    const int r0 = tid >> 3;
    const int ck = tid & 7;
    const float* Ab = A  + (size_t)(brow * 128) * K + ck * 4;
    const float* Bb = Bt + (size_t)(bcol * 128) * K + ck * 4;
    const int KT = K >> 5;

    const int aRow = (lane & 7) + ((lane >> 3) & 1) * 8;
    const int aChk = (lane >> 4);
    const int bRow = (lane & 7) + (lane >> 4) * 8;
    const int bChk = (lane >> 3) & 1;

    float acc[4][4][4];
    #pragma unroll
    for (int mt = 0; mt < 4; mt++)
        #pragma unroll
        for (int nt = 0; nt < 4; nt++)
            #pragma unroll
            for (int i = 0; i < 4; i++) acc[mt][nt][i] = 0.f;

    auto load_stage = [&](int kt, int s) {
        const uint32_t sA = sbase + s * TG_STAGE;
        const uint32_t sB = sA + 16384;
        const int k0 = kt * 32;
        #pragma unroll
        for (int j = 0; j < 4; ++j) {
            const int r = j * 32 + r0;
            const uint32_t off = swz((uint32_t)(r * 128 + ck * 16));
            cpasync16(sA + off, Ab + (size_t)r * K + k0);
            cpasync16(sB + off, Bb + (size_t)r * K + k0);
        }
        CP_COMMIT();
    };

    load_stage(0, 0);
    load_stage(1, 1);

    for (int kt = 0; kt < KT; ++kt) {
        if (kt + 1 < KT) CP_WAIT(1); else CP_WAIT(0);
        __syncthreads();
        if (kt + 2 < KT) load_stage(kt + 2, (kt + 2) % 3);

        const uint32_t sA = sbase + (kt % 3) * TG_STAGE;
        const uint32_t sB = sA + 16384;

        #pragma unroll
        for (int ks = 0; ks < 4; ++ks) {
            const int chunkA = ks * 2;
            uint32_t af[4][4];
            #pragma unroll
            for (int mt = 0; mt < 4; ++mt) {
                const int row = wm * 64 + mt * 16 + aRow;
                const uint32_t ad = sA + swz((uint32_t)(row * 128 + (chunkA + aChk) * 16));
                ldmx4(af[mt][0], af[mt][1], af[mt][2], af[mt][3], ad);
            }
            uint32_t bf[4][2];
            #pragma unroll
            for (int np = 0; np < 2; ++np) {
                const int nrow = wn * 32 + np * 16 + bRow;
                const uint32_t bd = sB + swz((uint32_t)(nrow * 128 + (chunkA + bChk) * 16));
                uint32_t t0, t1, t2, t3;
                ldmx4(t0, t1, t2, t3, bd);
                bf[np * 2][0] = t0;     bf[np * 2][1] = t1;
                bf[np * 2 + 1][0] = t2; bf[np * 2 + 1][1] = t3;
            }
            #pragma unroll
            for (int mt = 0; mt < 4; ++mt)
                #pragma unroll
                for (int nt = 0; nt < 4; ++nt)
                    mma_tf32(acc[mt][nt][0], acc[mt][nt][1],
                             acc[mt][nt][2], acc[mt][nt][3],
                             af[mt][0], af[mt][1], af[mt][2], af[mt][3],
                             bf[nt][0], bf[nt][1]);
        }
    }

    #pragma unroll
    for (int mt = 0; mt < 4; mt++) {
        const int r0g = brow * 128 + wm * 64 + mt * 16 + g;
        const int r1g = r0g + 8;
        #pragma unroll
        for (int nt = 0; nt < 4; nt++) {
            const int c = bcol * 128 + wn * 32 + nt * 8 + tg * 2;
            float2 o0 = make_float2(acc[mt][nt][0], acc[mt][nt][1]);
            float2 o1 = make_float2(acc[mt][nt][2], acc[mt][nt][3]);
            if constexpr (EPI >= 1) {
                float2 bv = *reinterpret_cast<const float2*>(bias + c);
                o0.x += bv.x; o0.y += bv.y;
                o1.x += bv.x; o1.y += bv.y;
            }
            if constexpr (EPI == 1) {
                float2 rv0 = *reinterpret_cast<const float2*>(resid + (size_t)r0g * N + c);
                float2 rv1 = *reinterpret_cast<const float2*>(resid + (size_t)r1g * N + c);
                o0.x += rv0.x; o0.y += rv0.y;
                o1.x += rv1.x; o1.y += rv1.y;
            }
            if constexpr (EPI == 2) {
                o0.x = fmaxf(o0.x, 0.f); o0.y = fmaxf(o0.y, 0.f);
                o1.x = fmaxf(o1.x, 0.f); o1.y = fmaxf(o1.y, 0.f);
            }
            if constexpr (EPI == 0 || EPI == 2) {
                o0.x = f2tf32(o0.x); o0.y = f2tf32(o0.y);
                o1.x = f2tf32(o1.x); o1.y = f2tf32(o1.y);
            }
            *reinterpret_cast<float2*>(C + (size_t)r0g * N + c) = o0;
            *reinterpret_cast<float2*>(C + (size_t)r1g * N + c) = o1;
        }
    }
}

// ---------------- fast exp2 (fma pipe) ----------------
__device__ __forceinline__ float fexp2(float x) {
    x = fmaxf(x, -120.f);
    float k  = __fadd_rn(x, 12582912.f);
    int   sc = __float_as_int(k) << 23;
    float f  = __fsub_rn(x, __fsub_rn(k, 12582912.f));
    float p  = 0.0013333558f;
    p = fmaf(p, f, 0.0096181291f);
    p = fmaf(p, f, 0.0555041087f);
    p = fmaf(p, f, 0.2402265070f);
    p = fmaf(p, f, 0.6931471806f);
    p = fmaf(p, f, 1.0f);
    return __int_as_float(__float_as_int(p) + sc);
}

// ---------------- flash attention v5: split-K over key tiles ----------------
// 64-q x 64-k tiles, 128 threads, 4 CTAs/SM. Max 16 k-tiles per block.
// grid.x = 48:  bx<32 -> qb = 16 + bx/2, seg = bx&1 (heavy segs first)
//               bx>=32 -> qb = bx-32, seg = 0 (full block)
#define FS   68
#define VS_S 72
#define FA_SMEM ((64*FS + 64*FS + 64*VS_S) * 4)

__global__ __launch_bounds__(128, 4) void flash_tc(
    const float* __restrict__ qkv, float* __restrict__ out,
    float* __restrict__ pO, float* __restrict__ pml)
{
    extern __shared__ float sm[];
    float* Qs = sm;
    float* Ks = Qs + 64 * FS;
    float* Vs = Ks + 64 * FS;

    const int tid  = threadIdx.x;
    const int warp = tid >> 5;
    const int lane = tid & 31;
    const int g    = lane >> 2;
    const int tg   = lane & 3;
    const int bx   = blockIdx.x;
    const int h    = blockIdx.y;
    int qb, seg;
    if (bx < 32) { qb = 16 + (bx >> 1); seg = bx & 1; }
    else         { qb = bx - 32;        seg = 0; }
    const int q0   = qb * 64;
    const int w16  = warp * 16;
    const int kt0  = seg * 16;
    const int kt1  = min(qb + 1, kt0 + 16);
    const bool full = (kt0 == 0) && (kt1 == qb + 1);

    const int aRow = (lane & 7) + ((lane >> 3) & 1) * 8;
    const int aChk = lane >> 4;
    const int bRow = (lane & 7) + (lane >> 4) * 8;
    const int bChk = (lane >> 3) & 1;

    const float* qp = qkv + h * HSZ;
    const float* kp = qkv + DD + h * HSZ;
    const float* vp = qkv + 2 * DD + h * HSZ;

    {
        const uint32_t qsb = smem_u32(Qs);
        #pragma unroll
        for (int j = 0; j < 8; ++j) {
            int idx = j * 128 + tid;
            int r = idx >> 4, c4 = idx & 15;
            cpasync16(qsb + (uint32_t)((r * FS + c4 * 4) * 4),
                      qp + (size_t)(q0 + r) * (3 * DD) + c4 * 4);
        }
        CP_COMMIT();
    }

    float O[8][4];
    #pragma unroll
    for (int nt = 0; nt < 8; nt++)
        #pragma unroll
        for (int i = 0; i < 4; i++) O[nt][i] = 0.f;
    float m0 = -1e30f, m1 = -1e30f, l0 = 0.f, l1 = 0.f;

    const int row0 = q0 + w16 + g;
    const int row1 = row0 + 8;
    const float SC = 0.18033688011112042f;   // (1/8) * log2(e)

    const uint32_t qbase = smem_u32(Qs) + (uint32_t)((w16 + aRow) * FS * 4 + aChk * 16);
    const uint32_t kbase = smem_u32(Ks) + (uint32_t)(bRow * FS * 4 + bChk * 16);
    const uint32_t ksb = smem_u32(Ks);
    const uint32_t vsb = smem_u32(Vs);

    const int srcL  = (g << 2) + (tg >> 1);
    const int srcH  = srcL + 2;
    const bool odd  = (tg & 1) != 0;

    for (int kt = kt0; kt < kt1; ++kt) {
        __syncthreads();
        {
            #pragma unroll
            for (int j = 0; j < 8; ++j) {
                int idx = j * 128 + tid;
                int r = idx >> 4, c4 = idx & 15;
                size_t gi = (size_t)(kt * 64 + r) * (3 * DD) + c4 * 4;
                cpasync16(ksb + (uint32_t)((r * FS + c4 * 4) * 4), kp + gi);
                cpasync16(vsb + (uint32_t)((r * VS_S + c4 * 4) * 4), vp + gi);
            }
            CP_COMMIT();
        }
        CP_WAIT(0);
        __syncthreads();

        float s[8][4];
        #pragma unroll
        for (int nt = 0; nt < 8; nt++)
            #pragma unroll
            for (int i = 0; i < 4; i++) s[nt][i] = 0.f;

        #pragma unroll
        for (int kk = 0; kk < 8; ++kk) {
            uint32_t a0, a1, a2, a3;
            ldmx4(a0, a1, a2, a3, qbase + kk * 32);
            uint32_t bf[8][2];
            #pragma unroll
            for (int n16 = 0; n16 < 4; ++n16) {
                uint32_t t0, t1, t2, t3;
                ldmx4(t0, t1, t2, t3, kbase + (uint32_t)(n16 * 16 * FS * 4) + kk * 32);
                bf[n16 * 2][0] = t0;     bf[n16 * 2][1] = t1;
                bf[n16 * 2 + 1][0] = t2; bf[n16 * 2 + 1][1] = t3;
            }
            #pragma unroll
            for (int nt = 0; nt < 8; ++nt)
                mma_tf32(s[nt][0], s[nt][1], s[nt][2], s[nt][3],
                         a0, a1, a2, a3, bf[nt][0], bf[nt][1]);
        }

        float mb0 = -1e30f, mb1 = -1e30f;
        #pragma unroll
        for (int nt = 0; nt < 8; ++nt) {
            int c0 = kt * 64 + nt * 8 + 2 * tg;
            float z0 = (c0     > row0) ? -1e30f : s[nt][0] * SC;
            float z1 = (c0 + 1 > row0) ? -1e30f : s[nt][1] * SC;
            float z2 = (c0     > row1) ? -1e30f : s[nt][2] * SC;
            float z3 = (c0 + 1 > row1) ? -1e30f : s[nt][3] * SC;
            s[nt][0] = z0; s[nt][1] = z1; s[nt][2] = z2; s[nt][3] = z3;
            mb0 = fmaxf(mb0, fmaxf(z0, z1));
            mb1 = fmaxf(mb1, fmaxf(z2, z3));
        }
        mb0 = fmaxf(mb0, __shfl_xor_sync(0xffffffffu, mb0, 1));
        mb0 = fmaxf(mb0, __shfl_xor_sync(0xffffffffu, mb0, 2));
        mb1 = fmaxf(mb1, __shfl_xor_sync(0xffffffffu, mb1, 1));
        mb1 = fmaxf(mb1, __shfl_xor_sync(0xffffffffu, mb1, 2));

        float mn0 = fmaxf(m0, mb0), mn1 = fmaxf(m1, mb1);
        float al0 = fexp2(m0 - mn0), al1 = fexp2(m1 - mn1);
        m0 = mn0; m1 = mn1;

        float rs0 = 0.f, rs1 = 0.f;
        #pragma unroll
        for (int nt = 0; nt < 8; ++nt) {
            float p0 = fexp2(s[nt][0] - mn0);
            float p1 = fexp2(s[nt][1] - mn0);
            float p2 = fexp2(s[nt][2] - mn1);
            float p3 = fexp2(s[nt][3] - mn1);
            rs0 += p0 + p1; rs1 += p2 + p3;
            s[nt][0] = f2tf32(p0);
            s[nt][1] = f2tf32(p1);
            s[nt][2] = f2tf32(p2);
            s[nt][3] = f2tf32(p3);
        }
        rs0 += __shfl_xor_sync(0xffffffffu, rs0, 1);
        rs0 += __shfl_xor_sync(0xffffffffu, rs0, 2);
        rs1 += __shfl_xor_sync(0xffffffffu, rs1, 1);
        rs1 += __shfl_xor_sync(0xffffffffu, rs1, 2);
        l0 = l0 * al0 + rs0;
        l1 = l1 * al1 + rs1;

        #pragma unroll
        for (int nt = 0; nt < 8; ++nt) {
            O[nt][0] *= al0; O[nt][1] *= al0;
            O[nt][2] *= al1; O[nt][3] *= al1;
        }

        #pragma unroll
        for (int kk = 0; kk < 8; ++kk) {
            float v00 = __shfl_sync(0xffffffffu, s[kk][0], srcL);
            float v01 = __shfl_sync(0xffffffffu, s[kk][1], srcL);
            float v10 = __shfl_sync(0xffffffffu, s[kk][2], srcL);
            float v11 = __shfl_sync(0xffffffffu, s[kk][3], srcL);
            float v20 = __shfl_sync(0xffffffffu, s[kk][0], srcH);
            float v21 = __shfl_sync(0xffffffffu, s[kk][1], srcH);
            float v30 = __shfl_sync(0xffffffffu, s[kk][2], srcH);
            float v31 = __shfl_sync(0xffffffffu, s[kk][3], srcH);
            uint32_t a0 = __float_as_uint(odd ? v01 : v00);
            uint32_t a1 = __float_as_uint(odd ? v11 : v10);
            uint32_t a2 = __float_as_uint(odd ? v21 : v20);
            uint32_t a3 = __float_as_uint(odd ? v31 : v30);
            #pragma unroll
            for (int nt = 0; nt < 8; ++nt) {
                uint32_t b0 = __float_as_uint(Vs[(kk * 8 + tg) * VS_S + nt * 8 + g]);
                uint32_t b1 = __float_as_uint(Vs[(kk * 8 + tg + 4) * VS_S + nt * 8 + g]);
                mma_tf32(O[nt][0], O[nt][1], O[nt][2], O[nt][3],
                         a0, a1, a2, a3, b0, b1);
            }
        }
    }

    if (full) {
        float inv0 = 1.0f / l0, inv1 = 1.0f / l1;
        #pragma unroll
        for (int nt = 0; nt < 8; ++nt) {
            int c = h * HSZ + nt * 8 + 2 * tg;
            float2 o0 = make_float2(f2tf32(O[nt][0] * inv0), f2tf32(O[nt][1] * inv0));
            float2 o1 = make_float2(f2tf32(O[nt][2] * inv1), f2tf32(O[nt][3] * inv1));
            *reinterpret_cast<float2*>(out + (size_t)row0 * DD + c) = o0;
            *reinterpret_cast<float2*>(out + (size_t)row1 * DD + c) = o1;
        }
    } else {
        // partial: unnormalized O + per-row (m, l)
        const int p = (h * 16 + (qb - 16)) * 2 + seg;
        float* pb = pO + (size_t)p * 4096;
        const int lr0 = w16 + g, lr1 = lr0 + 8;
        #pragma unroll
        for (int nt = 0; nt < 8; ++nt) {
            int c = nt * 8 + 2 * tg;
            *reinterpret_cast<float2*>(pb + lr0 * 64 + c) = make_float2(O[nt][0], O[nt][1]);
            *reinterpret_cast<float2*>(pb + lr1 * 64 + c) = make_float2(O[nt][2], O[nt][3]);
        }
        if (tg == 0) {
            float* mlb = pml + (size_t)p * 128;
            mlb[lr0 * 2]     = m0;
            mlb[lr0 * 2 + 1] = l0;
            mlb[lr1 * 2]     = m1;
            mlb[lr1 * 2 + 1] = l1;
        }
    }
}

// ---------------- split-K merge: combine 2 segments for qb >= 16 ----------------
__global__ __launch_bounds__(128) void flash_merge(
    const float* __restrict__ pO, const float* __restrict__ pml,
    float* __restrict__ out)
{
    __shared__ float w0s[64], w1s[64];
    const int qb16 = blockIdx.x;     // 0..15 -> qb = 16+qb16
    const int h    = blockIdx.y;
    const int tid  = threadIdx.x;
    const int p0 = (h * 16 + qb16) * 2;
    const int p1 = p0 + 1;

    if (tid < 64) {
        float m0 = pml[(size_t)p0 * 128 + tid * 2];
        float l0 = pml[(size_t)p0 * 128 + tid * 2 + 1];
        float m1 = pml[(size_t)p1 * 128 + tid * 2];
        float l1 = pml[(size_t)p1 * 128 + tid * 2 + 1];
        float M  = fmaxf(m0, m1);
        float w0 = fexp2(m0 - M), w1 = fexp2(m1 - M);
        float inv = 1.0f / (w0 * l0 + w1 * l1);
        w0s[tid] = w0 * inv;
        w1s[tid] = w1 * inv;
    }
    __syncthreads();

    const float* b0 = pO + (size_t)p0 * 4096;
    const float* b1 = pO + (size_t)p1 * 4096;
    const int q0 = (16 + qb16) * 64;
    #pragma unroll
    for (int i = 0; i < 8; ++i) {
        int idx = (i * 128 + tid) * 4;
        int r = idx >> 6, c = idx & 63;
        float4 v0 = *reinterpret_cast<const float4*>(b0 + r * 64 + c);
        float4 v1 = *reinterpret_cast<const float4*>(b1 + r * 64 + c);
        float w0 = w0s[r], w1 = w1s[r];
        float4 o;
        o.x = f2tf32(w0 * v0.x + w1 * v1.x);
        o.y = f2tf32(w0 * v0.y + w1 * v1.y);
        o.z = f2tf32(w0 * v0.z + w1 * v1.z);
        o.w = f2tf32(w0 * v0.w + w1 * v1.w);
        *reinterpret_cast<float4*>(out + (size_t)(q0 + r) * DD + h * HSZ + c) = o;
    }
}

// ---------------- launch ----------------
extern "C" void kernel_launch(void* const* d_in, const int* in_sizes, int n_in,
                              void* d_out, int out_size)
{
    const float* x    = (const float*)d_in[0];
    const float* Wq   = (const float*)d_in[1];
    const float* Wk   = (const float*)d_in[2];
    const float* Wv   = (const float*)d_in[3];
    const float* Wo   = (const float*)d_in[4];
    const float* bo   = (const float*)d_in[5];
    const float* W1   = (const float*)d_in[6];
    const float* b1   = (const float*)d_in[7];
    const float* W2   = (const float*)d_in[8];
    const float* b2   = (const float*)d_in[9];
    const float* ln1s = (const float*)d_in[10];
    const float* ln1b = (const float*)d_in[11];
    const float* ln2s = (const float*)d_in[12];
    const float* ln2b = (const float*)d_in[13];
    float* out = (float*)d_out;

    float *h, *wqkvT, *woT, *w1T, *w2T, *qkv, *att, *x2, *ff, *pO, *pml;
    cudaGetSymbolAddress((void**)&h,     g_h);
    cudaGetSymbolAddress((void**)&wqkvT, g_wqkvT);
    cudaGetSymbolAddress((void**)&woT,   g_WoT);
    cudaGetSymbolAddress((void**)&w1T,   g_W1T);
    cudaGetSymbolAddress((void**)&w2T,   g_W2T);
    cudaGetSymbolAddress((void**)&qkv,   g_qkv);
    cudaGetSymbolAddress((void**)&att,   g_att);
    cudaGetSymbolAddress((void**)&x2,    g_x2);
    cudaGetSymbolAddress((void**)&ff,    g_ff);
    cudaGetSymbolAddress((void**)&pO,    g_pO);
    cudaGetSymbolAddress((void**)&pml,   g_pml);

    cudaFuncSetAttribute(flash_tc, cudaFuncAttributeMaxDynamicSharedMemorySize, FA_SMEM);
    cudaFuncSetAttribute(tg2<0>, cudaFuncAttributeMaxDynamicSharedMemorySize, TG_SMEM);
    cudaFuncSetAttribute(tg2<1>, cudaFuncAttributeMaxDynamicSharedMemorySize, TG_SMEM);
    cudaFuncSetAttribute(tg2<2>, cudaFuncAttributeMaxDynamicSharedMemorySize, TG_SMEM);

    // 1. LN1
    ln_kernel<<<TT, 256>>>(x, ln1s, ln1b, h);
    // 2. ALL weight transposes in one launch
    transpose_all<<<12288, dim3(32, 8)>>>(Wq, Wk, Wv, Wo, W1, W2,
                                          wqkvT, woT, w1T, w2T);
    // 3. QKV GEMM (rounded output)
    tg2<0><<<dim3(3 * DD / 128, TT / 128), 256, TG_SMEM>>>(
        TT, 3 * DD, DD, h, wqkvT, nullptr, nullptr, qkv);
    // 4. causal flash attention, split-K (max 16 k-tiles/block)
    flash_tc<<<dim3(48, HH), 128, FA_SMEM>>>(qkv, att, pO, pml);
    // 4b. merge split-K partials for qb >= 16
    flash_merge<<<dim3(16, HH), 128>>>(pO, pml, att);
    // 5. output proj + bias + residual (fp32 output)
    tg2<1><<<dim3(DD / 128, TT / 128), 256, TG_SMEM>>>(
        TT, DD, DD, att, woT, bo, x, x2);
    // 6. LN2
    ln_kernel<<<TT, 256>>>(x2, ln2s, ln2b, h);
    // 7. FFN1 (rounded output)
    tg2<2><<<dim3(DFF / 128, TT / 128), 256, TG_SMEM>>>(
        TT, DFF, DD, h, w1T, b1, nullptr, ff);
    // 8. FFN2 (fp32 output)
    tg2<1><<<dim3(DD / 128, TT / 128), 256, TG_SMEM>>>(
        TT, DD, DFF, ff, w2T, b2, x2, out);
}

// round 11
// speedup vs baseline: 2.1056x; 1.5052x over previous
#include <cuda_runtime.h>
#include <cuda_fp16.h>
#include <cstdint>

#define TT 2048
#define DD 1024
#define HH 16
#define HSZ 64
#define DFF 4096

// ---------------- scratch (no allocs allowed) ----------------
__device__ __half g_h[TT * DD];            // LN output (fp16)
__device__ __half g_wqkvT[3 * DD * DD];    // QKV weights, [3D][D] K-major (fp16)
__device__ __half g_WoT[DD * DD];          // Wo^T (fp16)
__device__ __half g_W1T[DD * DFF];         // W1^T (fp16)
__device__ __half g_W2T[DFF * DD];         // W2^T (fp16)
__device__ float  g_qkv[TT * 3 * DD];      // QKV activations (tf32-rounded fp32)
__device__ __half g_att[TT * DD];          // attention output (fp16)
__device__ float  g_x2[TT * DD];           // residual after attention (fp32)
__device__ __half g_ff[TT * DFF];          // FFN hidden (fp16)
__device__ float  g_pO[16 * 16 * 2 * 64 * 64];   // split-K partials
__device__ float  g_pml[16 * 16 * 2 * 64 * 2];

// ---------------- helpers ----------------
__device__ __forceinline__ uint32_t smem_u32(const void* p) {
    return (uint32_t)__cvta_generic_to_shared(p);
}
__device__ __forceinline__ float f2tf32(float x) {
    uint32_t r;
    asm("cvt.rna.tf32.f32 %0, %1;" : "=r"(r) : "f"(x));
    return __uint_as_float(r);
}
__device__ __forceinline__ uint32_t swz(uint32_t off) {
    return off ^ ((off >> 3) & 0x70);
}
__device__ __forceinline__ void mma_tf32(
    float& d0, float& d1, float& d2, float& d3,
    uint32_t a0, uint32_t a1, uint32_t a2, uint32_t a3,
    uint32_t b0, uint32_t b1)
{
    asm volatile(
        "mma.sync.aligned.m16n8k8.row.col.f32.tf32.tf32.f32 "
        "{%0,%1,%2,%3}, {%4,%5,%6,%7}, {%8,%9}, {%0,%1,%2,%3};\n"
        : "+f"(d0), "+f"(d1), "+f"(d2), "+f"(d3)
        : "r"(a0), "r"(a1), "r"(a2), "r"(a3), "r"(b0), "r"(b1));
}
__device__ __forceinline__ void mma_f16(
    float& d0, float& d1, float& d2, float& d3,
    uint32_t a0, uint32_t a1, uint32_t a2, uint32_t a3,
    uint32_t b0, uint32_t b1)
{
    asm volatile(
        "mma.sync.aligned.m16n8k16.row.col.f32.f16.f16.f32 "
        "{%0,%1,%2,%3}, {%4,%5,%6,%7}, {%8,%9}, {%0,%1,%2,%3};\n"
        : "+f"(d0), "+f"(d1), "+f"(d2), "+f"(d3)
        : "r"(a0), "r"(a1), "r"(a2), "r"(a3), "r"(b0), "r"(b1));
}
__device__ __forceinline__ void ldmx4(
    uint32_t& r0, uint32_t& r1, uint32_t& r2, uint32_t& r3, uint32_t addr)
{
    asm volatile("ldmatrix.sync.aligned.m8n8.x4.shared.b16 {%0,%1,%2,%3}, [%4];"
                 : "=r"(r0), "=r"(r1), "=r"(r2), "=r"(r3) : "r"(addr) : "memory");
}
__device__ __forceinline__ void cpasync16(uint32_t saddr, const void* gaddr) {
    asm volatile("cp.async.cg.shared.global [%0], [%1], 16;" :: "r"(saddr), "l"(gaddr));
}
#define CP_COMMIT() asm volatile("cp.async.commit_group;" ::: "memory")
#define CP_WAIT(n)  asm volatile("cp.async.wait_group %0;" :: "n"(n) : "memory")

// ---------------- LayerNorm (emits fp16) ----------------
__global__ __launch_bounds__(256) void ln_kernel(
    const float* __restrict__ x, const float* __restrict__ g,
    const float* __restrict__ b, __half* __restrict__ y)
{
    int row = blockIdx.x;
    int tid = threadIdx.x;
    float4 v = reinterpret_cast<const float4*>(x + (size_t)row * DD)[tid];
    float s  = v.x + v.y + v.z + v.w;
    float ss = v.x * v.x + v.y * v.y + v.z * v.z + v.w * v.w;
    #pragma unroll
    for (int o = 16; o > 0; o >>= 1) {
        s  += __shfl_xor_sync(0xffffffffu, s, o);
        ss += __shfl_xor_sync(0xffffffffu, ss, o);
    }
    __shared__ float sb[8], ssb[8], stats[2];
    int wid = tid >> 5, lane = tid & 31;
    if (lane == 0) { sb[wid] = s; ssb[wid] = ss; }
    __syncthreads();
    if (tid == 0) {
        float a = 0.f, c = 0.f;
        #pragma unroll
        for (int i = 0; i < 8; i++) { a += sb[i]; c += ssb[i]; }
        float mean = a * (1.0f / DD);
        float var  = c * (1.0f / DD) - mean * mean;
        stats[0] = mean;
        stats[1] = rsqrtf(var + 1e-6f);
    }
    __syncthreads();
    float mean = stats[0], rstd = stats[1];
    float4 gg = reinterpret_cast<const float4*>(g)[tid];
    float4 bb = reinterpret_cast<const float4*>(b)[tid];
    union { __half2 h[2]; uint2 u; } pk;
    pk.h[0] = __floats2half2_rn((v.x - mean) * rstd * gg.x + bb.x,
                                (v.y - mean) * rstd * gg.y + bb.y);
    pk.h[1] = __floats2half2_rn((v.z - mean) * rstd * gg.z + bb.z,
                                (v.w - mean) * rstd * gg.w + bb.w);
    reinterpret_cast<uint2*>(y + (size_t)row * DD)[tid] = pk.u;
}

// ---------------- ALL weight transposes in one launch (emit fp16) ----------------
__global__ __launch_bounds__(256) void transpose_all(
    const float* __restrict__ Wq, const float* __restrict__ Wk,
    const float* __restrict__ Wv, const float* __restrict__ Wo,
    const float* __restrict__ W1, const float* __restrict__ W2,
    __half* __restrict__ wqkvT, __half* __restrict__ woT,
    __half* __restrict__ w1T, __half* __restrict__ w2T)
{
    __shared__ float t[32][33];
    const int b = blockIdx.x;
    const float* ip; __half* op;
    int R, C, bx, by;
    if (b < 3072) {
        const int w = b >> 10;
        const int r = b & 1023;
        const int head = r >> 6;
        const int rr = r & 63;
        bx = (rr & 1) * 32;
        by = (rr >> 1) * 32;
        ip = (w == 0 ? Wq : (w == 1 ? Wk : Wv)) + (size_t)head * DD * HSZ;
        op = wqkvT + (size_t)w * DD * DD + (size_t)head * HSZ * DD;
        R = DD; C = HSZ;
    } else if (b < 4096) {
        const int r = b - 3072;
        bx = (r & 31) * 32; by = (r >> 5) * 32;
        ip = Wo; op = woT; R = DD; C = DD;
    } else if (b < 8192) {
        const int r = b - 4096;
        bx = (r & 127) * 32; by = (r >> 7) * 32;
        ip = W1; op = w1T; R = DD; C = DFF;
    } else {
        const int r = b - 8192;
        bx = (r & 31) * 32; by = (r >> 5) * 32;
        ip = W2; op = w2T; R = DFF; C = DD;
    }
    const int x = threadIdx.x, y = threadIdx.y;
    #pragma unroll
    for (int j = 0; j < 32; j += 8)
        t[y + j][x] = ip[(size_t)(by + y + j) * C + bx + x];
    __syncthreads();
    #pragma unroll
    for (int j = 0; j < 32; j += 8)
        op[(size_t)(bx + y + j) * R + by + x] = __float2half_rn(t[x][y + j]);
}

// ---------------- fp16 mma.sync GEMM, cp.async 3-stage + ldmatrix ----------------
// C[M,N] = epi( A[M,K] row-major fp16  x  Bt[N,K] K-major fp16 ^T )
// CTA 128x128, BK=64 halfs (128B/row), 8 warps (2x4), warp tile 64x32.
// stage: A 16KB + B 16KB. 3 stages = 96KB.
// EPI: 0 = tf32-round -> fp32 C, 1 = +bias+resid -> fp32 C, 2 = relu(+bias) -> fp16 C
#define TG_STAGE 32768
#define TG_SMEM  (3 * TG_STAGE)

template <int EPI>
__global__ __launch_bounds__(256, 1) void tg2(
    int M, int N, int K,
    const __half* __restrict__ A, const __half* __restrict__ Bt,
    const float* __restrict__ bias, const float* __restrict__ resid,
    void* __restrict__ Cv)
{
    extern __shared__ float dynsm[];
    const int tid  = threadIdx.x;
    const int warp = tid >> 5, lane = tid & 31;
    const int wm = warp & 1, wn = warp >> 1;
    const int g = lane >> 2, tg = lane & 3;
    const int brow = blockIdx.y, bcol = blockIdx.x;

    const uint32_t sbase = smem_u32(dynsm);
    const int r0 = tid >> 3;      // 0..31
    const int ck = tid & 7;       // 16B chunk (8 halfs)
    const __half* Ab = A  + (size_t)(brow * 128) * K + ck * 8;
    const __half* Bb = Bt + (size_t)(bcol * 128) * K + ck * 8;
    const int KT = K >> 6;

    const int aRow = (lane & 7) + ((lane >> 3) & 1) * 8;
    const int aChk = (lane >> 4);
    const int bRow = (lane & 7) + (lane >> 4) * 8;
    const int bChk = (lane >> 3) & 1;

    float acc[4][4][4];
    #pragma unroll
    for (int mt = 0; mt < 4; mt++)
        #pragma unroll
        for (int nt = 0; nt < 4; nt++)
            #pragma unroll
            for (int i = 0; i < 4; i++) acc[mt][nt][i] = 0.f;

    auto load_stage = [&](int kt, int s) {
        const uint32_t sA = sbase + s * TG_STAGE;
        const uint32_t sB = sA + 16384;
        const int k0 = kt * 64;
        #pragma unroll
        for (int j = 0; j < 4; ++j) {
            const int r = j * 32 + r0;
            const uint32_t off = swz((uint32_t)(r * 128 + ck * 16));
            cpasync16(sA + off, Ab + (size_t)r * K + k0);
            cpasync16(sB + off, Bb + (size_t)r * K + k0);
        }
        CP_COMMIT();
    };

    load_stage(0, 0);
    if (KT > 1) load_stage(1, 1);

    for (int kt = 0; kt < KT; ++kt) {
        if (kt + 1 < KT) CP_WAIT(1); else CP_WAIT(0);
        __syncthreads();
        if (kt + 2 < KT) load_stage(kt + 2, (kt + 2) % 3);

        const uint32_t sA = sbase + (kt % 3) * TG_STAGE;
        const uint32_t sB = sA + 16384;

        #pragma unroll
        for (int ks = 0; ks < 4; ++ks) {      // 4 k16-steps per 64-k stage
            uint32_t af[4][4];
            #pragma unroll
            for (int mt = 0; mt < 4; ++mt) {
                const int row = wm * 64 + mt * 16 + aRow;
                const uint32_t ad = sA + swz((uint32_t)(row * 128 + ks * 32 + aChk * 16));
                ldmx4(af[mt][0], af[mt][1], af[mt][2], af[mt][3], ad);
            }
            uint32_t bf[4][2];
            #pragma unroll
            for (int np = 0; np < 2; ++np) {
                const int nrow = wn * 32 + np * 16 + bRow;
                const uint32_t bd = sB + swz((uint32_t)(nrow * 128 + ks * 32 + bChk * 16));
                uint32_t t0, t1, t2, t3;
                ldmx4(t0, t1, t2, t3, bd);
                bf[np * 2][0] = t0;     bf[np * 2][1] = t1;
                bf[np * 2 + 1][0] = t2; bf[np * 2 + 1][1] = t3;
            }
            #pragma unroll
            for (int mt = 0; mt < 4; ++mt)
                #pragma unroll
                for (int nt = 0; nt < 4; ++nt)
                    mma_f16(acc[mt][nt][0], acc[mt][nt][1],
                            acc[mt][nt][2], acc[mt][nt][3],
                            af[mt][0], af[mt][1], af[mt][2], af[mt][3],
                            bf[nt][0], bf[nt][1]);
        }
    }

    // ---------------- epilogue ----------------
    #pragma unroll
    for (int mt = 0; mt < 4; mt++) {
        const int r0g = brow * 128 + wm * 64 + mt * 16 + g;
        const int r1g = r0g + 8;
        #pragma unroll
        for (int nt = 0; nt < 4; nt++) {
            const int c = bcol * 128 + wn * 32 + nt * 8 + tg * 2;
            float2 o0 = make_float2(acc[mt][nt][0], acc[mt][nt][1]);
            float2 o1 = make_float2(acc[mt][nt][2], acc[mt][nt][3]);
            if constexpr (EPI >= 1) {
                float2 bv = *reinterpret_cast<const float2*>(bias + c);
                o0.x += bv.x; o0.y += bv.y;
                o1.x += bv.x; o1.y += bv.y;
            }
            if constexpr (EPI == 1) {
                const float* C = (const float*)Cv;   // silence unused warn path
                (void)C;
                float2 rv0 = *reinterpret_cast<const float2*>(resid + (size_t)r0g * N + c);
                float2 rv1 = *reinterpret_cast<const float2*>(resid + (size_t)r1g * N + c);
                o0.x += rv0.x; o0.y += rv0.y;
                o1.x += rv1.x; o1.y += rv1.y;
            }
            if constexpr (EPI == 2) {
                // relu + fp16 store (feeds FFN2 as fp16 A operand)
                __half* C = (__half*)Cv;
                __half2 h0 = __floats2half2_rn(fmaxf(o0.x, 0.f), fmaxf(o0.y, 0.f));
                __half2 h1 = __floats2half2_rn(fmaxf(o1.x, 0.f), fmaxf(o1.y, 0.f));
                *reinterpret_cast<__half2*>(C + (size_t)r0g * N + c) = h0;
                *reinterpret_cast<__half2*>(C + (size_t)r1g * N + c) = h1;
            } else {
                float* C = (float*)Cv;
                if constexpr (EPI == 0) {   // feeds flash (tf32 path)
                    o0.x = f2tf32(o0.x); o0.y = f2tf32(o0.y);
                    o1.x = f2tf32(o1.x); o1.y = f2tf32(o1.y);
                }
                *reinterpret_cast<float2*>(C + (size_t)r0g * N + c) = o0;
                *reinterpret_cast<float2*>(C + (size_t)r1g * N + c) = o1;
            }
        }
    }
}

// ---------------- fast exp2 (fma pipe) ----------------
__device__ __forceinline__ float fexp2(float x) {
    x = fmaxf(x, -120.f);
    float k  = __fadd_rn(x, 12582912.f);
    int   sc = __float_as_int(k) << 23;
    float f  = __fsub_rn(x, __fsub_rn(k, 12582912.f));
    float p  = 0.0013333558f;
    p = fmaf(p, f, 0.0096181291f);
    p = fmaf(p, f, 0.0555041087f);
    p = fmaf(p, f, 0.2402265070f);
    p = fmaf(p, f, 0.6931471806f);
    p = fmaf(p, f, 1.0f);
    return __int_as_float(__float_as_int(p) + sc);
}

// ---------------- flash attention v5 (split-K, tf32) — att out fp16 ----------------
#define FS   68
#define VS_S 72
#define FA_SMEM ((64*FS + 64*FS + 64*VS_S) * 4)

__global__ __launch_bounds__(128, 4) void flash_tc(
    const float* __restrict__ qkv, __half* __restrict__ out,
    float* __restrict__ pO, float* __restrict__ pml)
{
    extern __shared__ float sm[];
    float* Qs = sm;
    float* Ks = Qs + 64 * FS;
    float* Vs = Ks + 64 * FS;

    const int tid  = threadIdx.x;
    const int warp = tid >> 5;
    const int lane = tid & 31;
    const int g    = lane >> 2;
    const int tg   = lane & 3;
    const int bx   = blockIdx.x;
    const int h    = blockIdx.y;
    int qb, seg;
    if (bx < 32) { qb = 16 + (bx >> 1); seg = bx & 1; }
    else         { qb = bx - 32;        seg = 0; }
    const int q0   = qb * 64;
    const int w16  = warp * 16;
    const int kt0  = seg * 16;
    const int kt1  = min(qb + 1, kt0 + 16);
    const bool full = (kt0 == 0) && (kt1 == qb + 1);

    const int aRow = (lane & 7) + ((lane >> 3) & 1) * 8;
    const int aChk = lane >> 4;
    const int bRow = (lane & 7) + (lane >> 4) * 8;
    const int bChk = (lane >> 3) & 1;

    const float* qp = qkv + h * HSZ;
    const float* kp = qkv + DD + h * HSZ;
    const float* vp = qkv + 2 * DD + h * HSZ;

    {
        const uint32_t qsb = smem_u32(Qs);
        #pragma unroll
        for (int j = 0; j < 8; ++j) {
            int idx = j * 128 + tid;
            int r = idx >> 4, c4 = idx & 15;
            cpasync16(qsb + (uint32_t)((r * FS + c4 * 4) * 4),
                      qp + (size_t)(q0 + r) * (3 * DD) + c4 * 4);
        }
        CP_COMMIT();
    }

    float O[8][4];
    #pragma unroll
    for (int nt = 0; nt < 8; nt++)
        #pragma unroll
        for (int i = 0; i < 4; i++) O[nt][i] = 0.f;
    float m0 = -1e30f, m1 = -1e30f, l0 = 0.f, l1 = 0.f;

    const int row0 = q0 + w16 + g;
    const int row1 = row0 + 8;
    const float SC = 0.18033688011112042f;   // (1/8) * log2(e)

    const uint32_t qbase = smem_u32(Qs) + (uint32_t)((w16 + aRow) * FS * 4 + aChk * 16);
    const uint32_t kbase = smem_u32(Ks) + (uint32_t)(bRow * FS * 4 + bChk * 16);
    const uint32_t ksb = smem_u32(Ks);
    const uint32_t vsb = smem_u32(Vs);

    const int srcL  = (g << 2) + (tg >> 1);
    const int srcH  = srcL + 2;
    const bool odd  = (tg & 1) != 0;

    for (int kt = kt0; kt < kt1; ++kt) {
        __syncthreads();
        {
            #pragma unroll
            for (int j = 0; j < 8; ++j) {
                int idx = j * 128 + tid;
                int r = idx >> 4, c4 = idx & 15;
                size_t gi = (size_t)(kt * 64 + r) * (3 * DD) + c4 * 4;
                cpasync16(ksb + (uint32_t)((r * FS + c4 * 4) * 4), kp + gi);
                cpasync16(vsb + (uint32_t)((r * VS_S + c4 * 4) * 4), vp + gi);
            }
            CP_COMMIT();
        }
        CP_WAIT(0);
        __syncthreads();

        float s[8][4];
        #pragma unroll
        for (int nt = 0; nt < 8; nt++)
            #pragma unroll
            for (int i = 0; i < 4; i++) s[nt][i] = 0.f;

        #pragma unroll
        for (int kk = 0; kk < 8; ++kk) {
            uint32_t a0, a1, a2, a3;
            ldmx4(a0, a1, a2, a3, qbase + kk * 32);
            uint32_t bf[8][2];
            #pragma unroll
            for (int n16 = 0; n16 < 4; ++n16) {
                uint32_t t0, t1, t2, t3;
                ldmx4(t0, t1, t2, t3, kbase + (uint32_t)(n16 * 16 * FS * 4) + kk * 32);
                bf[n16 * 2][0] = t0;     bf[n16 * 2][1] = t1;
                bf[n16 * 2 + 1][0] = t2; bf[n16 * 2 + 1][1] = t3;
            }
            #pragma unroll
            for (int nt = 0; nt < 8; ++nt)
                mma_tf32(s[nt][0], s[nt][1], s[nt][2], s[nt][3],
                         a0, a1, a2, a3, bf[nt][0], bf[nt][1]);
        }

        float mb0 = -1e30f, mb1 = -1e30f;
        #pragma unroll
        for (int nt = 0; nt < 8; ++nt) {
            int c0 = kt * 64 + nt * 8 + 2 * tg;
            float z0 = (c0     > row0) ? -1e30f : s[nt][0] * SC;
            float z1 = (c0 + 1 > row0) ? -1e30f : s[nt][1] * SC;
            float z2 = (c0     > row1) ? -1e30f : s[nt][2] * SC;
            float z3 = (c0 + 1 > row1) ? -1e30f : s[nt][3] * SC;
            s[nt][0] = z0; s[nt][1] = z1; s[nt][2] = z2; s[nt][3] = z3;
            mb0 = fmaxf(mb0, fmaxf(z0, z1));
            mb1 = fmaxf(mb1, fmaxf(z2, z3));
        }
        mb0 = fmaxf(mb0, __shfl_xor_sync(0xffffffffu, mb0, 1));
        mb0 = fmaxf(mb0, __shfl_xor_sync(0xffffffffu, mb0, 2));
        mb1 = fmaxf(mb1, __shfl_xor_sync(0xffffffffu, mb1, 1));
        mb1 = fmaxf(mb1, __shfl_xor_sync(0xffffffffu, mb1, 2));

        float mn0 = fmaxf(m0, mb0), mn1 = fmaxf(m1, mb1);
        float al0 = fexp2(m0 - mn0), al1 = fexp2(m1 - mn1);
        m0 = mn0; m1 = mn1;

        float rs0 = 0.f, rs1 = 0.f;
        #pragma unroll
        for (int nt = 0; nt < 8; ++nt) {
            float p0 = fexp2(s[nt][0] - mn0);
            float p1 = fexp2(s[nt][1] - mn0);
            float p2 = fexp2(s[nt][2] - mn1);
            float p3 = fexp2(s[nt][3] - mn1);
            rs0 += p0 + p1; rs1 += p2 + p3;
            s[nt][0] = f2tf32(p0);
            s[nt][1] = f2tf32(p1);
            s[nt][2] = f2tf32(p2);
            s[nt][3] = f2tf32(p3);
        }
        rs0 += __shfl_xor_sync(0xffffffffu, rs0, 1);
        rs0 += __shfl_xor_sync(0xffffffffu, rs0, 2);
        rs1 += __shfl_xor_sync(0xffffffffu, rs1, 1);
        rs1 += __shfl_xor_sync(0xffffffffu, rs1, 2);
        l0 = l0 * al0 + rs0;
        l1 = l1 * al1 + rs1;

        #pragma unroll
        for (int nt = 0; nt < 8; ++nt) {
            O[nt][0] *= al0; O[nt][1] *= al0;
            O[nt][2] *= al1; O[nt][3] *= al1;
        }

        #pragma unroll
        for (int kk = 0; kk < 8; ++kk) {
            float v00 = __shfl_sync(0xffffffffu, s[kk][0], srcL);
            float v01 = __shfl_sync(0xffffffffu, s[kk][1], srcL);
            float v10 = __shfl_sync(0xffffffffu, s[kk][2], srcL);
            float v11 = __shfl_sync(0xffffffffu, s[kk][3], srcL);
            float v20 = __shfl_sync(0xffffffffu, s[kk][0], srcH);
            float v21 = __shfl_sync(0xffffffffu, s[kk][1], srcH);
            float v30 = __shfl_sync(0xffffffffu, s[kk][2], srcH);
            float v31 = __shfl_sync(0xffffffffu, s[kk][3], srcH);
            uint32_t a0 = __float_as_uint(odd ? v01 : v00);
            uint32_t a1 = __float_as_uint(odd ? v11 : v10);
            uint32_t a2 = __float_as_uint(odd ? v21 : v20);
            uint32_t a3 = __float_as_uint(odd ? v31 : v30);
            #pragma unroll
            for (int nt = 0; nt < 8; ++nt) {
                uint32_t b0 = __float_as_uint(Vs[(kk * 8 + tg) * VS_S + nt * 8 + g]);
                uint32_t b1 = __float_as_uint(Vs[(kk * 8 + tg + 4) * VS_S + nt * 8 + g]);
                mma_tf32(O[nt][0], O[nt][1], O[nt][2], O[nt][3],
                         a0, a1, a2, a3, b0, b1);
            }
        }
    }

    if (full) {
        float inv0 = 1.0f / l0, inv1 = 1.0f / l1;
        #pragma unroll
        for (int nt = 0; nt < 8; ++nt) {
            int c = h * HSZ + nt * 8 + 2 * tg;
            __half2 o0 = __floats2half2_rn(O[nt][0] * inv0, O[nt][1] * inv0);
            __half2 o1 = __floats2half2_rn(O[nt][2] * inv1, O[nt][3] * inv1);
            *reinterpret_cast<__half2*>(out + (size_t)row0 * DD + c) = o0;
            *reinterpret_cast<__half2*>(out + (size_t)row1 * DD + c) = o1;
        }
    } else {
        const int p = (h * 16 + (qb - 16)) * 2 + seg;
        float* pb = pO + (size_t)p * 4096;
        const int lr0 = w16 + g, lr1 = lr0 + 8;
        #pragma unroll
        for (int nt = 0; nt < 8; ++nt) {
            int c = nt * 8 + 2 * tg;
            *reinterpret_cast<float2*>(pb + lr0 * 64 + c) = make_float2(O[nt][0], O[nt][1]);
            *reinterpret_cast<float2*>(pb + lr1 * 64 + c) = make_float2(O[nt][2], O[nt][3]);
        }
        if (tg == 0) {
            float* mlb = pml + (size_t)p * 128;
            mlb[lr0 * 2]     = m0;
            mlb[lr0 * 2 + 1] = l0;
            mlb[lr1 * 2]     = m1;
            mlb[lr1 * 2 + 1] = l1;
        }
    }
}

// ---------------- split-K merge (writes fp16 att) ----------------
__global__ __launch_bounds__(128) void flash_merge(
    const float* __restrict__ pO, const float* __restrict__ pml,
    __half* __restrict__ out)
{
    __shared__ float w0s[64], w1s[64];
    const int qb16 = blockIdx.x;
    const int h    = blockIdx.y;
    const int tid  = threadIdx.x;
    const int p0 = (h * 16 + qb16) * 2;
    const int p1 = p0 + 1;

    if (tid < 64) {
        float m0 = pml[(size_t)p0 * 128 + tid * 2];
        float l0 = pml[(size_t)p0 * 128 + tid * 2 + 1];
        float m1 = pml[(size_t)p1 * 128 + tid * 2];
        float l1 = pml[(size_t)p1 * 128 + tid * 2 + 1];
        float M  = fmaxf(m0, m1);
        float w0 = fexp2(m0 - M), w1 = fexp2(m1 - M);
        float inv = 1.0f / (w0 * l0 + w1 * l1);
        w0s[tid] = w0 * inv;
        w1s[tid] = w1 * inv;
    }
    __syncthreads();

    const float* b0 = pO + (size_t)p0 * 4096;
    const float* b1 = pO + (size_t)p1 * 4096;
    const int q0 = (16 + qb16) * 64;
    #pragma unroll
    for (int i = 0; i < 8; ++i) {
        int idx = (i * 128 + tid) * 4;
        int r = idx >> 6, c = idx & 63;
        float4 v0 = *reinterpret_cast<const float4*>(b0 + r * 64 + c);
        float4 v1 = *reinterpret_cast<const float4*>(b1 + r * 64 + c);
        float w0 = w0s[r], w1 = w1s[r];
        union { __half2 h[2]; uint2 u; } pk;
        pk.h[0] = __floats2half2_rn(w0 * v0.x + w1 * v1.x, w0 * v0.y + w1 * v1.y);
        pk.h[1] = __floats2half2_rn(w0 * v0.z + w1 * v1.z, w0 * v0.w + w1 * v1.w);
        *reinterpret_cast<uint2*>(out + (size_t)(q0 + r) * DD + h * HSZ + c) = pk.u;
    }
}

// ---------------- launch ----------------
extern "C" void kernel_launch(void* const* d_in, const int* in_sizes, int n_in,
                              void* d_out, int out_size)
{
    const float* x    = (const float*)d_in[0];
    const float* Wq   = (const float*)d_in[1];
    const float* Wk   = (const float*)d_in[2];
    const float* Wv   = (const float*)d_in[3];
    const float* Wo   = (const float*)d_in[4];
    const float* bo   = (const float*)d_in[5];
    const float* W1   = (const float*)d_in[6];
    const float* b1   = (const float*)d_in[7];
    const float* W2   = (const float*)d_in[8];
    const float* b2   = (const float*)d_in[9];
    const float* ln1s = (const float*)d_in[10];
    const float* ln1b = (const float*)d_in[11];
    const float* ln2s = (const float*)d_in[12];
    const float* ln2b = (const float*)d_in[13];
    float* out = (float*)d_out;

    __half *h, *wqkvT, *woT, *w1T, *w2T, *att, *ff;
    float *qkv, *x2, *pO, *pml;
    cudaGetSymbolAddress((void**)&h,     g_h);
    cudaGetSymbolAddress((void**)&wqkvT, g_wqkvT);
    cudaGetSymbolAddress((void**)&woT,   g_WoT);
    cudaGetSymbolAddress((void**)&w1T,   g_W1T);
    cudaGetSymbolAddress((void**)&w2T,   g_W2T);
    cudaGetSymbolAddress((void**)&qkv,   g_qkv);
    cudaGetSymbolAddress((void**)&att,   g_att);
    cudaGetSymbolAddress((void**)&x2,    g_x2);
    cudaGetSymbolAddress((void**)&ff,    g_ff);
    cudaGetSymbolAddress((void**)&pO,    g_pO);
    cudaGetSymbolAddress((void**)&pml,   g_pml);

    cudaFuncSetAttribute(flash_tc, cudaFuncAttributeMaxDynamicSharedMemorySize, FA_SMEM);
    cudaFuncSetAttribute(tg2<0>, cudaFuncAttributeMaxDynamicSharedMemorySize, TG_SMEM);
    cudaFuncSetAttribute(tg2<1>, cudaFuncAttributeMaxDynamicSharedMemorySize, TG_SMEM);
    cudaFuncSetAttribute(tg2<2>, cudaFuncAttributeMaxDynamicSharedMemorySize, TG_SMEM);

    // 1. LN1 -> fp16
    ln_kernel<<<TT, 256>>>(x, ln1s, ln1b, h);
    // 2. weight transposes -> fp16 K-major
    transpose_all<<<12288, dim3(32, 8)>>>(Wq, Wk, Wv, Wo, W1, W2,
                                          wqkvT, woT, w1T, w2T);
    // 3. QKV GEMM (fp16 in, tf32-rounded fp32 out)
    tg2<0><<<dim3(3 * DD / 128, TT / 128), 256, TG_SMEM>>>(
        TT, 3 * DD, DD, h, wqkvT, nullptr, nullptr, qkv);
    // 4. flash attention split-K (att -> fp16)
    flash_tc<<<dim3(48, HH), 128, FA_SMEM>>>(qkv, att, pO, pml);
    flash_merge<<<dim3(16, HH), 128>>>(pO, pml, att);
    // 5. output proj + bias + residual (fp32 out)
    tg2<1><<<dim3(DD / 128, TT / 128), 256, TG_SMEM>>>(
        TT, DD, DD, att, woT, bo, x, x2);
    // 6. LN2 -> fp16
    ln_kernel<<<TT, 256>>>(x2, ln2s, ln2b, h);
    // 7. FFN1 (relu, fp16 out)
    tg2<2><<<dim3(DFF / 128, TT / 128), 256, TG_SMEM>>>(
        TT, DFF, DD, h, w1T, b1, nullptr, ff);
    // 8. FFN2 (fp32 out)
    tg2<1><<<dim3(DD / 128, TT / 128), 256, TG_SMEM>>>(
        TT, DD, DFF, ff, w2T, b2, x2, out);
}

// round 12
// speedup vs baseline: 2.4539x; 1.1654x over previous
#include <cuda_runtime.h>
#include <cuda_fp16.h>
#include <cstdint>

#define TT 2048
#define DD 1024
#define HH 16
#define HSZ 64
#define DFF 4096

// ---------------- scratch (no allocs allowed) ----------------
__device__ __half g_h[TT * DD];            // LN output (fp16)
__device__ __half g_wqkvT[3 * DD * DD];    // QKV weights, [3D][D] K-major (fp16)
__device__ __half g_WoT[DD * DD];          // Wo^T (fp16)
__device__ __half g_W1T[DD * DFF];         // W1^T (fp16)
__device__ __half g_W2T[DFF * DD];         // W2^T (fp16)
__device__ __half g_qkv[TT * 3 * DD];      // QKV activations (fp16)
__device__ __half g_att[TT * DD];          // attention output (fp16)
__device__ float  g_x2[TT * DD];           // residual after attention (fp32)
__device__ __half g_ff[TT * DFF];          // FFN hidden (fp16)
__device__ float  g_pO[16 * 16 * 2 * 64 * 64];   // split-K partials
__device__ float  g_pml[16 * 16 * 2 * 64 * 2];

// ---------------- helpers ----------------
__device__ __forceinline__ uint32_t smem_u32(const void* p) {
    return (uint32_t)__cvta_generic_to_shared(p);
}
__device__ __forceinline__ uint32_t swz(uint32_t off) {
    return off ^ ((off >> 3) & 0x70);
}
__device__ __forceinline__ void mma_f16(
    float& d0, float& d1, float& d2, float& d3,
    uint32_t a0, uint32_t a1, uint32_t a2, uint32_t a3,
    uint32_t b0, uint32_t b1)
{
    asm volatile(
        "mma.sync.aligned.m16n8k16.row.col.f32.f16.f16.f32 "
        "{%0,%1,%2,%3}, {%4,%5,%6,%7}, {%8,%9}, {%0,%1,%2,%3};\n"
        : "+f"(d0), "+f"(d1), "+f"(d2), "+f"(d3)
        : "r"(a0), "r"(a1), "r"(a2), "r"(a3), "r"(b0), "r"(b1));
}
__device__ __forceinline__ void ldmx4(
    uint32_t& r0, uint32_t& r1, uint32_t& r2, uint32_t& r3, uint32_t addr)
{
    asm volatile("ldmatrix.sync.aligned.m8n8.x4.shared.b16 {%0,%1,%2,%3}, [%4];"
                 : "=r"(r0), "=r"(r1), "=r"(r2), "=r"(r3) : "r"(addr) : "memory");
}
__device__ __forceinline__ void ldmx4t(
    uint32_t& r0, uint32_t& r1, uint32_t& r2, uint32_t& r3, uint32_t addr)
{
    asm volatile("ldmatrix.sync.aligned.m8n8.x4.trans.shared.b16 {%0,%1,%2,%3}, [%4];"
                 : "=r"(r0), "=r"(r1), "=r"(r2), "=r"(r3) : "r"(addr) : "memory");
}
__device__ __forceinline__ void cpasync16(uint32_t saddr, const void* gaddr) {
    asm volatile("cp.async.cg.shared.global [%0], [%1], 16;" :: "r"(saddr), "l"(gaddr));
}
__device__ __forceinline__ uint32_t packh2(float lo, float hi) {
    __half2 h = __floats2half2_rn(lo, hi);
    return *reinterpret_cast<uint32_t*>(&h);
}
#define CP_COMMIT() asm volatile("cp.async.commit_group;" ::: "memory")
#define CP_WAIT(n)  asm volatile("cp.async.wait_group %0;" :: "n"(n) : "memory")

// ---------------- LayerNorm (emits fp16) ----------------
__global__ __launch_bounds__(256) void ln_kernel(
    const float* __restrict__ x, const float* __restrict__ g,
    const float* __restrict__ b, __half* __restrict__ y)
{
    int row = blockIdx.x;
    int tid = threadIdx.x;
    float4 v = reinterpret_cast<const float4*>(x + (size_t)row * DD)[tid];
    float s  = v.x + v.y + v.z + v.w;
    float ss = v.x * v.x + v.y * v.y + v.z * v.z + v.w * v.w;
    #pragma unroll
    for (int o = 16; o > 0; o >>= 1) {
        s  += __shfl_xor_sync(0xffffffffu, s, o);
        ss += __shfl_xor_sync(0xffffffffu, ss, o);
    }
    __shared__ float sb[8], ssb[8], stats[2];
    int wid = tid >> 5, lane = tid & 31;
    if (lane == 0) { sb[wid] = s; ssb[wid] = ss; }
    __syncthreads();
    if (tid == 0) {
        float a = 0.f, c = 0.f;
        #pragma unroll
        for (int i = 0; i < 8; i++) { a += sb[i]; c += ssb[i]; }
        float mean = a * (1.0f / DD);
        float var  = c * (1.0f / DD) - mean * mean;
        stats[0] = mean;
        stats[1] = rsqrtf(var + 1e-6f);
    }
    __syncthreads();
    float mean = stats[0], rstd = stats[1];
    float4 gg = reinterpret_cast<const float4*>(g)[tid];
    float4 bb = reinterpret_cast<const float4*>(b)[tid];
    union { __half2 h[2]; uint2 u; } pk;
    pk.h[0] = __floats2half2_rn((v.x - mean) * rstd * gg.x + bb.x,
                                (v.y - mean) * rstd * gg.y + bb.y);
    pk.h[1] = __floats2half2_rn((v.z - mean) * rstd * gg.z + bb.z,
                                (v.w - mean) * rstd * gg.w + bb.w);
    reinterpret_cast<uint2*>(y + (size_t)row * DD)[tid] = pk.u;
}

// ---------------- ALL weight transposes in one launch (emit fp16) ----------------
__global__ __launch_bounds__(256) void transpose_all(
    const float* __restrict__ Wq, const float* __restrict__ Wk,
    const float* __restrict__ Wv, const float* __restrict__ Wo,
    const float* __restrict__ W1, const float* __restrict__ W2,
    __half* __restrict__ wqkvT, __half* __restrict__ woT,
    __half* __restrict__ w1T, __half* __restrict__ w2T)
{
    __shared__ float t[32][33];
    const int b = blockIdx.x;
    const float* ip; __half* op;
    int R, C, bx, by;
    if (b < 3072) {
        const int w = b >> 10;
        const int r = b & 1023;
        const int head = r >> 6;
        const int rr = r & 63;
        bx = (rr & 1) * 32;
        by = (rr >> 1) * 32;
        ip = (w == 0 ? Wq : (w == 1 ? Wk : Wv)) + (size_t)head * DD * HSZ;
        op = wqkvT + (size_t)w * DD * DD + (size_t)head * HSZ * DD;
        R = DD; C = HSZ;
    } else if (b < 4096) {
        const int r = b - 3072;
        bx = (r & 31) * 32; by = (r >> 5) * 32;
        ip = Wo; op = woT; R = DD; C = DD;
    } else if (b < 8192) {
        const int r = b - 4096;
        bx = (r & 127) * 32; by = (r >> 7) * 32;
        ip = W1; op = w1T; R = DD; C = DFF;
    } else {
        const int r = b - 8192;
        bx = (r & 31) * 32; by = (r >> 5) * 32;
        ip = W2; op = w2T; R = DFF; C = DD;
    }
    const int x = threadIdx.x, y = threadIdx.y;
    #pragma unroll
    for (int j = 0; j < 32; j += 8)
        t[y + j][x] = ip[(size_t)(by + y + j) * C + bx + x];
    __syncthreads();
    #pragma unroll
    for (int j = 0; j < 32; j += 8)
        op[(size_t)(bx + y + j) * R + by + x] = __float2half_rn(t[x][y + j]);
}

// ---------------- fp16 mma.sync GEMM, cp.async 3-stage + ldmatrix ----------------
// EPI: 0 = fp16 C (feeds flash), 1 = +bias+resid -> fp32 C, 2 = relu(+bias) -> fp16 C
#define TG_STAGE 32768
#define TG_SMEM  (3 * TG_STAGE)

template <int EPI>
__global__ __launch_bounds__(256, 1) void tg2(
    int M, int N, int K,
    const __half* __restrict__ A, const __half* __restrict__ Bt,
    const float* __restrict__ bias, const float* __restrict__ resid,
    void* __restrict__ Cv)
{
    extern __shared__ float dynsm[];
    const int tid  = threadIdx.x;
    const int warp = tid >> 5, lane = tid & 31;
    const int wm = warp & 1, wn = warp >> 1;
    const int g = lane >> 2, tg = lane & 3;
    const int brow = blockIdx.y, bcol = blockIdx.x;

    const uint32_t sbase = smem_u32(dynsm);
    const int r0 = tid >> 3;
    const int ck = tid & 7;
    const __half* Ab = A  + (size_t)(brow * 128) * K + ck * 8;
    const __half* Bb = Bt + (size_t)(bcol * 128) * K + ck * 8;
    const int KT = K >> 6;

    const int aRow = (lane & 7) + ((lane >> 3) & 1) * 8;
    const int aChk = (lane >> 4);
    const int bRow = (lane & 7) + (lane >> 4) * 8;
    const int bChk = (lane >> 3) & 1;

    float acc[4][4][4];
    #pragma unroll
    for (int mt = 0; mt < 4; mt++)
        #pragma unroll
        for (int nt = 0; nt < 4; nt++)
            #pragma unroll
            for (int i = 0; i < 4; i++) acc[mt][nt][i] = 0.f;

    auto load_stage = [&](int kt, int s) {
        const uint32_t sA = sbase + s * TG_STAGE;
        const uint32_t sB = sA + 16384;
        const int k0 = kt * 64;
        #pragma unroll
        for (int j = 0; j < 4; ++j) {
            const int r = j * 32 + r0;
            const uint32_t off = swz((uint32_t)(r * 128 + ck * 16));
            cpasync16(sA + off, Ab + (size_t)r * K + k0);
            cpasync16(sB + off, Bb + (size_t)r * K + k0);
        }
        CP_COMMIT();
    };

    load_stage(0, 0);
    if (KT > 1) load_stage(1, 1);

    for (int kt = 0; kt < KT; ++kt) {
        if (kt + 1 < KT) CP_WAIT(1); else CP_WAIT(0);
        __syncthreads();
        if (kt + 2 < KT) load_stage(kt + 2, (kt + 2) % 3);

        const uint32_t sA = sbase + (kt % 3) * TG_STAGE;
        const uint32_t sB = sA + 16384;

        #pragma unroll
        for (int ks = 0; ks < 4; ++ks) {
            uint32_t af[4][4];
            #pragma unroll
            for (int mt = 0; mt < 4; ++mt) {
                const int row = wm * 64 + mt * 16 + aRow;
                const uint32_t ad = sA + swz((uint32_t)(row * 128 + ks * 32 + aChk * 16));
                ldmx4(af[mt][0], af[mt][1], af[mt][2], af[mt][3], ad);
            }
            uint32_t bf[4][2];
            #pragma unroll
            for (int np = 0; np < 2; ++np) {
                const int nrow = wn * 32 + np * 16 + bRow;
                const uint32_t bd = sB + swz((uint32_t)(nrow * 128 + ks * 32 + bChk * 16));
                uint32_t t0, t1, t2, t3;
                ldmx4(t0, t1, t2, t3, bd);
                bf[np * 2][0] = t0;     bf[np * 2][1] = t1;
                bf[np * 2 + 1][0] = t2; bf[np * 2 + 1][1] = t3;
            }
            #pragma unroll
            for (int mt = 0; mt < 4; ++mt)
                #pragma unroll
                for (int nt = 0; nt < 4; ++nt)
                    mma_f16(acc[mt][nt][0], acc[mt][nt][1],
                            acc[mt][nt][2], acc[mt][nt][3],
                            af[mt][0], af[mt][1], af[mt][2], af[mt][3],
                            bf[nt][0], bf[nt][1]);
        }
    }

    #pragma unroll
    for (int mt = 0; mt < 4; mt++) {
        const int r0g = brow * 128 + wm * 64 + mt * 16 + g;
        const int r1g = r0g + 8;
        #pragma unroll
        for (int nt = 0; nt < 4; nt++) {
            const int c = bcol * 128 + wn * 32 + nt * 8 + tg * 2;
            float2 o0 = make_float2(acc[mt][nt][0], acc[mt][nt][1]);
            float2 o1 = make_float2(acc[mt][nt][2], acc[mt][nt][3]);
            if constexpr (EPI >= 1) {
                float2 bv = *reinterpret_cast<const float2*>(bias + c);
                o0.x += bv.x; o0.y += bv.y;
                o1.x += bv.x; o1.y += bv.y;
            }
            if constexpr (EPI == 1) {
                float2 rv0 = *reinterpret_cast<const float2*>(resid + (size_t)r0g * N + c);
                float2 rv1 = *reinterpret_cast<const float2*>(resid + (size_t)r1g * N + c);
                o0.x += rv0.x; o0.y += rv0.y;
                o1.x += rv1.x; o1.y += rv1.y;
                float* C = (float*)Cv;
                *reinterpret_cast<float2*>(C + (size_t)r0g * N + c) = o0;
                *reinterpret_cast<float2*>(C + (size_t)r1g * N + c) = o1;
            } else {
                if constexpr (EPI == 2) {
                    o0.x = fmaxf(o0.x, 0.f); o0.y = fmaxf(o0.y, 0.f);
                    o1.x = fmaxf(o1.x, 0.f); o1.y = fmaxf(o1.y, 0.f);
                }
                __half* C = (__half*)Cv;
                __half2 h0 = __floats2half2_rn(o0.x, o0.y);
                __half2 h1 = __floats2half2_rn(o1.x, o1.y);
                *reinterpret_cast<__half2*>(C + (size_t)r0g * N + c) = h0;
                *reinterpret_cast<__half2*>(C + (size_t)r1g * N + c) = h1;
            }
        }
    }
}

// ---------------- fast exp2 (fma pipe) ----------------
__device__ __forceinline__ float fexp2(float x) {
    x = fmaxf(x, -120.f);
    float k  = __fadd_rn(x, 12582912.f);
    int   sc = __float_as_int(k) << 23;
    float f  = __fsub_rn(x, __fsub_rn(k, 12582912.f));
    float p  = 0.0013333558f;
    p = fmaf(p, f, 0.0096181291f);
    p = fmaf(p, f, 0.0555041087f);
    p = fmaf(p, f, 0.2402265070f);
    p = fmaf(p, f, 0.6931471806f);
    p = fmaf(p, f, 1.0f);
    return __int_as_float(__float_as_int(p) + sc);
}

// ---------------- flash attention v6: all-fp16 mma (split-K) ----------------
// 64q x 64k tiles, 128 threads, 4 CTAs/SM. Q/K/V fp16 smem, 128B swizzled rows.
// QK^T: ldmatrix frags. PV: P packed from C-frags in regs (no shfl/smem!),
// V B-frags via ldmatrix.trans. Max 16 k-tiles/block + split-K merge.
#define FA_SMEM (3 * 64 * 128)    // 24 KB

__global__ __launch_bounds__(128, 4) void flash_tc(
    const __half* __restrict__ qkv, __half* __restrict__ out,
    float* __restrict__ pO, float* __restrict__ pml)
{
    extern __shared__ char fsm[];
    const uint32_t qsb = smem_u32(fsm);
    const uint32_t ksb = qsb + 64 * 128;
    const uint32_t vsb = ksb + 64 * 128;

    const int tid  = threadIdx.x;
    const int warp = tid >> 5;
    const int lane = tid & 31;
    const int g    = lane >> 2;
    const int tg   = lane & 3;
    const int bx   = blockIdx.x;
    const int h    = blockIdx.y;
    int qb, seg;
    if (bx < 32) { qb = 16 + (bx >> 1); seg = bx & 1; }
    else         { qb = bx - 32;        seg = 0; }
    const int q0   = qb * 64;
    const int w16  = warp * 16;
    const int kt0  = seg * 16;
    const int kt1  = min(qb + 1, kt0 + 16);
    const bool full = (kt0 == 0) && (kt1 == qb + 1);

    const int aRow = (lane & 7) + ((lane >> 3) & 1) * 8;
    const int aChk = lane >> 4;
    const int bRow = (lane & 7) + (lane >> 4) * 8;
    const int bChk = (lane >> 3) & 1;
    // V-trans lane mapping: matrix = lane>>3 -> (khalf = (lane>>3)&1, +dblk = lane>>4)
    const int vKeyLoc = ((lane >> 3) & 1) * 8 + (lane & 7);
    const int vL7  = lane & 7;
    const int vL16 = lane >> 4;

    const __half* qp = qkv + h * HSZ;
    const __half* kp = qkv + DD + h * HSZ;
    const __half* vp = qkv + 2 * DD + h * HSZ;

    // Q tile: 64 rows x 128B (8 chunks) = 512 chunks / 128 thr = 4 each
    {
        #pragma unroll
        for (int j = 0; j < 4; ++j) {
            int idx = j * 128 + tid;
            int r = idx >> 3, ck = idx & 7;
            cpasync16(qsb + swz((uint32_t)(r * 128 + ck * 16)),
                      qp + (size_t)(q0 + r) * (3 * DD) + ck * 8);
        }
        CP_COMMIT();
    }

    float O[8][4];
    #pragma unroll
    for (int nt = 0; nt < 8; nt++)
        #pragma unroll
        for (int i = 0; i < 4; i++) O[nt][i] = 0.f;
    float m0 = -1e30f, m1 = -1e30f, l0 = 0.f, l1 = 0.f;

    const int row0 = q0 + w16 + g;
    const int row1 = row0 + 8;
    const float SC = 0.18033688011112042f;   // (1/8) * log2(e)

    for (int kt = kt0; kt < kt1; ++kt) {
        __syncthreads();
        {
            #pragma unroll
            for (int j = 0; j < 4; ++j) {
                int idx = j * 128 + tid;
                int r = idx >> 3, ck = idx & 7;
                size_t gi = (size_t)(kt * 64 + r) * (3 * DD) + ck * 8;
                uint32_t off = swz((uint32_t)(r * 128 + ck * 16));
                cpasync16(ksb + off, kp + gi);
                cpasync16(vsb + off, vp + gi);
            }
            CP_COMMIT();
        }
        CP_WAIT(0);
        __syncthreads();

        // ---- S = Q K^T : 4 k16-steps ----
        float s[8][4];
        #pragma unroll
        for (int nt = 0; nt < 8; nt++)
            #pragma unroll
            for (int i = 0; i < 4; i++) s[nt][i] = 0.f;

        #pragma unroll
        for (int kk = 0; kk < 4; ++kk) {
            uint32_t a0, a1, a2, a3;
            ldmx4(a0, a1, a2, a3,
                  qsb + swz((uint32_t)((w16 + aRow) * 128 + kk * 32 + aChk * 16)));
            uint32_t bf[8][2];
            #pragma unroll
            for (int n16 = 0; n16 < 4; ++n16) {
                uint32_t t0, t1, t2, t3;
                ldmx4(t0, t1, t2, t3,
                      ksb + swz((uint32_t)((n16 * 16 + bRow) * 128 + kk * 32 + bChk * 16)));
                bf[n16 * 2][0] = t0;     bf[n16 * 2][1] = t1;
                bf[n16 * 2 + 1][0] = t2; bf[n16 * 2 + 1][1] = t3;
            }
            #pragma unroll
            for (int nt = 0; nt < 8; ++nt)
                mma_f16(s[nt][0], s[nt][1], s[nt][2], s[nt][3],
                        a0, a1, a2, a3, bf[nt][0], bf[nt][1]);
        }

        // ---- softmax (log2 domain), causal mask ----
        float mb0 = -1e30f, mb1 = -1e30f;
        #pragma unroll
        for (int nt = 0; nt < 8; ++nt) {
            int c0 = kt * 64 + nt * 8 + 2 * tg;
            float z0 = (c0     > row0) ? -1e30f : s[nt][0] * SC;
            float z1 = (c0 + 1 > row0) ? -1e30f : s[nt][1] * SC;
            float z2 = (c0     > row1) ? -1e30f : s[nt][2] * SC;
            float z3 = (c0 + 1 > row1) ? -1e30f : s[nt][3] * SC;
            s[nt][0] = z0; s[nt][1] = z1; s[nt][2] = z2; s[nt][3] = z3;
            mb0 = fmaxf(mb0, fmaxf(z0, z1));
            mb1 = fmaxf(mb1, fmaxf(z2, z3));
        }
        mb0 = fmaxf(mb0, __shfl_xor_sync(0xffffffffu, mb0, 1));
        mb0 = fmaxf(mb0, __shfl_xor_sync(0xffffffffu, mb0, 2));
        mb1 = fmaxf(mb1, __shfl_xor_sync(0xffffffffu, mb1, 1));
        mb1 = fmaxf(mb1, __shfl_xor_sync(0xffffffffu, mb1, 2));

        float mn0 = fmaxf(m0, mb0), mn1 = fmaxf(m1, mb1);
        float al0 = fexp2(m0 - mn0), al1 = fexp2(m1 - mn1);
        m0 = mn0; m1 = mn1;

        float rs0 = 0.f, rs1 = 0.f;
        #pragma unroll
        for (int nt = 0; nt < 8; ++nt) {
            float p0 = fexp2(s[nt][0] - mn0);
            float p1 = fexp2(s[nt][1] - mn0);
            float p2 = fexp2(s[nt][2] - mn1);
            float p3 = fexp2(s[nt][3] - mn1);
            rs0 += p0 + p1; rs1 += p2 + p3;
            s[nt][0] = p0; s[nt][1] = p1; s[nt][2] = p2; s[nt][3] = p3;
        }
        rs0 += __shfl_xor_sync(0xffffffffu, rs0, 1);
        rs0 += __shfl_xor_sync(0xffffffffu, rs0, 2);
        rs1 += __shfl_xor_sync(0xffffffffu, rs1, 1);
        rs1 += __shfl_xor_sync(0xffffffffu, rs1, 2);
        l0 = l0 * al0 + rs0;
        l1 = l1 * al1 + rs1;

        #pragma unroll
        for (int nt = 0; nt < 8; ++nt) {
            O[nt][0] *= al0; O[nt][1] *= al0;
            O[nt][2] *= al1; O[nt][3] *= al1;
        }

        // ---- O += P V : P A-frags packed from C-frags (register-local),
        //                 V B-frags via ldmatrix.trans ----
        #pragma unroll
        for (int kk = 0; kk < 4; ++kk) {
            uint32_t a0 = packh2(s[2*kk][0],   s[2*kk][1]);     // row g,   k 2tg..
            uint32_t a1 = packh2(s[2*kk][2],   s[2*kk][3]);     // row g+8, k 2tg..
            uint32_t a2 = packh2(s[2*kk+1][0], s[2*kk+1][1]);   // row g,   k 2tg+8..
            uint32_t a3 = packh2(s[2*kk+1][2], s[2*kk+1][3]);   // row g+8, k 2tg+8..
            #pragma unroll
            for (int i = 0; i < 4; ++i) {      // d-block pairs (n16)
                const int key = kt * 0 + 16 * kk + vKeyLoc;     // local key row
                const uint32_t dblk = (uint32_t)(((2 * i + vL16) ^ vL7) * 16);
                uint32_t t0, t1, t2, t3;
                ldmx4t(t0, t1, t2, t3, vsb + (uint32_t)(key * 128) + dblk);
                mma_f16(O[2*i][0], O[2*i][1], O[2*i][2], O[2*i][3],
                        a0, a1, a2, a3, t0, t1);
                mma_f16(O[2*i+1][0], O[2*i+1][1], O[2*i+1][2], O[2*i+1][3],
                        a0, a1, a2, a3, t2, t3);
            }
        }
    }

    if (full) {
        float inv0 = 1.0f / l0, inv1 = 1.0f / l1;
        #pragma unroll
        for (int nt = 0; nt < 8; ++nt) {
            int c = h * HSZ + nt * 8 + 2 * tg;
            __half2 o0 = __floats2half2_rn(O[nt][0] * inv0, O[nt][1] * inv0);
            __half2 o1 = __floats2half2_rn(O[nt][2] * inv1, O[nt][3] * inv1);
            *reinterpret_cast<__half2*>(out + (size_t)row0 * DD + c) = o0;
            *reinterpret_cast<__half2*>(out + (size_t)row1 * DD + c) = o1;
        }
    } else {
        const int p = (h * 16 + (qb - 16)) * 2 + seg;
        float* pb = pO + (size_t)p * 4096;
        const int lr0 = w16 + g, lr1 = lr0 + 8;
        #pragma unroll
        for (int nt = 0; nt < 8; ++nt) {
            int c = nt * 8 + 2 * tg;
            *reinterpret_cast<float2*>(pb + lr0 * 64 + c) = make_float2(O[nt][0], O[nt][1]);
            *reinterpret_cast<float2*>(pb + lr1 * 64 + c) = make_float2(O[nt][2], O[nt][3]);
        }
        if (tg == 0) {
            float* mlb = pml + (size_t)p * 128;
            mlb[lr0 * 2]     = m0;
            mlb[lr0 * 2 + 1] = l0;
            mlb[lr1 * 2]     = m1;
            mlb[lr1 * 2 + 1] = l1;
        }
    }
}

// ---------------- split-K merge (writes fp16 att) ----------------
__global__ __launch_bounds__(128) void flash_merge(
    const float* __restrict__ pO, const float* __restrict__ pml,
    __half* __restrict__ out)
{
    __shared__ float w0s[64], w1s[64];
    const int qb16 = blockIdx.x;
    const int h    = blockIdx.y;
    const int tid  = threadIdx.x;
    const int p0 = (h * 16 + qb16) * 2;
    const int p1 = p0 + 1;

    if (tid < 64) {
        float m0 = pml[(size_t)p0 * 128 + tid * 2];
        float l0 = pml[(size_t)p0 * 128 + tid * 2 + 1];
        float m1 = pml[(size_t)p1 * 128 + tid * 2];
        float l1 = pml[(size_t)p1 * 128 + tid * 2 + 1];
        float M  = fmaxf(m0, m1);
        float w0 = fexp2(m0 - M), w1 = fexp2(m1 - M);
        float inv = 1.0f / (w0 * l0 + w1 * l1);
        w0s[tid] = w0 * inv;
        w1s[tid] = w1 * inv;
    }
    __syncthreads();

    const float* b0 = pO + (size_t)p0 * 4096;
    const float* b1 = pO + (size_t)p1 * 4096;
    const int q0 = (16 + qb16) * 64;
    #pragma unroll
    for (int i = 0; i < 8; ++i) {
        int idx = (i * 128 + tid) * 4;
        int r = idx >> 6, c = idx & 63;
        float4 v0 = *reinterpret_cast<const float4*>(b0 + r * 64 + c);
        float4 v1 = *reinterpret_cast<const float4*>(b1 + r * 64 + c);
        float w0 = w0s[r], w1 = w1s[r];
        union { __half2 h[2]; uint2 u; } pk;
        pk.h[0] = __floats2half2_rn(w0 * v0.x + w1 * v1.x, w0 * v0.y + w1 * v1.y);
        pk.h[1] = __floats2half2_rn(w0 * v0.z + w1 * v1.z, w0 * v0.w + w1 * v1.w);
        *reinterpret_cast<uint2*>(out + (size_t)(q0 + r) * DD + h * HSZ + c) = pk.u;
    }
}

// ---------------- launch ----------------
extern "C" void kernel_launch(void* const* d_in, const int* in_sizes, int n_in,
                              void* d_out, int out_size)
{
    const float* x    = (const float*)d_in[0];
    const float* Wq   = (const float*)d_in[1];
    const float* Wk   = (const float*)d_in[2];
    const float* Wv   = (const float*)d_in[3];
    const float* Wo   = (const float*)d_in[4];
    const float* bo   = (const float*)d_in[5];
    const float* W1   = (const float*)d_in[6];
    const float* b1   = (const float*)d_in[7];
    const float* W2   = (const float*)d_in[8];
    const float* b2   = (const float*)d_in[9];
    const float* ln1s = (const float*)d_in[10];
    const float* ln1b = (const float*)d_in[11];
    const float* ln2s = (const float*)d_in[12];
    const float* ln2b = (const float*)d_in[13];
    float* out = (float*)d_out;

    __half *h, *wqkvT, *woT, *w1T, *w2T, *att, *ff, *qkv;
    float *x2, *pO, *pml;
    cudaGetSymbolAddress((void**)&h,     g_h);
    cudaGetSymbolAddress((void**)&wqkvT, g_wqkvT);
    cudaGetSymbolAddress((void**)&woT,   g_WoT);
    cudaGetSymbolAddress((void**)&w1T,   g_W1T);
    cudaGetSymbolAddress((void**)&w2T,   g_W2T);
    cudaGetSymbolAddress((void**)&qkv,   g_qkv);
    cudaGetSymbolAddress((void**)&att,   g_att);
    cudaGetSymbolAddress((void**)&x2,    g_x2);
    cudaGetSymbolAddress((void**)&ff,    g_ff);
    cudaGetSymbolAddress((void**)&pO,    g_pO);
    cudaGetSymbolAddress((void**)&pml,   g_pml);

    cudaFuncSetAttribute(flash_tc, cudaFuncAttributeMaxDynamicSharedMemorySize, FA_SMEM);
    cudaFuncSetAttribute(tg2<0>, cudaFuncAttributeMaxDynamicSharedMemorySize, TG_SMEM);
    cudaFuncSetAttribute(tg2<1>, cudaFuncAttributeMaxDynamicSharedMemorySize, TG_SMEM);
    cudaFuncSetAttribute(tg2<2>, cudaFuncAttributeMaxDynamicSharedMemorySize, TG_SMEM);

    // 1. LN1 -> fp16
    ln_kernel<<<TT, 256>>>(x, ln1s, ln1b, h);
    // 2. weight transposes -> fp16 K-major
    transpose_all<<<12288, dim3(32, 8)>>>(Wq, Wk, Wv, Wo, W1, W2,
                                          wqkvT, woT, w1T, w2T);
    // 3. QKV GEMM (fp16 out)
    tg2<0><<<dim3(3 * DD / 128, TT / 128), 256, TG_SMEM>>>(
        TT, 3 * DD, DD, h, wqkvT, nullptr, nullptr, qkv);
    // 4. flash attention split-K, all-fp16 mma
    flash_tc<<<dim3(48, HH), 128, FA_SMEM>>>(qkv, att, pO, pml);
    flash_merge<<<dim3(16, HH), 128>>>(pO, pml, att);
    // 5. output proj + bias + residual (fp32 out)
    tg2<1><<<dim3(DD / 128, TT / 128), 256, TG_SMEM>>>(
        TT, DD, DD, att, woT, bo, x, x2);
    // 6. LN2 -> fp16
    ln_kernel<<<TT, 256>>>(x2, ln2s, ln2b, h);
    // 7. FFN1 (relu, fp16 out)
    tg2<2><<<dim3(DFF / 128, TT / 128), 256, TG_SMEM>>>(
        TT, DFF, DD, h, w1T, b1, nullptr, ff);
    // 8. FFN2 (fp32 out)
    tg2<1><<<dim3(DD / 128, TT / 128), 256, TG_SMEM>>>(
        TT, DD, DFF, ff, w2T, b2, x2, out);
}

// round 13
// speedup vs baseline: 2.4649x; 1.0045x over previous
#include <cuda_runtime.h>
#include <cuda_fp16.h>
#include <cstdint>

#define TT 2048
#define DD 1024
#define HH 16
#define HSZ 64
#define DFF 4096

// ---------------- scratch (no allocs allowed) ----------------
__device__ __half g_h[TT * DD];            // LN output (fp16)
__device__ __half g_wqkvT[3 * DD * DD];    // QKV weights, [3D][D] K-major (fp16)
__device__ __half g_WoT[DD * DD];          // Wo^T (fp16)
__device__ __half g_W1T[DD * DFF];         // W1^T (fp16)
__device__ __half g_W2T[DFF * DD];         // W2^T (fp16)
__device__ __half g_qkv[TT * 3 * DD];      // QKV activations (fp16)
__device__ __half g_att[TT * DD];          // attention output (fp16)
__device__ float  g_x2[TT * DD];           // residual after attention (fp32)
__device__ __half g_ff[TT * DFF];          // FFN hidden (fp16)
__device__ float  g_pO[16 * 16 * 2 * 64 * 64];   // split-K partials
__device__ float  g_pml[16 * 16 * 2 * 64 * 2];

// ---------------- helpers ----------------
__device__ __forceinline__ uint32_t smem_u32(const void* p) {
    return (uint32_t)__cvta_generic_to_shared(p);
}
__device__ __forceinline__ uint32_t swz(uint32_t off) {
    return off ^ ((off >> 3) & 0x70);
}
__device__ __forceinline__ void mma_f16(
    float& d0, float& d1, float& d2, float& d3,
    uint32_t a0, uint32_t a1, uint32_t a2, uint32_t a3,
    uint32_t b0, uint32_t b1)
{
    asm volatile(
        "mma.sync.aligned.m16n8k16.row.col.f32.f16.f16.f32 "
        "{%0,%1,%2,%3}, {%4,%5,%6,%7}, {%8,%9}, {%0,%1,%2,%3};\n"
        : "+f"(d0), "+f"(d1), "+f"(d2), "+f"(d3)
        : "r"(a0), "r"(a1), "r"(a2), "r"(a3), "r"(b0), "r"(b1));
}
__device__ __forceinline__ void ldmx4(
    uint32_t& r0, uint32_t& r1, uint32_t& r2, uint32_t& r3, uint32_t addr)
{
    asm volatile("ldmatrix.sync.aligned.m8n8.x4.shared.b16 {%0,%1,%2,%3}, [%4];"
                 : "=r"(r0), "=r"(r1), "=r"(r2), "=r"(r3) : "r"(addr) : "memory");
}
__device__ __forceinline__ void ldmx4t(
    uint32_t& r0, uint32_t& r1, uint32_t& r2, uint32_t& r3, uint32_t addr)
{
    asm volatile("ldmatrix.sync.aligned.m8n8.x4.trans.shared.b16 {%0,%1,%2,%3}, [%4];"
                 : "=r"(r0), "=r"(r1), "=r"(r2), "=r"(r3) : "r"(addr) : "memory");
}
__device__ __forceinline__ void cpasync16(uint32_t saddr, const void* gaddr) {
    asm volatile("cp.async.cg.shared.global [%0], [%1], 16;" :: "r"(saddr), "l"(gaddr));
}
__device__ __forceinline__ uint32_t packh2(float lo, float hi) {
    __half2 h = __floats2half2_rn(lo, hi);
    return *reinterpret_cast<uint32_t*>(&h);
}
#define CP_COMMIT() asm volatile("cp.async.commit_group;" ::: "memory")
#define CP_WAIT(n)  asm volatile("cp.async.wait_group %0;" :: "n"(n) : "memory")

// ---------------- LayerNorm (emits fp16) ----------------
__global__ __launch_bounds__(256) void ln_kernel(
    const float* __restrict__ x, const float* __restrict__ g,
    const float* __restrict__ b, __half* __restrict__ y)
{
    int row = blockIdx.x;
    int tid = threadIdx.x;
    float4 v = reinterpret_cast<const float4*>(x + (size_t)row * DD)[tid];
    float s  = v.x + v.y + v.z + v.w;
    float ss = v.x * v.x + v.y * v.y + v.z * v.z + v.w * v.w;
    #pragma unroll
    for (int o = 16; o > 0; o >>= 1) {
        s  += __shfl_xor_sync(0xffffffffu, s, o);
        ss += __shfl_xor_sync(0xffffffffu, ss, o);
    }
    __shared__ float sb[8], ssb[8], stats[2];
    int wid = tid >> 5, lane = tid & 31;
    if (lane == 0) { sb[wid] = s; ssb[wid] = ss; }
    __syncthreads();
    if (tid == 0) {
        float a = 0.f, c = 0.f;
        #pragma unroll
        for (int i = 0; i < 8; i++) { a += sb[i]; c += ssb[i]; }
        float mean = a * (1.0f / DD);
        float var  = c * (1.0f / DD) - mean * mean;
        stats[0] = mean;
        stats[1] = rsqrtf(var + 1e-6f);
    }
    __syncthreads();
    float mean = stats[0], rstd = stats[1];
    float4 gg = reinterpret_cast<const float4*>(g)[tid];
    float4 bb = reinterpret_cast<const float4*>(b)[tid];
    union { __half2 h[2]; uint2 u; } pk;
    pk.h[0] = __floats2half2_rn((v.x - mean) * rstd * gg.x + bb.x,
                                (v.y - mean) * rstd * gg.y + bb.y);
    pk.h[1] = __floats2half2_rn((v.z - mean) * rstd * gg.z + bb.z,
                                (v.w - mean) * rstd * gg.w + bb.w);
    reinterpret_cast<uint2*>(y + (size_t)row * DD)[tid] = pk.u;
}

// ---------------- ALL weight transposes in one launch (emit fp16) ----------------
__global__ __launch_bounds__(256) void transpose_all(
    const float* __restrict__ Wq, const float* __restrict__ Wk,
    const float* __restrict__ Wv, const float* __restrict__ Wo,
    const float* __restrict__ W1, const float* __restrict__ W2,
    __half* __restrict__ wqkvT, __half* __restrict__ woT,
    __half* __restrict__ w1T, __half* __restrict__ w2T)
{
    __shared__ float t[32][33];
    const int b = blockIdx.x;
    const float* ip; __half* op;
    int R, C, bx, by;
    if (b < 3072) {
        const int w = b >> 10;
        const int r = b & 1023;
        const int head = r >> 6;
        const int rr = r & 63;
        bx = (rr & 1) * 32;
        by = (rr >> 1) * 32;
        ip = (w == 0 ? Wq : (w == 1 ? Wk : Wv)) + (size_t)head * DD * HSZ;
        op = wqkvT + (size_t)w * DD * DD + (size_t)head * HSZ * DD;
        R = DD; C = HSZ;
    } else if (b < 4096) {
        const int r = b - 3072;
        bx = (r & 31) * 32; by = (r >> 5) * 32;
        ip = Wo; op = woT; R = DD; C = DD;
    } else if (b < 8192) {
        const int r = b - 4096;
        bx = (r & 127) * 32; by = (r >> 7) * 32;
        ip = W1; op = w1T; R = DD; C = DFF;
    } else {
        const int r = b - 8192;
        bx = (r & 31) * 32; by = (r >> 5) * 32;
        ip = W2; op = w2T; R = DFF; C = DD;
    }
    const int x = threadIdx.x, y = threadIdx.y;
    #pragma unroll
    for (int j = 0; j < 32; j += 8)
        t[y + j][x] = ip[(size_t)(by + y + j) * C + bx + x];
    __syncthreads();
    #pragma unroll
    for (int j = 0; j < 32; j += 8)
        op[(size_t)(bx + y + j) * R + by + x] = __float2half_rn(t[x][y + j]);
}

// ---------------- fp16 mma.sync GEMM, cp.async 3-stage + ldmatrix ----------------
// EPI: 0 = fp16 C (feeds flash), 1 = +bias+resid -> fp32 C, 2 = relu(+bias) -> fp16 C
#define TG_STAGE 32768
#define TG_SMEM  (3 * TG_STAGE)

template <int EPI>
__global__ __launch_bounds__(256, 1) void tg2(
    int M, int N, int K,
    const __half* __restrict__ A, const __half* __restrict__ Bt,
    const float* __restrict__ bias, const float* __restrict__ resid,
    void* __restrict__ Cv)
{
    extern __shared__ float dynsm[];
    const int tid  = threadIdx.x;
    const int warp = tid >> 5, lane = tid & 31;
    const int wm = warp & 1, wn = warp >> 1;
    const int g = lane >> 2, tg = lane & 3;
    const int brow = blockIdx.y, bcol = blockIdx.x;

    const uint32_t sbase = smem_u32(dynsm);
    const int r0 = tid >> 3;
    const int ck = tid & 7;
    const __half* Ab = A  + (size_t)(brow * 128) * K + ck * 8;
    const __half* Bb = Bt + (size_t)(bcol * 128) * K + ck * 8;
    const int KT = K >> 6;

    const int aRow = (lane & 7) + ((lane >> 3) & 1) * 8;
    const int aChk = (lane >> 4);
    const int bRow = (lane & 7) + (lane >> 4) * 8;
    const int bChk = (lane >> 3) & 1;

    float acc[4][4][4];
    #pragma unroll
    for (int mt = 0; mt < 4; mt++)
        #pragma unroll
        for (int nt = 0; nt < 4; nt++)
            #pragma unroll
            for (int i = 0; i < 4; i++) acc[mt][nt][i] = 0.f;

    auto load_stage = [&](int kt, int s) {
        const uint32_t sA = sbase + s * TG_STAGE;
        const uint32_t sB = sA + 16384;
        const int k0 = kt * 64;
        #pragma unroll
        for (int j = 0; j < 4; ++j) {
            const int r = j * 32 + r0;
            const uint32_t off = swz((uint32_t)(r * 128 + ck * 16));
            cpasync16(sA + off, Ab + (size_t)r * K + k0);
            cpasync16(sB + off, Bb + (size_t)r * K + k0);
        }
        CP_COMMIT();
    };

    load_stage(0, 0);
    if (KT > 1) load_stage(1, 1);

    for (int kt = 0; kt < KT; ++kt) {
        if (kt + 1 < KT) CP_WAIT(1); else CP_WAIT(0);
        __syncthreads();
        if (kt + 2 < KT) load_stage(kt + 2, (kt + 2) % 3);

        const uint32_t sA = sbase + (kt % 3) * TG_STAGE;
        const uint32_t sB = sA + 16384;

        #pragma unroll
        for (int ks = 0; ks < 4; ++ks) {
            uint32_t af[4][4];
            #pragma unroll
            for (int mt = 0; mt < 4; ++mt) {
                const int row = wm * 64 + mt * 16 + aRow;
                const uint32_t ad = sA + swz((uint32_t)(row * 128 + ks * 32 + aChk * 16));
                ldmx4(af[mt][0], af[mt][1], af[mt][2], af[mt][3], ad);
            }
            uint32_t bf[4][2];
            #pragma unroll
            for (int np = 0; np < 2; ++np) {
                const int nrow = wn * 32 + np * 16 + bRow;
                const uint32_t bd = sB + swz((uint32_t)(nrow * 128 + ks * 32 + bChk * 16));
                uint32_t t0, t1, t2, t3;
                ldmx4(t0, t1, t2, t3, bd);
                bf[np * 2][0] = t0;     bf[np * 2][1] = t1;
                bf[np * 2 + 1][0] = t2; bf[np * 2 + 1][1] = t3;
            }
            #pragma unroll
            for (int mt = 0; mt < 4; ++mt)
                #pragma unroll
                for (int nt = 0; nt < 4; ++nt)
                    mma_f16(acc[mt][nt][0], acc[mt][nt][1],
                            acc[mt][nt][2], acc[mt][nt][3],
                            af[mt][0], af[mt][1], af[mt][2], af[mt][3],
                            bf[nt][0], bf[nt][1]);
        }
    }

    #pragma unroll
    for (int mt = 0; mt < 4; mt++) {
        const int r0g = brow * 128 + wm * 64 + mt * 16 + g;
        const int r1g = r0g + 8;
        #pragma unroll
        for (int nt = 0; nt < 4; nt++) {
            const int c = bcol * 128 + wn * 32 + nt * 8 + tg * 2;
            float2 o0 = make_float2(acc[mt][nt][0], acc[mt][nt][1]);
            float2 o1 = make_float2(acc[mt][nt][2], acc[mt][nt][3]);
            if constexpr (EPI >= 1) {
                float2 bv = *reinterpret_cast<const float2*>(bias + c);
                o0.x += bv.x; o0.y += bv.y;
                o1.x += bv.x; o1.y += bv.y;
            }
            if constexpr (EPI == 1) {
                float2 rv0 = *reinterpret_cast<const float2*>(resid + (size_t)r0g * N + c);
                float2 rv1 = *reinterpret_cast<const float2*>(resid + (size_t)r1g * N + c);
                o0.x += rv0.x; o0.y += rv0.y;
                o1.x += rv1.x; o1.y += rv1.y;
                float* C = (float*)Cv;
                *reinterpret_cast<float2*>(C + (size_t)r0g * N + c) = o0;
                *reinterpret_cast<float2*>(C + (size_t)r1g * N + c) = o1;
            } else {
                if constexpr (EPI == 2) {
                    o0.x = fmaxf(o0.x, 0.f); o0.y = fmaxf(o0.y, 0.f);
                    o1.x = fmaxf(o1.x, 0.f); o1.y = fmaxf(o1.y, 0.f);
                }
                __half* C = (__half*)Cv;
                __half2 h0 = __floats2half2_rn(o0.x, o0.y);
                __half2 h1 = __floats2half2_rn(o1.x, o1.y);
                *reinterpret_cast<__half2*>(C + (size_t)r0g * N + c) = h0;
                *reinterpret_cast<__half2*>(C + (size_t)r1g * N + c) = h1;
            }
        }
    }
}

// ---------------- fast exp2 (fma pipe) ----------------
__device__ __forceinline__ float fexp2(float x) {
    x = fmaxf(x, -120.f);
    float k  = __fadd_rn(x, 12582912.f);
    int   sc = __float_as_int(k) << 23;
    float f  = __fsub_rn(x, __fsub_rn(k, 12582912.f));
    float p  = 0.0013333558f;
    p = fmaf(p, f, 0.0096181291f);
    p = fmaf(p, f, 0.0555041087f);
    p = fmaf(p, f, 0.2402265070f);
    p = fmaf(p, f, 0.6931471806f);
    p = fmaf(p, f, 1.0f);
    return __int_as_float(__float_as_int(p) + sc);
}

// ---------------- flash attention v7: all-fp16 mma, K/V double-buffered ----------------
// 64q x 64k tiles, 128 threads, 4 CTAs/SM. smem = Q 8KB + 2x(K 8KB + V 8KB) = 40KB.
#define FA_SMEM (5 * 64 * 128)    // 40 KB

__global__ __launch_bounds__(128, 4) void flash_tc(
    const __half* __restrict__ qkv, __half* __restrict__ out,
    float* __restrict__ pO, float* __restrict__ pml)
{
    extern __shared__ char fsm[];
    const uint32_t qsb = smem_u32(fsm);
    // buffer b: K at qsb + 8192 + b*16384, V at +8192 more
    const int tid  = threadIdx.x;
    const int warp = tid >> 5;
    const int lane = tid & 31;
    const int g    = lane >> 2;
    const int tg   = lane & 3;
    const int bx   = blockIdx.x;
    const int h    = blockIdx.y;
    int qb, seg;
    if (bx < 32) { qb = 16 + (bx >> 1); seg = bx & 1; }
    else         { qb = bx - 32;        seg = 0; }
    const int q0   = qb * 64;
    const int w16  = warp * 16;
    const int kt0  = seg * 16;
    const int kt1  = min(qb + 1, kt0 + 16);
    const bool full = (kt0 == 0) && (kt1 == qb + 1);

    const int aRow = (lane & 7) + ((lane >> 3) & 1) * 8;
    const int aChk = lane >> 4;
    const int bRow = (lane & 7) + (lane >> 4) * 8;
    const int bChk = (lane >> 3) & 1;
    const int vKeyLoc = ((lane >> 3) & 1) * 8 + (lane & 7);
    const int vL7  = lane & 7;
    const int vL16 = lane >> 4;

    const __half* qp = qkv + h * HSZ;
    const __half* kp = qkv + DD + h * HSZ;
    const __half* vp = qkv + 2 * DD + h * HSZ;

    // loader for K/V tile kt into buffer b
    auto load_kv = [&](int kt, int b) {
        const uint32_t kb = qsb + 8192 + b * 16384;
        const uint32_t vb = kb + 8192;
        #pragma unroll
        for (int j = 0; j < 4; ++j) {
            int idx = j * 128 + tid;
            int r = idx >> 3, ck = idx & 7;
            size_t gi = (size_t)(kt * 64 + r) * (3 * DD) + ck * 8;
            uint32_t off = swz((uint32_t)(r * 128 + ck * 16));
            cpasync16(kb + off, kp + gi);
            cpasync16(vb + off, vp + gi);
        }
        CP_COMMIT();
    };

    // Q tile
    {
        #pragma unroll
        for (int j = 0; j < 4; ++j) {
            int idx = j * 128 + tid;
            int r = idx >> 3, ck = idx & 7;
            cpasync16(qsb + swz((uint32_t)(r * 128 + ck * 16)),
                      qp + (size_t)(q0 + r) * (3 * DD) + ck * 8);
        }
        CP_COMMIT();
    }
    // prefetch first K/V tile
    load_kv(kt0, kt0 & 1);

    float O[8][4];
    #pragma unroll
    for (int nt = 0; nt < 8; nt++)
        #pragma unroll
        for (int i = 0; i < 4; i++) O[nt][i] = 0.f;
    float m0 = -1e30f, m1 = -1e30f, l0 = 0.f, l1 = 0.f;

    const int row0 = q0 + w16 + g;
    const int row1 = row0 + 8;
    const float SC = 0.18033688011112042f;   // (1/8) * log2(e)

    for (int kt = kt0; kt < kt1; ++kt) {
        const bool has_next = (kt + 1 < kt1);
        if (has_next) load_kv(kt + 1, (kt + 1) & 1);   // prefetch behind compute
        if (has_next) CP_WAIT(1); else CP_WAIT(0);
        __syncthreads();

        const uint32_t ksb = qsb + 8192 + (kt & 1) * 16384;
        const uint32_t vsb = ksb + 8192;

        // ---- S = Q K^T : 4 k16-steps ----
        float s[8][4];
        #pragma unroll
        for (int nt = 0; nt < 8; nt++)
            #pragma unroll
            for (int i = 0; i < 4; i++) s[nt][i] = 0.f;

        #pragma unroll
        for (int kk = 0; kk < 4; ++kk) {
            uint32_t a0, a1, a2, a3;
            ldmx4(a0, a1, a2, a3,
                  qsb + swz((uint32_t)((w16 + aRow) * 128 + kk * 32 + aChk * 16)));
            uint32_t bf[8][2];
            #pragma unroll
            for (int n16 = 0; n16 < 4; ++n16) {
                uint32_t t0, t1, t2, t3;
                ldmx4(t0, t1, t2, t3,
                      ksb + swz((uint32_t)((n16 * 16 + bRow) * 128 + kk * 32 + bChk * 16)));
                bf[n16 * 2][0] = t0;     bf[n16 * 2][1] = t1;
                bf[n16 * 2 + 1][0] = t2; bf[n16 * 2 + 1][1] = t3;
            }
            #pragma unroll
            for (int nt = 0; nt < 8; ++nt)
                mma_f16(s[nt][0], s[nt][1], s[nt][2], s[nt][3],
                        a0, a1, a2, a3, bf[nt][0], bf[nt][1]);
        }

        // ---- softmax (log2 domain), causal mask ----
        float mb0 = -1e30f, mb1 = -1e30f;
        #pragma unroll
        for (int nt = 0; nt < 8; ++nt) {
            int c0 = kt * 64 + nt * 8 + 2 * tg;
            float z0 = (c0     > row0) ? -1e30f : s[nt][0] * SC;
            float z1 = (c0 + 1 > row0) ? -1e30f : s[nt][1] * SC;
            float z2 = (c0     > row1) ? -1e30f : s[nt][2] * SC;
            float z3 = (c0 + 1 > row1) ? -1e30f : s[nt][3] * SC;
            s[nt][0] = z0; s[nt][1] = z1; s[nt][2] = z2; s[nt][3] = z3;
            mb0 = fmaxf(mb0, fmaxf(z0, z1));
            mb1 = fmaxf(mb1, fmaxf(z2, z3));
        }
        mb0 = fmaxf(mb0, __shfl_xor_sync(0xffffffffu, mb0, 1));
        mb0 = fmaxf(mb0, __shfl_xor_sync(0xffffffffu, mb0, 2));
        mb1 = fmaxf(mb1, __shfl_xor_sync(0xffffffffu, mb1, 1));
        mb1 = fmaxf(mb1, __shfl_xor_sync(0xffffffffu, mb1, 2));

        float mn0 = fmaxf(m0, mb0), mn1 = fmaxf(m1, mb1);
        float al0 = fexp2(m0 - mn0), al1 = fexp2(m1 - mn1);
        m0 = mn0; m1 = mn1;

        float rs0 = 0.f, rs1 = 0.f;
        #pragma unroll
        for (int nt = 0; nt < 8; ++nt) {
            float p0 = fexp2(s[nt][0] - mn0);
            float p1 = fexp2(s[nt][1] - mn0);
            float p2 = fexp2(s[nt][2] - mn1);
            float p3 = fexp2(s[nt][3] - mn1);
            rs0 += p0 + p1; rs1 += p2 + p3;
            s[nt][0] = p0; s[nt][1] = p1; s[nt][2] = p2; s[nt][3] = p3;
        }
        rs0 += __shfl_xor_sync(0xffffffffu, rs0, 1);
        rs0 += __shfl_xor_sync(0xffffffffu, rs0, 2);
        rs1 += __shfl_xor_sync(0xffffffffu, rs1, 1);
        rs1 += __shfl_xor_sync(0xffffffffu, rs1, 2);
        l0 = l0 * al0 + rs0;
        l1 = l1 * al1 + rs1;

        #pragma unroll
        for (int nt = 0; nt < 8; ++nt) {
            O[nt][0] *= al0; O[nt][1] *= al0;
            O[nt][2] *= al1; O[nt][3] *= al1;
        }

        // ---- O += P V : P packed from C-frags; V via ldmatrix.trans ----
        #pragma unroll
        for (int kk = 0; kk < 4; ++kk) {
            uint32_t a0 = packh2(s[2*kk][0],   s[2*kk][1]);
            uint32_t a1 = packh2(s[2*kk][2],   s[2*kk][3]);
            uint32_t a2 = packh2(s[2*kk+1][0], s[2*kk+1][1]);
            uint32_t a3 = packh2(s[2*kk+1][2], s[2*kk+1][3]);
            #pragma unroll
            for (int i = 0; i < 4; ++i) {
                const int key = 16 * kk + vKeyLoc;
                const uint32_t dblk = (uint32_t)(((2 * i + vL16) ^ vL7) * 16);
                uint32_t t0, t1, t2, t3;
                ldmx4t(t0, t1, t2, t3, vsb + (uint32_t)(key * 128) + dblk);
                mma_f16(O[2*i][0], O[2*i][1], O[2*i][2], O[2*i][3],
                        a0, a1, a2, a3, t0, t1);
                mma_f16(O[2*i+1][0], O[2*i+1][1], O[2*i+1][2], O[2*i+1][3],
                        a0, a1, a2, a3, t2, t3);
            }
        }
        if (has_next) __syncthreads();   // all reads of this buffer done before reuse
    }

    if (full) {
        float inv0 = 1.0f / l0, inv1 = 1.0f / l1;
        #pragma unroll
        for (int nt = 0; nt < 8; ++nt) {
            int c = h * HSZ + nt * 8 + 2 * tg;
            __half2 o0 = __floats2half2_rn(O[nt][0] * inv0, O[nt][1] * inv0);
            __half2 o1 = __floats2half2_rn(O[nt][2] * inv1, O[nt][3] * inv1);
            *reinterpret_cast<__half2*>(out + (size_t)row0 * DD + c) = o0;
            *reinterpret_cast<__half2*>(out + (size_t)row1 * DD + c) = o1;
        }
    } else {
        const int p = (h * 16 + (qb - 16)) * 2 + seg;
        float* pb = pO + (size_t)p * 4096;
        const int lr0 = w16 + g, lr1 = lr0 + 8;
        #pragma unroll
        for (int nt = 0; nt < 8; ++nt) {
            int c = nt * 8 + 2 * tg;
            *reinterpret_cast<float2*>(pb + lr0 * 64 + c) = make_float2(O[nt][0], O[nt][1]);
            *reinterpret_cast<float2*>(pb + lr1 * 64 + c) = make_float2(O[nt][2], O[nt][3]);
        }
        if (tg == 0) {
            float* mlb = pml + (size_t)p * 128;
            mlb[lr0 * 2]     = m0;
            mlb[lr0 * 2 + 1] = l0;
            mlb[lr1 * 2]     = m1;
            mlb[lr1 * 2 + 1] = l1;
        }
    }
}

// ---------------- split-K merge (writes fp16 att) ----------------
__global__ __launch_bounds__(128) void flash_merge(
    const float* __restrict__ pO, const float* __restrict__ pml,
    __half* __restrict__ out)
{
    __shared__ float w0s[64], w1s[64];
    const int qb16 = blockIdx.x;
    const int h    = blockIdx.y;
    const int tid  = threadIdx.x;
    const int p0 = (h * 16 + qb16) * 2;
    const int p1 = p0 + 1;

    if (tid < 64) {
        float m0 = pml[(size_t)p0 * 128 + tid * 2];
        float l0 = pml[(size_t)p0 * 128 + tid * 2 + 1];
        float m1 = pml[(size_t)p1 * 128 + tid * 2];
        float l1 = pml[(size_t)p1 * 128 + tid * 2 + 1];
        float M  = fmaxf(m0, m1);
        float w0 = fexp2(m0 - M), w1 = fexp2(m1 - M);
        float inv = 1.0f / (w0 * l0 + w1 * l1);
        w0s[tid] = w0 * inv;
        w1s[tid] = w1 * inv;
    }
    __syncthreads();

    const float* b0 = pO + (size_t)p0 * 4096;
    const float* b1 = pO + (size_t)p1 * 4096;
    const int q0 = (16 + qb16) * 64;
    #pragma unroll
    for (int i = 0; i < 8; ++i) {
        int idx = (i * 128 + tid) * 4;
        int r = idx >> 6, c = idx & 63;
        float4 v0 = *reinterpret_cast<const float4*>(b0 + r * 64 + c);
        float4 v1 = *reinterpret_cast<const float4*>(b1 + r * 64 + c);
        float w0 = w0s[r], w1 = w1s[r];
        union { __half2 h[2]; uint2 u; } pk;
        pk.h[0] = __floats2half2_rn(w0 * v0.x + w1 * v1.x, w0 * v0.y + w1 * v1.y);
        pk.h[1] = __floats2half2_rn(w0 * v0.z + w1 * v1.z, w0 * v0.w + w1 * v1.w);
        *reinterpret_cast<uint2*>(out + (size_t)(q0 + r) * DD + h * HSZ + c) = pk.u;
    }
}

// ---------------- launch ----------------
extern "C" void kernel_launch(void* const* d_in, const int* in_sizes, int n_in,
                              void* d_out, int out_size)
{
    const float* x    = (const float*)d_in[0];
    const float* Wq   = (const float*)d_in[1];
    const float* Wk   = (const float*)d_in[2];
    const float* Wv   = (const float*)d_in[3];
    const float* Wo   = (const float*)d_in[4];
    const float* bo   = (const float*)d_in[5];
    const float* W1   = (const float*)d_in[6];
    const float* b1   = (const float*)d_in[7];
    const float* W2   = (const float*)d_in[8];
    const float* b2   = (const float*)d_in[9];
    const float* ln1s = (const float*)d_in[10];
    const float* ln1b = (const float*)d_in[11];
    const float* ln2s = (const float*)d_in[12];
    const float* ln2b = (const float*)d_in[13];
    float* out = (float*)d_out;

    __half *h, *wqkvT, *woT, *w1T, *w2T, *att, *ff, *qkv;
    float *x2, *pO, *pml;
    cudaGetSymbolAddress((void**)&h,     g_h);
    cudaGetSymbolAddress((void**)&wqkvT, g_wqkvT);
    cudaGetSymbolAddress((void**)&woT,   g_WoT);
    cudaGetSymbolAddress((void**)&w1T,   g_W1T);
    cudaGetSymbolAddress((void**)&w2T,   g_W2T);
    cudaGetSymbolAddress((void**)&qkv,   g_qkv);
    cudaGetSymbolAddress((void**)&att,   g_att);
    cudaGetSymbolAddress((void**)&x2,    g_x2);
    cudaGetSymbolAddress((void**)&ff,    g_ff);
    cudaGetSymbolAddress((void**)&pO,    g_pO);
    cudaGetSymbolAddress((void**)&pml,   g_pml);

    cudaFuncSetAttribute(flash_tc, cudaFuncAttributeMaxDynamicSharedMemorySize, FA_SMEM);
    cudaFuncSetAttribute(tg2<0>, cudaFuncAttributeMaxDynamicSharedMemorySize, TG_SMEM);
    cudaFuncSetAttribute(tg2<1>, cudaFuncAttributeMaxDynamicSharedMemorySize, TG_SMEM);
    cudaFuncSetAttribute(tg2<2>, cudaFuncAttributeMaxDynamicSharedMemorySize, TG_SMEM);

    // 1. LN1 -> fp16
    ln_kernel<<<TT, 256>>>(x, ln1s, ln1b, h);
    // 2. weight transposes -> fp16 K-major
    transpose_all<<<12288, dim3(32, 8)>>>(Wq, Wk, Wv, Wo, W1, W2,
                                          wqkvT, woT, w1T, w2T);
    // 3. QKV GEMM (fp16 out)
    tg2<0><<<dim3(3 * DD / 128, TT / 128), 256, TG_SMEM>>>(
        TT, 3 * DD, DD, h, wqkvT, nullptr, nullptr, qkv);
    // 4. flash attention split-K, fp16, double-buffered K/V
    flash_tc<<<dim3(48, HH), 128, FA_SMEM>>>(qkv, att, pO, pml);
    flash_merge<<<dim3(16, HH), 128>>>(pO, pml, att);
    // 5. output proj + bias + residual (fp32 out)
    tg2<1><<<dim3(DD / 128, TT / 128), 256, TG_SMEM>>>(
        TT, DD, DD, att, woT, bo, x, x2);
    // 6. LN2 -> fp16
    ln_kernel<<<TT, 256>>>(x2, ln2s, ln2b, h);
    // 7. FFN1 (relu, fp16 out)
    tg2<2><<<dim3(DFF / 128, TT / 128), 256, TG_SMEM>>>(
        TT, DFF, DD, h, w1T, b1, nullptr, ff);
    // 8. FFN2 (fp32 out)
    tg2<1><<<dim3(DD / 128, TT / 128), 256, TG_SMEM>>>(
        TT, DD, DFF, ff, w2T, b2, x2, out);
}

// round 14
// speedup vs baseline: 2.5707x; 1.0429x over previous
#include <cuda_runtime.h>
#include <cuda_fp16.h>
#include <cstdint>

#define TT 2048
#define DD 1024
#define HH 16
#define HSZ 64
#define DFF 4096

// ---------------- scratch (no allocs allowed) ----------------
__device__ __half g_h[TT * DD];            // LN output (fp16)
__device__ __half g_wqkvT[3 * DD * DD];    // QKV weights, [3D][D] K-major (fp16)
__device__ __half g_WoT[DD * DD];          // Wo^T (fp16)
__device__ __half g_W1T[DD * DFF];         // W1^T (fp16)
__device__ __half g_W2T[DFF * DD];         // W2^T (fp16)
__device__ __half g_qkv[TT * 3 * DD];      // QKV activations (fp16)
__device__ __half g_att[TT * DD];          // attention output (fp16)
__device__ float  g_x2[TT * DD];           // residual after attention (fp32)
__device__ __half g_ff[TT * DFF];          // FFN hidden (fp16)
__device__ float  g_pO[16 * 16 * 2 * 64 * 64];   // split-K partials
__device__ float  g_pml[16 * 16 * 2 * 64 * 2];   // raw (m, l)

// ---------------- helpers ----------------
__device__ __forceinline__ uint32_t smem_u32(const void* p) {
    return (uint32_t)__cvta_generic_to_shared(p);
}
__device__ __forceinline__ uint32_t swz(uint32_t off) {
    return off ^ ((off >> 3) & 0x70);
}
__device__ __forceinline__ void mma_f16(
    float& d0, float& d1, float& d2, float& d3,
    uint32_t a0, uint32_t a1, uint32_t a2, uint32_t a3,
    uint32_t b0, uint32_t b1)
{
    asm volatile(
        "mma.sync.aligned.m16n8k16.row.col.f32.f16.f16.f32 "
        "{%0,%1,%2,%3}, {%4,%5,%6,%7}, {%8,%9}, {%0,%1,%2,%3};\n"
        : "+f"(d0), "+f"(d1), "+f"(d2), "+f"(d3)
        : "r"(a0), "r"(a1), "r"(a2), "r"(a3), "r"(b0), "r"(b1));
}
__device__ __forceinline__ void ldmx4(
    uint32_t& r0, uint32_t& r1, uint32_t& r2, uint32_t& r3, uint32_t addr)
{
    asm volatile("ldmatrix.sync.aligned.m8n8.x4.shared.b16 {%0,%1,%2,%3}, [%4];"
                 : "=r"(r0), "=r"(r1), "=r"(r2), "=r"(r3) : "r"(addr) : "memory");
}
__device__ __forceinline__ void ldmx4t(
    uint32_t& r0, uint32_t& r1, uint32_t& r2, uint32_t& r3, uint32_t addr)
{
    asm volatile("ldmatrix.sync.aligned.m8n8.x4.trans.shared.b16 {%0,%1,%2,%3}, [%4];"
                 : "=r"(r0), "=r"(r1), "=r"(r2), "=r"(r3) : "r"(addr) : "memory");
}
__device__ __forceinline__ void cpasync16(uint32_t saddr, const void* gaddr) {
    asm volatile("cp.async.cg.shared.global [%0], [%1], 16;" :: "r"(saddr), "l"(gaddr));
}
__device__ __forceinline__ uint32_t packh2(float lo, float hi) {
    __half2 h = __floats2half2_rn(lo, hi);
    return *reinterpret_cast<uint32_t*>(&h);
}
#define CP_COMMIT() asm volatile("cp.async.commit_group;" ::: "memory")
#define CP_WAIT(n)  asm volatile("cp.async.wait_group %0;" :: "n"(n) : "memory")

// ---------------- fast exp2 (fma pipe) ----------------
__device__ __forceinline__ float fexp2(float x) {
    x = fmaxf(x, -120.f);
    float k  = __fadd_rn(x, 12582912.f);
    int   sc = __float_as_int(k) << 23;
    float f  = __fsub_rn(x, __fsub_rn(k, 12582912.f));
    float p  = 0.0013333558f;
    p = fmaf(p, f, 0.0096181291f);
    p = fmaf(p, f, 0.0555041087f);
    p = fmaf(p, f, 0.2402265070f);
    p = fmaf(p, f, 0.6931471806f);
    p = fmaf(p, f, 1.0f);
    return __int_as_float(__float_as_int(p) + sc);
}

// ---------------- LayerNorm row (device fn, emits fp16) ----------------
__device__ __forceinline__ void ln_row(
    const float* __restrict__ x, const float* __restrict__ g,
    const float* __restrict__ b, __half* __restrict__ y, int row, int tid)
{
    float4 v = reinterpret_cast<const float4*>(x + (size_t)row * DD)[tid];
    float s  = v.x + v.y + v.z + v.w;
    float ss = v.x * v.x + v.y * v.y + v.z * v.z + v.w * v.w;
    #pragma unroll
    for (int o = 16; o > 0; o >>= 1) {
        s  += __shfl_xor_sync(0xffffffffu, s, o);
        ss += __shfl_xor_sync(0xffffffffu, ss, o);
    }
    __shared__ float sb[8], ssb[8], stats[2];
    int wid = tid >> 5, lane = tid & 31;
    if (lane == 0) { sb[wid] = s; ssb[wid] = ss; }
    __syncthreads();
    if (tid == 0) {
        float a = 0.f, c = 0.f;
        #pragma unroll
        for (int i = 0; i < 8; i++) { a += sb[i]; c += ssb[i]; }
        float mean = a * (1.0f / DD);
        float var  = c * (1.0f / DD) - mean * mean;
        stats[0] = mean;
        stats[1] = rsqrtf(var + 1e-6f);
    }
    __syncthreads();
    float mean = stats[0], rstd = stats[1];
    float4 gg = reinterpret_cast<const float4*>(g)[tid];
    float4 bb = reinterpret_cast<const float4*>(b)[tid];
    union { __half2 h[2]; uint2 u; } pk;
    pk.h[0] = __floats2half2_rn((v.x - mean) * rstd * gg.x + bb.x,
                                (v.y - mean) * rstd * gg.y + bb.y);
    pk.h[1] = __floats2half2_rn((v.z - mean) * rstd * gg.z + bb.z,
                                (v.w - mean) * rstd * gg.w + bb.w);
    reinterpret_cast<uint2*>(y + (size_t)row * DD)[tid] = pk.u;
}

__global__ __launch_bounds__(256) void ln_kernel(
    const float* __restrict__ x, const float* __restrict__ g,
    const float* __restrict__ b, __half* __restrict__ y)
{
    ln_row(x, g, b, y, blockIdx.x, threadIdx.x);
}

// ---------------- prep: weight transposes + LN1 in ONE launch ----------------
// blocks [0,12288): transposes.  [12288, 12288+2048): LN1 rows.
__global__ __launch_bounds__(256) void prep_kernel(
    const float* __restrict__ Wq, const float* __restrict__ Wk,
    const float* __restrict__ Wv, const float* __restrict__ Wo,
    const float* __restrict__ W1, const float* __restrict__ W2,
    __half* __restrict__ wqkvT, __half* __restrict__ woT,
    __half* __restrict__ w1T, __half* __restrict__ w2T,
    const float* __restrict__ x, const float* __restrict__ ln1s,
    const float* __restrict__ ln1b, __half* __restrict__ hout)
{
    const int b = blockIdx.x;
    if (b >= 12288) {
        ln_row(x, ln1s, ln1b, hout, b - 12288, threadIdx.x);
        return;
    }
    __shared__ float t[32][33];
    const float* ip; __half* op;
    int R, C, bx, by;
    if (b < 3072) {
        const int w = b >> 10;
        const int r = b & 1023;
        const int head = r >> 6;
        const int rr = r & 63;
        bx = (rr & 1) * 32;
        by = (rr >> 1) * 32;
        ip = (w == 0 ? Wq : (w == 1 ? Wk : Wv)) + (size_t)head * DD * HSZ;
        op = wqkvT + (size_t)w * DD * DD + (size_t)head * HSZ * DD;
        R = DD; C = HSZ;
    } else if (b < 4096) {
        const int r = b - 3072;
        bx = (r & 31) * 32; by = (r >> 5) * 32;
        ip = Wo; op = woT; R = DD; C = DD;
    } else if (b < 8192) {
        const int r = b - 4096;
        bx = (r & 127) * 32; by = (r >> 7) * 32;
        ip = W1; op = w1T; R = DD; C = DFF;
    } else {
        const int r = b - 8192;
        bx = (r & 31) * 32; by = (r >> 5) * 32;
        ip = W2; op = w2T; R = DFF; C = DD;
    }
    const int x_ = threadIdx.x & 31, y_ = threadIdx.x >> 5;
    #pragma unroll
    for (int j = 0; j < 32; j += 8)
        t[y_ + j][x_] = ip[(size_t)(by + y_ + j) * C + bx + x_];
    __syncthreads();
    #pragma unroll
    for (int j = 0; j < 32; j += 8)
        op[(size_t)(bx + y_ + j) * R + by + x_] = __float2half_rn(t[x_][y_ + j]);
}

// ---------------- fp16 mma.sync GEMM (frozen) ----------------
#define TG_STAGE 32768
#define TG_SMEM  (3 * TG_STAGE)

template <int EPI>
__global__ __launch_bounds__(256, 1) void tg2(
    int M, int N, int K,
    const __half* __restrict__ A, const __half* __restrict__ Bt,
    const float* __restrict__ bias, const float* __restrict__ resid,
    void* __restrict__ Cv)
{
    extern __shared__ float dynsm[];
    const int tid  = threadIdx.x;
    const int warp = tid >> 5, lane = tid & 31;
    const int wm = warp & 1, wn = warp >> 1;
    const int g = lane >> 2, tg = lane & 3;
    const int brow = blockIdx.y, bcol = blockIdx.x;

    const uint32_t sbase = smem_u32(dynsm);
    const int r0 = tid >> 3;
    const int ck = tid & 7;
    const __half* Ab = A  + (size_t)(brow * 128) * K + ck * 8;
    const __half* Bb = Bt + (size_t)(bcol * 128) * K + ck * 8;
    const int KT = K >> 6;

    const int aRow = (lane & 7) + ((lane >> 3) & 1) * 8;
    const int aChk = (lane >> 4);
    const int bRow = (lane & 7) + (lane >> 4) * 8;
    const int bChk = (lane >> 3) & 1;

    float acc[4][4][4];
    #pragma unroll
    for (int mt = 0; mt < 4; mt++)
        #pragma unroll
        for (int nt = 0; nt < 4; nt++)
            #pragma unroll
            for (int i = 0; i < 4; i++) acc[mt][nt][i] = 0.f;

    auto load_stage = [&](int kt, int s) {
        const uint32_t sA = sbase + s * TG_STAGE;
        const uint32_t sB = sA + 16384;
        const int k0 = kt * 64;
        #pragma unroll
        for (int j = 0; j < 4; ++j) {
            const int r = j * 32 + r0;
            const uint32_t off = swz((uint32_t)(r * 128 + ck * 16));
            cpasync16(sA + off, Ab + (size_t)r * K + k0);
            cpasync16(sB + off, Bb + (size_t)r * K + k0);
        }
        CP_COMMIT();
    };

    load_stage(0, 0);
    if (KT > 1) load_stage(1, 1);

    for (int kt = 0; kt < KT; ++kt) {
        if (kt + 1 < KT) CP_WAIT(1); else CP_WAIT(0);
        __syncthreads();
        if (kt + 2 < KT) load_stage(kt + 2, (kt + 2) % 3);

        const uint32_t sA = sbase + (kt % 3) * TG_STAGE;
        const uint32_t sB = sA + 16384;

        #pragma unroll
        for (int ks = 0; ks < 4; ++ks) {
            uint32_t af[4][4];
            #pragma unroll
            for (int mt = 0; mt < 4; ++mt) {
                const int row = wm * 64 + mt * 16 + aRow;
                const uint32_t ad = sA + swz((uint32_t)(row * 128 + ks * 32 + aChk * 16));
                ldmx4(af[mt][0], af[mt][1], af[mt][2], af[mt][3], ad);
            }
            uint32_t bf[4][2];
            #pragma unroll
            for (int np = 0; np < 2; ++np) {
                const int nrow = wn * 32 + np * 16 + bRow;
                const uint32_t bd = sB + swz((uint32_t)(nrow * 128 + ks * 32 + bChk * 16));
                uint32_t t0, t1, t2, t3;
                ldmx4(t0, t1, t2, t3, bd);
                bf[np * 2][0] = t0;     bf[np * 2][1] = t1;
                bf[np * 2 + 1][0] = t2; bf[np * 2 + 1][1] = t3;
            }
            #pragma unroll
            for (int mt = 0; mt < 4; ++mt)
                #pragma unroll
                for (int nt = 0; nt < 4; ++nt)
                    mma_f16(acc[mt][nt][0], acc[mt][nt][1],
                            acc[mt][nt][2], acc[mt][nt][3],
                            af[mt][0], af[mt][1], af[mt][2], af[mt][3],
                            bf[nt][0], bf[nt][1]);
        }
    }

    #pragma unroll
    for (int mt = 0; mt < 4; mt++) {
        const int r0g = brow * 128 + wm * 64 + mt * 16 + g;
        const int r1g = r0g + 8;
        #pragma unroll
        for (int nt = 0; nt < 4; nt++) {
            const int c = bcol * 128 + wn * 32 + nt * 8 + tg * 2;
            float2 o0 = make_float2(acc[mt][nt][0], acc[mt][nt][1]);
            float2 o1 = make_float2(acc[mt][nt][2], acc[mt][nt][3]);
            if constexpr (EPI >= 1) {
                float2 bv = *reinterpret_cast<const float2*>(bias + c);
                o0.x += bv.x; o0.y += bv.y;
                o1.x += bv.x; o1.y += bv.y;
            }
            if constexpr (EPI == 1) {
                float2 rv0 = *reinterpret_cast<const float2*>(resid + (size_t)r0g * N + c);
                float2 rv1 = *reinterpret_cast<const float2*>(resid + (size_t)r1g * N + c);
                o0.x += rv0.x; o0.y += rv0.y;
                o1.x += rv1.x; o1.y += rv1.y;
                float* C = (float*)Cv;
                *reinterpret_cast<float2*>(C + (size_t)r0g * N + c) = o0;
                *reinterpret_cast<float2*>(C + (size_t)r1g * N + c) = o1;
            } else {
                if constexpr (EPI == 2) {
                    o0.x = fmaxf(o0.x, 0.f); o0.y = fmaxf(o0.y, 0.f);
                    o1.x = fmaxf(o1.x, 0.f); o1.y = fmaxf(o1.y, 0.f);
                }
                __half* C = (__half*)Cv;
                __half2 h0 = __floats2half2_rn(o0.x, o0.y);
                __half2 h1 = __floats2half2_rn(o1.x, o1.y);
                *reinterpret_cast<__half2*>(C + (size_t)r0g * N + c) = h0;
                *reinterpret_cast<__half2*>(C + (size_t)r1g * N + c) = h1;
            }
        }
    }
}

// ---------------- flash attention v8 ----------------
// fp16 mma, split-K, K/V double buffer, work-sorted 1D grid,
// diagonal-only masking, raw-domain max with scale fused into exp.
#define FA_SMEM (5 * 64 * 128)    // 40 KB

__global__ __launch_bounds__(128, 4) void flash_tc(
    const __half* __restrict__ qkv, __half* __restrict__ out,
    float* __restrict__ pO, float* __restrict__ pml)
{
    extern __shared__ char fsm[];
    const uint32_t qsb = smem_u32(fsm);
    const int tid  = threadIdx.x;
    const int warp = tid >> 5;
    const int lane = tid & 31;
    const int g    = lane >> 2;
    const int tg   = lane & 3;

    // ---- work-sorted block id -> (h, qb, seg) ----
    const int id = blockIdx.x;     // 0..767
    int qb, seg, h;
    if (id < 256) {                              // 256 heavy seg0 (16 tiles)
        h = id & 15; qb = 16 + (id >> 4); seg = 0;
    } else {                                     // groups of 32, size desc 16..1
        const int id2 = id - 256;
        const int s = 16 - (id2 >> 5);
        const int j = id2 & 31;
        if (j < 16) { h = j;      qb = 15 + s; seg = 1; }   // seg1, size s
        else        { h = j - 16; qb = s - 1;  seg = 0; }   // full block, size s
    }
    const int q0   = qb * 64;
    const int w16  = warp * 16;
    const int kt0  = seg * 16;
    const int kt1  = min(qb + 1, kt0 + 16);
    const bool full = (kt0 == 0) && (kt1 == qb + 1);

    const int aRow = (lane & 7) + ((lane >> 3) & 1) * 8;
    const int aChk = lane >> 4;
    const int bRow = (lane & 7) + (lane >> 4) * 8;
    const int bChk = (lane >> 3) & 1;
    const int vKeyLoc = ((lane >> 3) & 1) * 8 + (lane & 7);
    const int vL7  = lane & 7;
    const int vL16 = lane >> 4;

    const __half* qp = qkv + h * HSZ;
    const __half* kp = qkv + DD + h * HSZ;
    const __half* vp = qkv + 2 * DD + h * HSZ;

    auto load_kv = [&](int kt, int b) {
        const uint32_t kb = qsb + 8192 + b * 16384;
        const uint32_t vb = kb + 8192;
        #pragma unroll
        for (int j = 0; j < 4; ++j) {
            int idx = j * 128 + tid;
            int r = idx >> 3, ck = idx & 7;
            size_t gi = (size_t)(kt * 64 + r) * (3 * DD) + ck * 8;
            uint32_t off = swz((uint32_t)(r * 128 + ck * 16));
            cpasync16(kb + off, kp + gi);
            cpasync16(vb + off, vp + gi);
        }
        CP_COMMIT();
    };

    {   // Q tile
        #pragma unroll
        for (int j = 0; j < 4; ++j) {
            int idx = j * 128 + tid;
            int r = idx >> 3, ck = idx & 7;
            cpasync16(qsb + swz((uint32_t)(r * 128 + ck * 16)),
                      qp + (size_t)(q0 + r) * (3 * DD) + ck * 8);
        }
        CP_COMMIT();
    }
    load_kv(kt0, kt0 & 1);

    float O[8][4];
    #pragma unroll
    for (int nt = 0; nt < 8; nt++)
        #pragma unroll
        for (int i = 0; i < 4; i++) O[nt][i] = 0.f;
    float m0 = -1e30f, m1 = -1e30f, l0 = 0.f, l1 = 0.f;   // raw-domain max

    const int row0 = q0 + w16 + g;
    const int row1 = row0 + 8;
    const float SC = 0.18033688011112042f;   // (1/8) * log2(e)

    for (int kt = kt0; kt < kt1; ++kt) {
        const bool has_next = (kt + 1 < kt1);
        if (has_next) load_kv(kt + 1, (kt + 1) & 1);
        if (has_next) CP_WAIT(1); else CP_WAIT(0);
        __syncthreads();

        const uint32_t ksb = qsb + 8192 + (kt & 1) * 16384;
        const uint32_t vsb = ksb + 8192;

        // ---- S = Q K^T ----
        float s[8][4];
        #pragma unroll
        for (int nt = 0; nt < 8; nt++)
            #pragma unroll
            for (int i = 0; i < 4; i++) s[nt][i] = 0.f;

        #pragma unroll
        for (int kk = 0; kk < 4; ++kk) {
            uint32_t a0, a1, a2, a3;
            ldmx4(a0, a1, a2, a3,
                  qsb + swz((uint32_t)((w16 + aRow) * 128 + kk * 32 + aChk * 16)));
            uint32_t bf[8][2];
            #pragma unroll
            for (int n16 = 0; n16 < 4; ++n16) {
                uint32_t t0, t1, t2, t3;
                ldmx4(t0, t1, t2, t3,
                      ksb + swz((uint32_t)((n16 * 16 + bRow) * 128 + kk * 32 + bChk * 16)));
                bf[n16 * 2][0] = t0;     bf[n16 * 2][1] = t1;
                bf[n16 * 2 + 1][0] = t2; bf[n16 * 2 + 1][1] = t3;
            }
            #pragma unroll
            for (int nt = 0; nt < 8; ++nt)
                mma_f16(s[nt][0], s[nt][1], s[nt][2], s[nt][3],
                        a0, a1, a2, a3, bf[nt][0], bf[nt][1]);
        }

        // ---- causal mask: ONLY the diagonal tile has masked elements ----
        if (kt == qb) {
            #pragma unroll
            for (int nt = 0; nt < 8; ++nt) {
                int c0 = kt * 64 + nt * 8 + 2 * tg;
                if (c0     > row0) s[nt][0] = -1e30f;
                if (c0 + 1 > row0) s[nt][1] = -1e30f;
                if (c0     > row1) s[nt][2] = -1e30f;
                if (c0 + 1 > row1) s[nt][3] = -1e30f;
            }
        }

        // ---- raw-domain row max ----
        float mb0 = -1e30f, mb1 = -1e30f;
        #pragma unroll
        for (int nt = 0; nt < 8; ++nt) {
            mb0 = fmaxf(mb0, fmaxf(s[nt][0], s[nt][1]));
            mb1 = fmaxf(mb1, fmaxf(s[nt][2], s[nt][3]));
        }
        mb0 = fmaxf(mb0, __shfl_xor_sync(0xffffffffu, mb0, 1));
        mb0 = fmaxf(mb0, __shfl_xor_sync(0xffffffffu, mb0, 2));
        mb1 = fmaxf(mb1, __shfl_xor_sync(0xffffffffu, mb1, 1));
        mb1 = fmaxf(mb1, __shfl_xor_sync(0xffffffffu, mb1, 2));

        float mn0 = fmaxf(m0, mb0), mn1 = fmaxf(m1, mb1);
        float al0 = fexp2((m0 - mn0) * SC), al1 = fexp2((m1 - mn1) * SC);
        m0 = mn0; m1 = mn1;
        const float ms0 = mn0 * SC, ms1 = mn1 * SC;

        float rs0 = 0.f, rs1 = 0.f;
        #pragma unroll
        for (int nt = 0; nt < 8; ++nt) {
            float p0 = fexp2(fmaf(s[nt][0], SC, -ms0));
            float p1 = fexp2(fmaf(s[nt][1], SC, -ms0));
            float p2 = fexp2(fmaf(s[nt][2], SC, -ms1));
            float p3 = fexp2(fmaf(s[nt][3], SC, -ms1));
            rs0 += p0 + p1; rs1 += p2 + p3;
            s[nt][0] = p0; s[nt][1] = p1; s[nt][2] = p2; s[nt][3] = p3;
        }
        rs0 += __shfl_xor_sync(0xffffffffu, rs0, 1);
        rs0 += __shfl_xor_sync(0xffffffffu, rs0, 2);
        rs1 += __shfl_xor_sync(0xffffffffu, rs1, 1);
        rs1 += __shfl_xor_sync(0xffffffffu, rs1, 2);
        l0 = l0 * al0 + rs0;
        l1 = l1 * al1 + rs1;

        #pragma unroll
        for (int nt = 0; nt < 8; ++nt) {
            O[nt][0] *= al0; O[nt][1] *= al0;
            O[nt][2] *= al1; O[nt][3] *= al1;
        }

        // ---- O += P V ----
        #pragma unroll
        for (int kk = 0; kk < 4; ++kk) {
            uint32_t a0 = packh2(s[2*kk][0],   s[2*kk][1]);
            uint32_t a1 = packh2(s[2*kk][2],   s[2*kk][3]);
            uint32_t a2 = packh2(s[2*kk+1][0], s[2*kk+1][1]);
            uint32_t a3 = packh2(s[2*kk+1][2], s[2*kk+1][3]);
            #pragma unroll
            for (int i = 0; i < 4; ++i) {
                const int key = 16 * kk + vKeyLoc;
                const uint32_t dblk = (uint32_t)(((2 * i + vL16) ^ vL7) * 16);
                uint32_t t0, t1, t2, t3;
                ldmx4t(t0, t1, t2, t3, vsb + (uint32_t)(key * 128) + dblk);
                mma_f16(O[2*i][0], O[2*i][1], O[2*i][2], O[2*i][3],
                        a0, a1, a2, a3, t0, t1);
                mma_f16(O[2*i+1][0], O[2*i+1][1], O[2*i+1][2], O[2*i+1][3],
                        a0, a1, a2, a3, t2, t3);
            }
        }
        if (has_next) __syncthreads();
    }

    if (full) {
        float inv0 = 1.0f / l0, inv1 = 1.0f / l1;
        #pragma unroll
        for (int nt = 0; nt < 8; ++nt) {
            int c = h * HSZ + nt * 8 + 2 * tg;
            __half2 o0 = __floats2half2_rn(O[nt][0] * inv0, O[nt][1] * inv0);
            __half2 o1 = __floats2half2_rn(O[nt][2] * inv1, O[nt][3] * inv1);
            *reinterpret_cast<__half2*>(out + (size_t)row0 * DD + c) = o0;
            *reinterpret_cast<__half2*>(out + (size_t)row1 * DD + c) = o1;
        }
    } else {
        const int p = (h * 16 + (qb - 16)) * 2 + seg;
        float* pb = pO + (size_t)p * 4096;
        const int lr0 = w16 + g, lr1 = lr0 + 8;
        #pragma unroll
        for (int nt = 0; nt < 8; ++nt) {
            int c = nt * 8 + 2 * tg;
            *reinterpret_cast<float2*>(pb + lr0 * 64 + c) = make_float2(O[nt][0], O[nt][1]);
            *reinterpret_cast<float2*>(pb + lr1 * 64 + c) = make_float2(O[nt][2], O[nt][3]);
        }
        if (tg == 0) {
            float* mlb = pml + (size_t)p * 128;
            mlb[lr0 * 2]     = m0;   // raw max
            mlb[lr0 * 2 + 1] = l0;
            mlb[lr1 * 2]     = m1;
            mlb[lr1 * 2 + 1] = l1;
        }
    }
}

// ---------------- split-K merge (raw m; scale applied here) ----------------
__global__ __launch_bounds__(128) void flash_merge(
    const float* __restrict__ pO, const float* __restrict__ pml,
    __half* __restrict__ out)
{
    __shared__ float w0s[64], w1s[64];
    const int qb16 = blockIdx.x;
    const int h    = blockIdx.y;
    const int tid  = threadIdx.x;
    const int p0 = (h * 16 + qb16) * 2;
    const int p1 = p0 + 1;
    const float SC = 0.18033688011112042f;

    if (tid < 64) {
        float m0 = pml[(size_t)p0 * 128 + tid * 2];
        float l0 = pml[(size_t)p0 * 128 + tid * 2 + 1];
        float m1 = pml[(size_t)p1 * 128 + tid * 2];
        float l1 = pml[(size_t)p1 * 128 + tid * 2 + 1];
        float M  = fmaxf(m0, m1);
        float w0 = fexp2((m0 - M) * SC), w1 = fexp2((m1 - M) * SC);
        float inv = 1.0f / (w0 * l0 + w1 * l1);
        w0s[tid] = w0 * inv;
        w1s[tid] = w1 * inv;
    }
    __syncthreads();

    const float* b0 = pO + (size_t)p0 * 4096;
    const float* b1 = pO + (size_t)p1 * 4096;
    const int q0 = (16 + qb16) * 64;
    #pragma unroll
    for (int i = 0; i < 8; ++i) {
        int idx = (i * 128 + tid) * 4;
        int r = idx >> 6, c = idx & 63;
        float4 v0 = *reinterpret_cast<const float4*>(b0 + r * 64 + c);
        float4 v1 = *reinterpret_cast<const float4*>(b1 + r * 64 + c);
        float w0 = w0s[r], w1 = w1s[r];
        union { __half2 h[2]; uint2 u; } pk;
        pk.h[0] = __floats2half2_rn(w0 * v0.x + w1 * v1.x, w0 * v0.y + w1 * v1.y);
        pk.h[1] = __floats2half2_rn(w0 * v0.z + w1 * v1.z, w0 * v0.w + w1 * v1.w);
        *reinterpret_cast<uint2*>(out + (size_t)(q0 + r) * DD + h * HSZ + c) = pk.u;
    }
}

// ---------------- launch ----------------
extern "C" void kernel_launch(void* const* d_in, const int* in_sizes, int n_in,
                              void* d_out, int out_size)
{
    const float* x    = (const float*)d_in[0];
    const float* Wq   = (const float*)d_in[1];
    const float* Wk   = (const float*)d_in[2];
    const float* Wv   = (const float*)d_in[3];
    const float* Wo   = (const float*)d_in[4];
    const float* bo   = (const float*)d_in[5];
    const float* W1   = (const float*)d_in[6];
    const float* b1   = (const float*)d_in[7];
    const float* W2   = (const float*)d_in[8];
    const float* b2   = (const float*)d_in[9];
    const float* ln1s = (const float*)d_in[10];
    const float* ln1b = (const float*)d_in[11];
    const float* ln2s = (const float*)d_in[12];
    const float* ln2b = (const float*)d_in[13];
    float* out = (float*)d_out;

    __half *h, *wqkvT, *woT, *w1T, *w2T, *att, *ff, *qkv;
    float *x2, *pO, *pml;
    cudaGetSymbolAddress((void**)&h,     g_h);
    cudaGetSymbolAddress((void**)&wqkvT, g_wqkvT);
    cudaGetSymbolAddress((void**)&woT,   g_WoT);
    cudaGetSymbolAddress((void**)&w1T,   g_W1T);
    cudaGetSymbolAddress((void**)&w2T,   g_W2T);
    cudaGetSymbolAddress((void**)&qkv,   g_qkv);
    cudaGetSymbolAddress((void**)&att,   g_att);
    cudaGetSymbolAddress((void**)&x2,    g_x2);
    cudaGetSymbolAddress((void**)&ff,    g_ff);
    cudaGetSymbolAddress((void**)&pO,    g_pO);
    cudaGetSymbolAddress((void**)&pml,   g_pml);

    cudaFuncSetAttribute(flash_tc, cudaFuncAttributeMaxDynamicSharedMemorySize, FA_SMEM);
    cudaFuncSetAttribute(tg2<0>, cudaFuncAttributeMaxDynamicSharedMemorySize, TG_SMEM);
    cudaFuncSetAttribute(tg2<1>, cudaFuncAttributeMaxDynamicSharedMemorySize, TG_SMEM);
    cudaFuncSetAttribute(tg2<2>, cudaFuncAttributeMaxDynamicSharedMemorySize, TG_SMEM);

    // 1. prep: weight transposes + LN1 (one launch)
    prep_kernel<<<12288 + 2048, 256>>>(Wq, Wk, Wv, Wo, W1, W2,
                                       wqkvT, woT, w1T, w2T,
                                       x, ln1s, ln1b, h);
    // 2. QKV GEMM (fp16 out)
    tg2<0><<<dim3(3 * DD / 128, TT / 128), 256, TG_SMEM>>>(
        TT, 3 * DD, DD, h, wqkvT, nullptr, nullptr, qkv);
    // 3. flash attention split-K, work-sorted 1D grid
    flash_tc<<<768, 128, FA_SMEM>>>(qkv, att, pO, pml);
    flash_merge<<<dim3(16, HH), 128>>>(pO, pml, att);
    // 4. output proj + bias + residual (fp32 out)
    tg2<1><<<dim3(DD / 128, TT / 128), 256, TG_SMEM>>>(
        TT, DD, DD, att, woT, bo, x, x2);
    // 5. LN2 -> fp16
    ln_kernel<<<TT, 256>>>(x2, ln2s, ln2b, h);
    // 6. FFN1 (relu, fp16 out)
    tg2<2><<<dim3(DFF / 128, TT / 128), 256, TG_SMEM>>>(
        TT, DFF, DD, h, w1T, b1, nullptr, ff);
    // 7. FFN2 (fp32 out)
    tg2<1><<<dim3(DD / 128, TT / 128), 256, TG_SMEM>>>(
        TT, DD, DFF, ff, w2T, b2, x2, out);
}

// round 15
// speedup vs baseline: 2.5717x; 1.0004x over previous
#include <cuda_runtime.h>
#include <cuda_fp16.h>
#include <cstdint>

#define TT 2048
#define DD 1024
#define HH 16
#define HSZ 64
#define DFF 4096

// ---------------- scratch (no allocs allowed) ----------------
__device__ __half g_h[TT * DD];            // LN output (fp16)
__device__ __half g_wqkvT[3 * DD * DD];    // QKV weights, [3D][D] K-major (fp16)
__device__ __half g_WoT[DD * DD];          // Wo^T (fp16)
__device__ __half g_W1T[DD * DFF];         // W1^T (fp16)
__device__ __half g_W2T[DFF * DD];         // W2^T (fp16)
__device__ __half g_qkv[TT * 3 * DD];      // QKV activations (fp16)
__device__ __half g_att[TT * DD];          // attention output (fp16)
__device__ float  g_x2[TT * DD];           // residual after attention (fp32)
__device__ __half g_ff[TT * DFF];          // FFN hidden (fp16)
__device__ float  g_pO[16 * 16 * 2 * 64 * 64];   // split-K partials
__device__ float  g_pml[16 * 16 * 2 * 64 * 2];   // raw (m, l)

// ---------------- helpers ----------------
__device__ __forceinline__ uint32_t smem_u32(const void* p) {
    return (uint32_t)__cvta_generic_to_shared(p);
}
__device__ __forceinline__ uint32_t swz(uint32_t off) {
    return off ^ ((off >> 3) & 0x70);
}
__device__ __forceinline__ void mma_f16(
    float& d0, float& d1, float& d2, float& d3,
    uint32_t a0, uint32_t a1, uint32_t a2, uint32_t a3,
    uint32_t b0, uint32_t b1)
{
    asm volatile(
        "mma.sync.aligned.m16n8k16.row.col.f32.f16.f16.f32 "
        "{%0,%1,%2,%3}, {%4,%5,%6,%7}, {%8,%9}, {%0,%1,%2,%3};\n"
        : "+f"(d0), "+f"(d1), "+f"(d2), "+f"(d3)
        : "r"(a0), "r"(a1), "r"(a2), "r"(a3), "r"(b0), "r"(b1));
}
__device__ __forceinline__ void ldmx4(
    uint32_t& r0, uint32_t& r1, uint32_t& r2, uint32_t& r3, uint32_t addr)
{
    asm volatile("ldmatrix.sync.aligned.m8n8.x4.shared.b16 {%0,%1,%2,%3}, [%4];"
                 : "=r"(r0), "=r"(r1), "=r"(r2), "=r"(r3) : "r"(addr) : "memory");
}
__device__ __forceinline__ void ldmx4t(
    uint32_t& r0, uint32_t& r1, uint32_t& r2, uint32_t& r3, uint32_t addr)
{
    asm volatile("ldmatrix.sync.aligned.m8n8.x4.trans.shared.b16 {%0,%1,%2,%3}, [%4];"
                 : "=r"(r0), "=r"(r1), "=r"(r2), "=r"(r3) : "r"(addr) : "memory");
}
__device__ __forceinline__ void cpasync16(uint32_t saddr, const void* gaddr) {
    asm volatile("cp.async.cg.shared.global [%0], [%1], 16;" :: "r"(saddr), "l"(gaddr));
}
__device__ __forceinline__ uint32_t packh2(float lo, float hi) {
    __half2 h = __floats2half2_rn(lo, hi);
    return *reinterpret_cast<uint32_t*>(&h);
}
#define CP_COMMIT() asm volatile("cp.async.commit_group;" ::: "memory")
#define CP_WAIT(n)  asm volatile("cp.async.wait_group %0;" :: "n"(n) : "memory")

// ---------------- fast exp2 (fma pipe) ----------------
__device__ __forceinline__ float fexp2(float x) {
    x = fmaxf(x, -120.f);
    float k  = __fadd_rn(x, 12582912.f);
    int   sc = __float_as_int(k) << 23;
    float f  = __fsub_rn(x, __fsub_rn(k, 12582912.f));
    float p  = 0.0013333558f;
    p = fmaf(p, f, 0.0096181291f);
    p = fmaf(p, f, 0.0555041087f);
    p = fmaf(p, f, 0.2402265070f);
    p = fmaf(p, f, 0.6931471806f);
    p = fmaf(p, f, 1.0f);
    return __int_as_float(__float_as_int(p) + sc);
}

// ---------------- LayerNorm row (device fn, emits fp16) ----------------
__device__ __forceinline__ void ln_row(
    const float* __restrict__ x, const float* __restrict__ g,
    const float* __restrict__ b, __half* __restrict__ y, int row, int tid)
{
    float4 v = reinterpret_cast<const float4*>(x + (size_t)row * DD)[tid];
    float s  = v.x + v.y + v.z + v.w;
    float ss = v.x * v.x + v.y * v.y + v.z * v.z + v.w * v.w;
    #pragma unroll
    for (int o = 16; o > 0; o >>= 1) {
        s  += __shfl_xor_sync(0xffffffffu, s, o);
        ss += __shfl_xor_sync(0xffffffffu, ss, o);
    }
    __shared__ float sb[8], ssb[8], stats[2];
    int wid = tid >> 5, lane = tid & 31;
    if (lane == 0) { sb[wid] = s; ssb[wid] = ss; }
    __syncthreads();
    if (tid == 0) {
        float a = 0.f, c = 0.f;
        #pragma unroll
        for (int i = 0; i < 8; i++) { a += sb[i]; c += ssb[i]; }
        float mean = a * (1.0f / DD);
        float var  = c * (1.0f / DD) - mean * mean;
        stats[0] = mean;
        stats[1] = rsqrtf(var + 1e-6f);
    }
    __syncthreads();
    float mean = stats[0], rstd = stats[1];
    float4 gg = reinterpret_cast<const float4*>(g)[tid];
    float4 bb = reinterpret_cast<const float4*>(b)[tid];
    union { __half2 h[2]; uint2 u; } pk;
    pk.h[0] = __floats2half2_rn((v.x - mean) * rstd * gg.x + bb.x,
                                (v.y - mean) * rstd * gg.y + bb.y);
    pk.h[1] = __floats2half2_rn((v.z - mean) * rstd * gg.z + bb.z,
                                (v.w - mean) * rstd * gg.w + bb.w);
    reinterpret_cast<uint2*>(y + (size_t)row * DD)[tid] = pk.u;
}

__global__ __launch_bounds__(256) void ln_kernel(
    const float* __restrict__ x, const float* __restrict__ g,
    const float* __restrict__ b, __half* __restrict__ y)
{
    ln_row(x, g, b, y, blockIdx.x, threadIdx.x);
}

// ---------------- prep: weight transposes + LN1 in ONE launch ----------------
// blocks [0,12288): transposes.  [12288, 12288+2048): LN1 rows.
__global__ __launch_bounds__(256) void prep_kernel(
    const float* __restrict__ Wq, const float* __restrict__ Wk,
    const float* __restrict__ Wv, const float* __restrict__ Wo,
    const float* __restrict__ W1, const float* __restrict__ W2,
    __half* __restrict__ wqkvT, __half* __restrict__ woT,
    __half* __restrict__ w1T, __half* __restrict__ w2T,
    const float* __restrict__ x, const float* __restrict__ ln1s,
    const float* __restrict__ ln1b, __half* __restrict__ hout)
{
    const int b = blockIdx.x;
    if (b >= 12288) {
        ln_row(x, ln1s, ln1b, hout, b - 12288, threadIdx.x);
        return;
    }
    __shared__ float t[32][33];
    const float* ip; __half* op;
    int R, C, bx, by;
    if (b < 3072) {
        const int w = b >> 10;
        const int r = b & 1023;
        const int head = r >> 6;
        const int rr = r & 63;
        bx = (rr & 1) * 32;
        by = (rr >> 1) * 32;
        ip = (w == 0 ? Wq : (w == 1 ? Wk : Wv)) + (size_t)head * DD * HSZ;
        op = wqkvT + (size_t)w * DD * DD + (size_t)head * HSZ * DD;
        R = DD; C = HSZ;
    } else if (b < 4096) {
        const int r = b - 3072;
        bx = (r & 31) * 32; by = (r >> 5) * 32;
        ip = Wo; op = woT; R = DD; C = DD;
    } else if (b < 8192) {
        const int r = b - 4096;
        bx = (r & 127) * 32; by = (r >> 7) * 32;
        ip = W1; op = w1T; R = DD; C = DFF;
    } else {
        const int r = b - 8192;
        bx = (r & 31) * 32; by = (r >> 5) * 32;
        ip = W2; op = w2T; R = DFF; C = DD;
    }
    const int x_ = threadIdx.x & 31, y_ = threadIdx.x >> 5;
    #pragma unroll
    for (int j = 0; j < 32; j += 8)
        t[y_ + j][x_] = ip[(size_t)(by + y_ + j) * C + bx + x_];
    __syncthreads();
    #pragma unroll
    for (int j = 0; j < 32; j += 8)
        op[(size_t)(bx + y_ + j) * R + by + x_] = __float2half_rn(t[x_][y_ + j]);
}

// ---------------- fp16 mma.sync GEMM (frozen) ----------------
#define TG_STAGE 32768
#define TG_SMEM  (3 * TG_STAGE)

template <int EPI>
__global__ __launch_bounds__(256, 1) void tg2(
    int M, int N, int K,
    const __half* __restrict__ A, const __half* __restrict__ Bt,
    const float* __restrict__ bias, const float* __restrict__ resid,
    void* __restrict__ Cv)
{
    extern __shared__ float dynsm[];
    const int tid  = threadIdx.x;
    const int warp = tid >> 5, lane = tid & 31;
    const int wm = warp & 1, wn = warp >> 1;
    const int g = lane >> 2, tg = lane & 3;
    const int brow = blockIdx.y, bcol = blockIdx.x;

    const uint32_t sbase = smem_u32(dynsm);
    const int r0 = tid >> 3;
    const int ck = tid & 7;
    const __half* Ab = A  + (size_t)(brow * 128) * K + ck * 8;
    const __half* Bb = Bt + (size_t)(bcol * 128) * K + ck * 8;
    const int KT = K >> 6;

    const int aRow = (lane & 7) + ((lane >> 3) & 1) * 8;
    const int aChk = (lane >> 4);
    const int bRow = (lane & 7) + (lane >> 4) * 8;
    const int bChk = (lane >> 3) & 1;

    float acc[4][4][4];
    #pragma unroll
    for (int mt = 0; mt < 4; mt++)
        #pragma unroll
        for (int nt = 0; nt < 4; nt++)
            #pragma unroll
            for (int i = 0; i < 4; i++) acc[mt][nt][i] = 0.f;

    auto load_stage = [&](int kt, int s) {
        const uint32_t sA = sbase + s * TG_STAGE;
        const uint32_t sB = sA + 16384;
        const int k0 = kt * 64;
        #pragma unroll
        for (int j = 0; j < 4; ++j) {
            const int r = j * 32 + r0;
            const uint32_t off = swz((uint32_t)(r * 128 + ck * 16));
            cpasync16(sA + off, Ab + (size_t)r * K + k0);
            cpasync16(sB + off, Bb + (size_t)r * K + k0);
        }
        CP_COMMIT();
    };

    load_stage(0, 0);
    if (KT > 1) load_stage(1, 1);

    for (int kt = 0; kt < KT; ++kt) {
        if (kt + 1 < KT) CP_WAIT(1); else CP_WAIT(0);
        __syncthreads();
        if (kt + 2 < KT) load_stage(kt + 2, (kt + 2) % 3);

        const uint32_t sA = sbase + (kt % 3) * TG_STAGE;
        const uint32_t sB = sA + 16384;

        #pragma unroll
        for (int ks = 0; ks < 4; ++ks) {
            uint32_t af[4][4];
            #pragma unroll
            for (int mt = 0; mt < 4; ++mt) {
                const int row = wm * 64 + mt * 16 + aRow;
                const uint32_t ad = sA + swz((uint32_t)(row * 128 + ks * 32 + aChk * 16));
                ldmx4(af[mt][0], af[mt][1], af[mt][2], af[mt][3], ad);
            }
            uint32_t bf[4][2];
            #pragma unroll
            for (int np = 0; np < 2; ++np) {
                const int nrow = wn * 32 + np * 16 + bRow;
                const uint32_t bd = sB + swz((uint32_t)(nrow * 128 + ks * 32 + bChk * 16));
                uint32_t t0, t1, t2, t3;
                ldmx4(t0, t1, t2, t3, bd);
                bf[np * 2][0] = t0;     bf[np * 2][1] = t1;
                bf[np * 2 + 1][0] = t2; bf[np * 2 + 1][1] = t3;
            }
            #pragma unroll
            for (int mt = 0; mt < 4; ++mt)
                #pragma unroll
                for (int nt = 0; nt < 4; ++nt)
                    mma_f16(acc[mt][nt][0], acc[mt][nt][1],
                            acc[mt][nt][2], acc[mt][nt][3],
                            af[mt][0], af[mt][1], af[mt][2], af[mt][3],
                            bf[nt][0], bf[nt][1]);
        }
    }

    #pragma unroll
    for (int mt = 0; mt < 4; mt++) {
        const int r0g = brow * 128 + wm * 64 + mt * 16 + g;
        const int r1g = r0g + 8;
        #pragma unroll
        for (int nt = 0; nt < 4; nt++) {
            const int c = bcol * 128 + wn * 32 + nt * 8 + tg * 2;
            float2 o0 = make_float2(acc[mt][nt][0], acc[mt][nt][1]);
            float2 o1 = make_float2(acc[mt][nt][2], acc[mt][nt][3]);
            if constexpr (EPI >= 1) {
                float2 bv = *reinterpret_cast<const float2*>(bias + c);
                o0.x += bv.x; o0.y += bv.y;
                o1.x += bv.x; o1.y += bv.y;
            }
            if constexpr (EPI == 1) {
                float2 rv0 = *reinterpret_cast<const float2*>(resid + (size_t)r0g * N + c);
                float2 rv1 = *reinterpret_cast<const float2*>(resid + (size_t)r1g * N + c);
                o0.x += rv0.x; o0.y += rv0.y;
                o1.x += rv1.x; o1.y += rv1.y;
                float* C = (float*)Cv;
                *reinterpret_cast<float2*>(C + (size_t)r0g * N + c) = o0;
                *reinterpret_cast<float2*>(C + (size_t)r1g * N + c) = o1;
            } else {
                if constexpr (EPI == 2) {
                    o0.x = fmaxf(o0.x, 0.f); o0.y = fmaxf(o0.y, 0.f);
                    o1.x = fmaxf(o1.x, 0.f); o1.y = fmaxf(o1.y, 0.f);
                }
                __half* C = (__half*)Cv;
                __half2 h0 = __floats2half2_rn(o0.x, o0.y);
                __half2 h1 = __floats2half2_rn(o1.x, o1.y);
                *reinterpret_cast<__half2*>(C + (size_t)r0g * N + c) = h0;
                *reinterpret_cast<__half2*>(C + (size_t)r1g * N + c) = h1;
            }
        }
    }
}

// ---------------- flash attention v8 ----------------
// fp16 mma, split-K, K/V double buffer, work-sorted 1D grid,
// diagonal-only masking, raw-domain max with scale fused into exp.
#define FA_SMEM (5 * 64 * 128)    // 40 KB

__global__ __launch_bounds__(128, 4) void flash_tc(
    const __half* __restrict__ qkv, __half* __restrict__ out,
    float* __restrict__ pO, float* __restrict__ pml)
{
    extern __shared__ char fsm[];
    const uint32_t qsb = smem_u32(fsm);
    const int tid  = threadIdx.x;
    const int warp = tid >> 5;
    const int lane = tid & 31;
    const int g    = lane >> 2;
    const int tg   = lane & 3;

    // ---- work-sorted block id -> (h, qb, seg) ----
    const int id = blockIdx.x;     // 0..767
    int qb, seg, h;
    if (id < 256) {                              // 256 heavy seg0 (16 tiles)
        h = id & 15; qb = 16 + (id >> 4); seg = 0;
    } else {                                     // groups of 32, size desc 16..1
        const int id2 = id - 256;
        const int s = 16 - (id2 >> 5);
        const int j = id2 & 31;
        if (j < 16) { h = j;      qb = 15 + s; seg = 1; }   // seg1, size s
        else        { h = j - 16; qb = s - 1;  seg = 0; }   // full block, size s
    }
    const int q0   = qb * 64;
    const int w16  = warp * 16;
    const int kt0  = seg * 16;
    const int kt1  = min(qb + 1, kt0 + 16);
    const bool full = (kt0 == 0) && (kt1 == qb + 1);

    const int aRow = (lane & 7) + ((lane >> 3) & 1) * 8;
    const int aChk = lane >> 4;
    const int bRow = (lane & 7) + (lane >> 4) * 8;
    const int bChk = (lane >> 3) & 1;
    const int vKeyLoc = ((lane >> 3) & 1) * 8 + (lane & 7);
    const int vL7  = lane & 7;
    const int vL16 = lane >> 4;

    const __half* qp = qkv + h * HSZ;
    const __half* kp = qkv + DD + h * HSZ;
    const __half* vp = qkv + 2 * DD + h * HSZ;

    auto load_kv = [&](int kt, int b) {
        const uint32_t kb = qsb + 8192 + b * 16384;
        const uint32_t vb = kb + 8192;
        #pragma unroll
        for (int j = 0; j < 4; ++j) {
            int idx = j * 128 + tid;
            int r = idx >> 3, ck = idx & 7;
            size_t gi = (size_t)(kt * 64 + r) * (3 * DD) + ck * 8;
            uint32_t off = swz((uint32_t)(r * 128 + ck * 16));
            cpasync16(kb + off, kp + gi);
            cpasync16(vb + off, vp + gi);
        }
        CP_COMMIT();
    };

    {   // Q tile
        #pragma unroll
        for (int j = 0; j < 4; ++j) {
            int idx = j * 128 + tid;
            int r = idx >> 3, ck = idx & 7;
            cpasync16(qsb + swz((uint32_t)(r * 128 + ck * 16)),
                      qp + (size_t)(q0 + r) * (3 * DD) + ck * 8);
        }
        CP_COMMIT();
    }
    load_kv(kt0, kt0 & 1);

    float O[8][4];
    #pragma unroll
    for (int nt = 0; nt < 8; nt++)
        #pragma unroll
        for (int i = 0; i < 4; i++) O[nt][i] = 0.f;
    float m0 = -1e30f, m1 = -1e30f, l0 = 0.f, l1 = 0.f;   // raw-domain max

    const int row0 = q0 + w16 + g;
    const int row1 = row0 + 8;
    const float SC = 0.18033688011112042f;   // (1/8) * log2(e)

    for (int kt = kt0; kt < kt1; ++kt) {
        const bool has_next = (kt + 1 < kt1);
        if (has_next) load_kv(kt + 1, (kt + 1) & 1);
        if (has_next) CP_WAIT(1); else CP_WAIT(0);
        __syncthreads();

        const uint32_t ksb = qsb + 8192 + (kt & 1) * 16384;
        const uint32_t vsb = ksb + 8192;

        // ---- S = Q K^T ----
        float s[8][4];
        #pragma unroll
        for (int nt = 0; nt < 8; nt++)
            #pragma unroll
            for (int i = 0; i < 4; i++) s[nt][i] = 0.f;

        #pragma unroll
        for (int kk = 0; kk < 4; ++kk) {
            uint32_t a0, a1, a2, a3;
            ldmx4(a0, a1, a2, a3,
                  qsb + swz((uint32_t)((w16 + aRow) * 128 + kk * 32 + aChk * 16)));
            uint32_t bf[8][2];
            #pragma unroll
            for (int n16 = 0; n16 < 4; ++n16) {
                uint32_t t0, t1, t2, t3;
                ldmx4(t0, t1, t2, t3,
                      ksb + swz((uint32_t)((n16 * 16 + bRow) * 128 + kk * 32 + bChk * 16)));
                bf[n16 * 2][0] = t0;     bf[n16 * 2][1] = t1;
                bf[n16 * 2 + 1][0] = t2; bf[n16 * 2 + 1][1] = t3;
            }
            #pragma unroll
            for (int nt = 0; nt < 8; ++nt)
                mma_f16(s[nt][0], s[nt][1], s[nt][2], s[nt][3],
                        a0, a1, a2, a3, bf[nt][0], bf[nt][1]);
        }

        // ---- causal mask: ONLY the diagonal tile has masked elements ----
        if (kt == qb) {
            #pragma unroll
            for (int nt = 0; nt < 8; ++nt) {
                int c0 = kt * 64 + nt * 8 + 2 * tg;
                if (c0     > row0) s[nt][0] = -1e30f;
                if (c0 + 1 > row0) s[nt][1] = -1e30f;
                if (c0     > row1) s[nt][2] = -1e30f;
                if (c0 + 1 > row1) s[nt][3] = -1e30f;
            }
        }

        // ---- raw-domain row max ----
        float mb0 = -1e30f, mb1 = -1e30f;
        #pragma unroll
        for (int nt = 0; nt < 8; ++nt) {
            mb0 = fmaxf(mb0, fmaxf(s[nt][0], s[nt][1]));
            mb1 = fmaxf(mb1, fmaxf(s[nt][2], s[nt][3]));
        }
        mb0 = fmaxf(mb0, __shfl_xor_sync(0xffffffffu, mb0, 1));
        mb0 = fmaxf(mb0, __shfl_xor_sync(0xffffffffu, mb0, 2));
        mb1 = fmaxf(mb1, __shfl_xor_sync(0xffffffffu, mb1, 1));
        mb1 = fmaxf(mb1, __shfl_xor_sync(0xffffffffu, mb1, 2));

        float mn0 = fmaxf(m0, mb0), mn1 = fmaxf(m1, mb1);
        float al0 = fexp2((m0 - mn0) * SC), al1 = fexp2((m1 - mn1) * SC);
        m0 = mn0; m1 = mn1;
        const float ms0 = mn0 * SC, ms1 = mn1 * SC;

        float rs0 = 0.f, rs1 = 0.f;
        #pragma unroll
        for (int nt = 0; nt < 8; ++nt) {
            float p0 = fexp2(fmaf(s[nt][0], SC, -ms0));
            float p1 = fexp2(fmaf(s[nt][1], SC, -ms0));
            float p2 = fexp2(fmaf(s[nt][2], SC, -ms1));
            float p3 = fexp2(fmaf(s[nt][3], SC, -ms1));
            rs0 += p0 + p1; rs1 += p2 + p3;
            s[nt][0] = p0; s[nt][1] = p1; s[nt][2] = p2; s[nt][3] = p3;
        }
        rs0 += __shfl_xor_sync(0xffffffffu, rs0, 1);
        rs0 += __shfl_xor_sync(0xffffffffu, rs0, 2);
        rs1 += __shfl_xor_sync(0xffffffffu, rs1, 1);
        rs1 += __shfl_xor_sync(0xffffffffu, rs1, 2);
        l0 = l0 * al0 + rs0;
        l1 = l1 * al1 + rs1;

        #pragma unroll
        for (int nt = 0; nt < 8; ++nt) {
            O[nt][0] *= al0; O[nt][1] *= al0;
            O[nt][2] *= al1; O[nt][3] *= al1;
        }

        // ---- O += P V ----
        #pragma unroll
        for (int kk = 0; kk < 4; ++kk) {
            uint32_t a0 = packh2(s[2*kk][0],   s[2*kk][1]);
            uint32_t a1 = packh2(s[2*kk][2],   s[2*kk][3]);
            uint32_t a2 = packh2(s[2*kk+1][0], s[2*kk+1][1]);
            uint32_t a3 = packh2(s[2*kk+1][2], s[2*kk+1][3]);
            #pragma unroll
            for (int i = 0; i < 4; ++i) {
                const int key = 16 * kk + vKeyLoc;
                const uint32_t dblk = (uint32_t)(((2 * i + vL16) ^ vL7) * 16);
                uint32_t t0, t1, t2, t3;
                ldmx4t(t0, t1, t2, t3, vsb + (uint32_t)(key * 128) + dblk);
                mma_f16(O[2*i][0], O[2*i][1], O[2*i][2], O[2*i][3],
                        a0, a1, a2, a3, t0, t1);
                mma_f16(O[2*i+1][0], O[2*i+1][1], O[2*i+1][2], O[2*i+1][3],
                        a0, a1, a2, a3, t2, t3);
            }
        }
        if (has_next) __syncthreads();
    }

    if (full) {
        float inv0 = 1.0f / l0, inv1 = 1.0f / l1;
        #pragma unroll
        for (int nt = 0; nt < 8; ++nt) {
            int c = h * HSZ + nt * 8 + 2 * tg;
            __half2 o0 = __floats2half2_rn(O[nt][0] * inv0, O[nt][1] * inv0);
            __half2 o1 = __floats2half2_rn(O[nt][2] * inv1, O[nt][3] * inv1);
            *reinterpret_cast<__half2*>(out + (size_t)row0 * DD + c) = o0;
            *reinterpret_cast<__half2*>(out + (size_t)row1 * DD + c) = o1;
        }
    } else {
        const int p = (h * 16 + (qb - 16)) * 2 + seg;
        float* pb = pO + (size_t)p * 4096;
        const int lr0 = w16 + g, lr1 = lr0 + 8;
        #pragma unroll
        for (int nt = 0; nt < 8; ++nt) {
            int c = nt * 8 + 2 * tg;
            *reinterpret_cast<float2*>(pb + lr0 * 64 + c) = make_float2(O[nt][0], O[nt][1]);
            *reinterpret_cast<float2*>(pb + lr1 * 64 + c) = make_float2(O[nt][2], O[nt][3]);
        }
        if (tg == 0) {
            float* mlb = pml + (size_t)p * 128;
            mlb[lr0 * 2]     = m0;   // raw max
            mlb[lr0 * 2 + 1] = l0;
            mlb[lr1 * 2]     = m1;
            mlb[lr1 * 2 + 1] = l1;
        }
    }
}

// ---------------- split-K merge (raw m; scale applied here) ----------------
__global__ __launch_bounds__(128) void flash_merge(
    const float* __restrict__ pO, const float* __restrict__ pml,
    __half* __restrict__ out)
{
    __shared__ float w0s[64], w1s[64];
    const int qb16 = blockIdx.x;
    const int h    = blockIdx.y;
    const int tid  = threadIdx.x;
    const int p0 = (h * 16 + qb16) * 2;
    const int p1 = p0 + 1;
    const float SC = 0.18033688011112042f;

    if (tid < 64) {
        float m0 = pml[(size_t)p0 * 128 + tid * 2];
        float l0 = pml[(size_t)p0 * 128 + tid * 2 + 1];
        float m1 = pml[(size_t)p1 * 128 + tid * 2];
        float l1 = pml[(size_t)p1 * 128 + tid * 2 + 1];
        float M  = fmaxf(m0, m1);
        float w0 = fexp2((m0 - M) * SC), w1 = fexp2((m1 - M) * SC);
        float inv = 1.0f / (w0 * l0 + w1 * l1);
        w0s[tid] = w0 * inv;
        w1s[tid] = w1 * inv;
    }
    __syncthreads();

    const float* b0 = pO + (size_t)p0 * 4096;
    const float* b1 = pO + (size_t)p1 * 4096;
    const int q0 = (16 + qb16) * 64;
    #pragma unroll
    for (int i = 0; i < 8; ++i) {
        int idx = (i * 128 + tid) * 4;
        int r = idx >> 6, c = idx & 63;
        float4 v0 = *reinterpret_cast<const float4*>(b0 + r * 64 + c);
        float4 v1 = *reinterpret_cast<const float4*>(b1 + r * 64 + c);
        float w0 = w0s[r], w1 = w1s[r];
        union { __half2 h[2]; uint2 u; } pk;
        pk.h[0] = __floats2half2_rn(w0 * v0.x + w1 * v1.x, w0 * v0.y + w1 * v1.y);
        pk.h[1] = __floats2half2_rn(w0 * v0.z + w1 * v1.z, w0 * v0.w + w1 * v1.w);
        *reinterpret_cast<uint2*>(out + (size_t)(q0 + r) * DD + h * HSZ + c) = pk.u;
    }
}

// ---------------- launch ----------------
extern "C" void kernel_launch(void* const* d_in, const int* in_sizes, int n_in,
                              void* d_out, int out_size)
{
    const float* x    = (const float*)d_in[0];
    const float* Wq   = (const float*)d_in[1];
    const float* Wk   = (const float*)d_in[2];
    const float* Wv   = (const float*)d_in[3];
    const float* Wo   = (const float*)d_in[4];
    const float* bo   = (const float*)d_in[5];
    const float* W1   = (const float*)d_in[6];
    const float* b1   = (const float*)d_in[7];
    const float* W2   = (const float*)d_in[8];
    const float* b2   = (const float*)d_in[9];
    const float* ln1s = (const float*)d_in[10];
    const float* ln1b = (const float*)d_in[11];
    const float* ln2s = (const float*)d_in[12];
    const float* ln2b = (const float*)d_in[13];
    float* out = (float*)d_out;

    __half *h, *wqkvT, *woT, *w1T, *w2T, *att, *ff, *qkv;
    float *x2, *pO, *pml;
    cudaGetSymbolAddress((void**)&h,     g_h);
    cudaGetSymbolAddress((void**)&wqkvT, g_wqkvT);
    cudaGetSymbolAddress((void**)&woT,   g_WoT);
    cudaGetSymbolAddress((void**)&w1T,   g_W1T);
    cudaGetSymbolAddress((void**)&w2T,   g_W2T);
    cudaGetSymbolAddress((void**)&qkv,   g_qkv);
    cudaGetSymbolAddress((void**)&att,   g_att);
    cudaGetSymbolAddress((void**)&x2,    g_x2);
    cudaGetSymbolAddress((void**)&ff,    g_ff);
    cudaGetSymbolAddress((void**)&pO,    g_pO);
    cudaGetSymbolAddress((void**)&pml,   g_pml);

    cudaFuncSetAttribute(flash_tc, cudaFuncAttributeMaxDynamicSharedMemorySize, FA_SMEM);
    cudaFuncSetAttribute(tg2<0>, cudaFuncAttributeMaxDynamicSharedMemorySize, TG_SMEM);
    cudaFuncSetAttribute(tg2<1>, cudaFuncAttributeMaxDynamicSharedMemorySize, TG_SMEM);
    cudaFuncSetAttribute(tg2<2>, cudaFuncAttributeMaxDynamicSharedMemorySize, TG_SMEM);

    // 1. prep: weight transposes + LN1 (one launch)
    prep_kernel<<<12288 + 2048, 256>>>(Wq, Wk, Wv, Wo, W1, W2,
                                       wqkvT, woT, w1T, w2T,
                                       x, ln1s, ln1b, h);
    // 2. QKV GEMM (fp16 out)
    tg2<0><<<dim3(3 * DD / 128, TT / 128), 256, TG_SMEM>>>(
        TT, 3 * DD, DD, h, wqkvT, nullptr, nullptr, qkv);
    // 3. flash attention split-K, work-sorted 1D grid
    flash_tc<<<768, 128, FA_SMEM>>>(qkv, att, pO, pml);
    flash_merge<<<dim3(16, HH), 128>>>(pO, pml, att);
    // 4. output proj + bias + residual (fp32 out)
    tg2<1><<<dim3(DD / 128, TT / 128), 256, TG_SMEM>>>(
        TT, DD, DD, att, woT, bo, x, x2);
    // 5. LN2 -> fp16
    ln_kernel<<<TT, 256>>>(x2, ln2s, ln2b, h);
    // 6. FFN1 (relu, fp16 out)
    tg2<2><<<dim3(DFF / 128, TT / 128), 256, TG_SMEM>>>(
        TT, DFF, DD, h, w1T, b1, nullptr, ff);
    // 7. FFN2 (fp32 out)
    tg2<1><<<dim3(DD / 128, TT / 128), 256, TG_SMEM>>>(
        TT, DD, DFF, ff, w2T, b2, x2, out);
}

// round 16
// speedup vs baseline: 2.5723x; 1.0003x over previous
#include <cuda_runtime.h>
#include <cuda_fp16.h>
#include <cstdint>

#define TT 2048
#define DD 1024
#define HH 16
#define HSZ 64
#define DFF 4096

// ---------------- scratch (no allocs allowed) ----------------
__device__ __half g_h[TT * DD];            // LN output (fp16)
__device__ __half g_wqkvT[3 * DD * DD];    // QKV weights, [3D][D] K-major (fp16)
__device__ __half g_WoT[DD * DD];          // Wo^T (fp16)
__device__ __half g_W1T[DD * DFF];         // W1^T (fp16)
__device__ __half g_W2T[DFF * DD];         // W2^T (fp16)
__device__ __half g_qkv[TT * 3 * DD];      // QKV activations (fp16)
__device__ __half g_att[TT * DD];          // attention output (fp16)
__device__ float  g_x2[TT * DD];           // residual after attention (fp32)
__device__ __half g_ff[TT * DFF];          // FFN hidden (fp16)
__device__ float  g_pO[16 * 16 * 2 * 64 * 64];   // split-K partials
__device__ float  g_pml[16 * 16 * 2 * 64 * 2];   // raw (m, l)

// ---------------- helpers ----------------
__device__ __forceinline__ uint32_t smem_u32(const void* p) {
    return (uint32_t)__cvta_generic_to_shared(p);
}
__device__ __forceinline__ uint32_t swz(uint32_t off) {
    return off ^ ((off >> 3) & 0x70);
}
__device__ __forceinline__ void mma_f16(
    float& d0, float& d1, float& d2, float& d3,
    uint32_t a0, uint32_t a1, uint32_t a2, uint32_t a3,
    uint32_t b0, uint32_t b1)
{
    asm volatile(
        "mma.sync.aligned.m16n8k16.row.col.f32.f16.f16.f32 "
        "{%0,%1,%2,%3}, {%4,%5,%6,%7}, {%8,%9}, {%0,%1,%2,%3};\n"
        : "+f"(d0), "+f"(d1), "+f"(d2), "+f"(d3)
        : "r"(a0), "r"(a1), "r"(a2), "r"(a3), "r"(b0), "r"(b1));
}
__device__ __forceinline__ void ldmx4(
    uint32_t& r0, uint32_t& r1, uint32_t& r2, uint32_t& r3, uint32_t addr)
{
    asm volatile("ldmatrix.sync.aligned.m8n8.x4.shared.b16 {%0,%1,%2,%3}, [%4];"
                 : "=r"(r0), "=r"(r1), "=r"(r2), "=r"(r3) : "r"(addr) : "memory");
}
__device__ __forceinline__ void ldmx4t(
    uint32_t& r0, uint32_t& r1, uint32_t& r2, uint32_t& r3, uint32_t addr)
{
    asm volatile("ldmatrix.sync.aligned.m8n8.x4.trans.shared.b16 {%0,%1,%2,%3}, [%4];"
                 : "=r"(r0), "=r"(r1), "=r"(r2), "=r"(r3) : "r"(addr) : "memory");
}
__device__ __forceinline__ void cpasync16(uint32_t saddr, const void* gaddr) {
    asm volatile("cp.async.cg.shared.global [%0], [%1], 16;" :: "r"(saddr), "l"(gaddr));
}
__device__ __forceinline__ uint32_t packh2(float lo, float hi) {
    __half2 h = __floats2half2_rn(lo, hi);
    return *reinterpret_cast<uint32_t*>(&h);
}
#define CP_COMMIT() asm volatile("cp.async.commit_group;" ::: "memory")
#define CP_WAIT(n)  asm volatile("cp.async.wait_group %0;" :: "n"(n) : "memory")

// ---------------- fast exp2 (fma pipe) ----------------
__device__ __forceinline__ float fexp2(float x) {
    x = fmaxf(x, -120.f);
    float k  = __fadd_rn(x, 12582912.f);
    int   sc = __float_as_int(k) << 23;
    float f  = __fsub_rn(x, __fsub_rn(k, 12582912.f));
    float p  = 0.0013333558f;
    p = fmaf(p, f, 0.0096181291f);
    p = fmaf(p, f, 0.0555041087f);
    p = fmaf(p, f, 0.2402265070f);
    p = fmaf(p, f, 0.6931471806f);
    p = fmaf(p, f, 1.0f);
    return __int_as_float(__float_as_int(p) + sc);
}

// ---------------- LayerNorm row (device fn, emits fp16) ----------------
__device__ __forceinline__ void ln_row(
    const float* __restrict__ x, const float* __restrict__ g,
    const float* __restrict__ b, __half* __restrict__ y, int row, int tid)
{
    float4 v = reinterpret_cast<const float4*>(x + (size_t)row * DD)[tid];
    float s  = v.x + v.y + v.z + v.w;
    float ss = v.x * v.x + v.y * v.y + v.z * v.z + v.w * v.w;
    #pragma unroll
    for (int o = 16; o > 0; o >>= 1) {
        s  += __shfl_xor_sync(0xffffffffu, s, o);
        ss += __shfl_xor_sync(0xffffffffu, ss, o);
    }
    __shared__ float sb[8], ssb[8], stats[2];
    int wid = tid >> 5, lane = tid & 31;
    if (lane == 0) { sb[wid] = s; ssb[wid] = ss; }
    __syncthreads();
    if (tid == 0) {
        float a = 0.f, c = 0.f;
        #pragma unroll
        for (int i = 0; i < 8; i++) { a += sb[i]; c += ssb[i]; }
        float mean = a * (1.0f / DD);
        float var  = c * (1.0f / DD) - mean * mean;
        stats[0] = mean;
        stats[1] = rsqrtf(var + 1e-6f);
    }
    __syncthreads();
    float mean = stats[0], rstd = stats[1];
    float4 gg = reinterpret_cast<const float4*>(g)[tid];
    float4 bb = reinterpret_cast<const float4*>(b)[tid];
    union { __half2 h[2]; uint2 u; } pk;
    pk.h[0] = __floats2half2_rn((v.x - mean) * rstd * gg.x + bb.x,
                                (v.y - mean) * rstd * gg.y + bb.y);
    pk.h[1] = __floats2half2_rn((v.z - mean) * rstd * gg.z + bb.z,
                                (v.w - mean) * rstd * gg.w + bb.w);
    reinterpret_cast<uint2*>(y + (size_t)row * DD)[tid] = pk.u;
}

__global__ __launch_bounds__(256) void ln_kernel(
    const float* __restrict__ x, const float* __restrict__ g,
    const float* __restrict__ b, __half* __restrict__ y)
{
    ln_row(x, g, b, y, blockIdx.x, threadIdx.x);
}

// ---------------- prep: weight transposes + LN1 in ONE launch ----------------
// blocks [0,12288): transposes.  [12288, 12288+2048): LN1 rows.
__global__ __launch_bounds__(256) void prep_kernel(
    const float* __restrict__ Wq, const float* __restrict__ Wk,
    const float* __restrict__ Wv, const float* __restrict__ Wo,
    const float* __restrict__ W1, const float* __restrict__ W2,
    __half* __restrict__ wqkvT, __half* __restrict__ woT,
    __half* __restrict__ w1T, __half* __restrict__ w2T,
    const float* __restrict__ x, const float* __restrict__ ln1s,
    const float* __restrict__ ln1b, __half* __restrict__ hout)
{
    const int b = blockIdx.x;
    if (b >= 12288) {
        ln_row(x, ln1s, ln1b, hout, b - 12288, threadIdx.x);
        return;
    }
    __shared__ float t[32][33];
    const float* ip; __half* op;
    int R, C, bx, by;
    if (b < 3072) {
        const int w = b >> 10;
        const int r = b & 1023;
        const int head = r >> 6;
        const int rr = r & 63;
        bx = (rr & 1) * 32;
        by = (rr >> 1) * 32;
        ip = (w == 0 ? Wq : (w == 1 ? Wk : Wv)) + (size_t)head * DD * HSZ;
        op = wqkvT + (size_t)w * DD * DD + (size_t)head * HSZ * DD;
        R = DD; C = HSZ;
    } else if (b < 4096) {
        const int r = b - 3072;
        bx = (r & 31) * 32; by = (r >> 5) * 32;
        ip = Wo; op = woT; R = DD; C = DD;
    } else if (b < 8192) {
        const int r = b - 4096;
        bx = (r & 127) * 32; by = (r >> 7) * 32;
        ip = W1; op = w1T; R = DD; C = DFF;
    } else {
        const int r = b - 8192;
        bx = (r & 31) * 32; by = (r >> 5) * 32;
        ip = W2; op = w2T; R = DFF; C = DD;
    }
    const int x_ = threadIdx.x & 31, y_ = threadIdx.x >> 5;
    #pragma unroll
    for (int j = 0; j < 32; j += 8)
        t[y_ + j][x_] = ip[(size_t)(by + y_ + j) * C + bx + x_];
    __syncthreads();
    #pragma unroll
    for (int j = 0; j < 32; j += 8)
        op[(size_t)(bx + y_ + j) * R + by + x_] = __float2half_rn(t[x_][y_ + j]);
}

// ---------------- fp16 mma.sync GEMM (frozen) ----------------
#define TG_STAGE 32768
#define TG_SMEM  (3 * TG_STAGE)

template <int EPI>
__global__ __launch_bounds__(256, 1) void tg2(
    int M, int N, int K,
    const __half* __restrict__ A, const __half* __restrict__ Bt,
    const float* __restrict__ bias, const float* __restrict__ resid,
    void* __restrict__ Cv)
{
    extern __shared__ float dynsm[];
    const int tid  = threadIdx.x;
    const int warp = tid >> 5, lane = tid & 31;
    const int wm = warp & 1, wn = warp >> 1;
    const int g = lane >> 2, tg = lane & 3;
    const int brow = blockIdx.y, bcol = blockIdx.x;

    const uint32_t sbase = smem_u32(dynsm);
    const int r0 = tid >> 3;
    const int ck = tid & 7;
    const __half* Ab = A  + (size_t)(brow * 128) * K + ck * 8;
    const __half* Bb = Bt + (size_t)(bcol * 128) * K + ck * 8;
    const int KT = K >> 6;

    const int aRow = (lane & 7) + ((lane >> 3) & 1) * 8;
    const int aChk = (lane >> 4);
    const int bRow = (lane & 7) + (lane >> 4) * 8;
    const int bChk = (lane >> 3) & 1;

    float acc[4][4][4];
    #pragma unroll
    for (int mt = 0; mt < 4; mt++)
        #pragma unroll
        for (int nt = 0; nt < 4; nt++)
            #pragma unroll
            for (int i = 0; i < 4; i++) acc[mt][nt][i] = 0.f;

    auto load_stage = [&](int kt, int s) {
        const uint32_t sA = sbase + s * TG_STAGE;
        const uint32_t sB = sA + 16384;
        const int k0 = kt * 64;
        #pragma unroll
        for (int j = 0; j < 4; ++j) {
            const int r = j * 32 + r0;
            const uint32_t off = swz((uint32_t)(r * 128 + ck * 16));
            cpasync16(sA + off, Ab + (size_t)r * K + k0);
            cpasync16(sB + off, Bb + (size_t)r * K + k0);
        }
        CP_COMMIT();
    };

    load_stage(0, 0);
    if (KT > 1) load_stage(1, 1);

    for (int kt = 0; kt < KT; ++kt) {
        if (kt + 1 < KT) CP_WAIT(1); else CP_WAIT(0);
        __syncthreads();
        if (kt + 2 < KT) load_stage(kt + 2, (kt + 2) % 3);

        const uint32_t sA = sbase + (kt % 3) * TG_STAGE;
        const uint32_t sB = sA + 16384;

        #pragma unroll
        for (int ks = 0; ks < 4; ++ks) {
            uint32_t af[4][4];
            #pragma unroll
            for (int mt = 0; mt < 4; ++mt) {
                const int row = wm * 64 + mt * 16 + aRow;
                const uint32_t ad = sA + swz((uint32_t)(row * 128 + ks * 32 + aChk * 16));
                ldmx4(af[mt][0], af[mt][1], af[mt][2], af[mt][3], ad);
            }
            uint32_t bf[4][2];
            #pragma unroll
            for (int np = 0; np < 2; ++np) {
                const int nrow = wn * 32 + np * 16 + bRow;
                const uint32_t bd = sB + swz((uint32_t)(nrow * 128 + ks * 32 + bChk * 16));
                uint32_t t0, t1, t2, t3;
                ldmx4(t0, t1, t2, t3, bd);
                bf[np * 2][0] = t0;     bf[np * 2][1] = t1;
                bf[np * 2 + 1][0] = t2; bf[np * 2 + 1][1] = t3;
            }
            #pragma unroll
            for (int mt = 0; mt < 4; ++mt)
                #pragma unroll
                for (int nt = 0; nt < 4; ++nt)
                    mma_f16(acc[mt][nt][0], acc[mt][nt][1],
                            acc[mt][nt][2], acc[mt][nt][3],
                            af[mt][0], af[mt][1], af[mt][2], af[mt][3],
                            bf[nt][0], bf[nt][1]);
        }
    }

    #pragma unroll
    for (int mt = 0; mt < 4; mt++) {
        const int r0g = brow * 128 + wm * 64 + mt * 16 + g;
        const int r1g = r0g + 8;
        #pragma unroll
        for (int nt = 0; nt < 4; nt++) {
            const int c = bcol * 128 + wn * 32 + nt * 8 + tg * 2;
            float2 o0 = make_float2(acc[mt][nt][0], acc[mt][nt][1]);
            float2 o1 = make_float2(acc[mt][nt][2], acc[mt][nt][3]);
            if constexpr (EPI >= 1) {
                float2 bv = *reinterpret_cast<const float2*>(bias + c);
                o0.x += bv.x; o0.y += bv.y;
                o1.x += bv.x; o1.y += bv.y;
            }
            if constexpr (EPI == 1) {
                float2 rv0 = *reinterpret_cast<const float2*>(resid + (size_t)r0g * N + c);
                float2 rv1 = *reinterpret_cast<const float2*>(resid + (size_t)r1g * N + c);
                o0.x += rv0.x; o0.y += rv0.y;
                o1.x += rv1.x; o1.y += rv1.y;
                float* C = (float*)Cv;
                *reinterpret_cast<float2*>(C + (size_t)r0g * N + c) = o0;
                *reinterpret_cast<float2*>(C + (size_t)r1g * N + c) = o1;
            } else {
                if constexpr (EPI == 2) {
                    o0.x = fmaxf(o0.x, 0.f); o0.y = fmaxf(o0.y, 0.f);
                    o1.x = fmaxf(o1.x, 0.f); o1.y = fmaxf(o1.y, 0.f);
                }
                __half* C = (__half*)Cv;
                __half2 h0 = __floats2half2_rn(o0.x, o0.y);
                __half2 h1 = __floats2half2_rn(o1.x, o1.y);
                *reinterpret_cast<__half2*>(C + (size_t)r0g * N + c) = h0;
                *reinterpret_cast<__half2*>(C + (size_t)r1g * N + c) = h1;
            }
        }
    }
}

// ---------------- flash attention v8 ----------------
// fp16 mma, split-K, K/V double buffer, work-sorted 1D grid,
// diagonal-only masking, raw-domain max with scale fused into exp.
#define FA_SMEM (5 * 64 * 128)    // 40 KB

__global__ __launch_bounds__(128, 4) void flash_tc(
    const __half* __restrict__ qkv, __half* __restrict__ out,
    float* __restrict__ pO, float* __restrict__ pml)
{
    extern __shared__ char fsm[];
    const uint32_t qsb = smem_u32(fsm);
    const int tid  = threadIdx.x;
    const int warp = tid >> 5;
    const int lane = tid & 31;
    const int g    = lane >> 2;
    const int tg   = lane & 3;

    // ---- work-sorted block id -> (h, qb, seg) ----
    const int id = blockIdx.x;     // 0..767
    int qb, seg, h;
    if (id < 256) {                              // 256 heavy seg0 (16 tiles)
        h = id & 15; qb = 16 + (id >> 4); seg = 0;
    } else {                                     // groups of 32, size desc 16..1
        const int id2 = id - 256;
        const int s = 16 - (id2 >> 5);
        const int j = id2 & 31;
        if (j < 16) { h = j;      qb = 15 + s; seg = 1; }   // seg1, size s
        else        { h = j - 16; qb = s - 1;  seg = 0; }   // full block, size s
    }
    const int q0   = qb * 64;
    const int w16  = warp * 16;
    const int kt0  = seg * 16;
    const int kt1  = min(qb + 1, kt0 + 16);
    const bool full = (kt0 == 0) && (kt1 == qb + 1);

    const int aRow = (lane & 7) + ((lane >> 3) & 1) * 8;
    const int aChk = lane >> 4;
    const int bRow = (lane & 7) + (lane >> 4) * 8;
    const int bChk = (lane >> 3) & 1;
    const int vKeyLoc = ((lane >> 3) & 1) * 8 + (lane & 7);
    const int vL7  = lane & 7;
    const int vL16 = lane >> 4;

    const __half* qp = qkv + h * HSZ;
    const __half* kp = qkv + DD + h * HSZ;
    const __half* vp = qkv + 2 * DD + h * HSZ;

    auto load_kv = [&](int kt, int b) {
        const uint32_t kb = qsb + 8192 + b * 16384;
        const uint32_t vb = kb + 8192;
        #pragma unroll
        for (int j = 0; j < 4; ++j) {
            int idx = j * 128 + tid;
            int r = idx >> 3, ck = idx & 7;
            size_t gi = (size_t)(kt * 64 + r) * (3 * DD) + ck * 8;
            uint32_t off = swz((uint32_t)(r * 128 + ck * 16));
            cpasync16(kb + off, kp + gi);
            cpasync16(vb + off, vp + gi);
        }
        CP_COMMIT();
    };

    {   // Q tile
        #pragma unroll
        for (int j = 0; j < 4; ++j) {
            int idx = j * 128 + tid;
            int r = idx >> 3, ck = idx & 7;
            cpasync16(qsb + swz((uint32_t)(r * 128 + ck * 16)),
                      qp + (size_t)(q0 + r) * (3 * DD) + ck * 8);
        }
        CP_COMMIT();
    }
    load_kv(kt0, kt0 & 1);

    float O[8][4];
    #pragma unroll
    for (int nt = 0; nt < 8; nt++)
        #pragma unroll
        for (int i = 0; i < 4; i++) O[nt][i] = 0.f;
    float m0 = -1e30f, m1 = -1e30f, l0 = 0.f, l1 = 0.f;   // raw-domain max

    const int row0 = q0 + w16 + g;
    const int row1 = row0 + 8;
    const float SC = 0.18033688011112042f;   // (1/8) * log2(e)

    for (int kt = kt0; kt < kt1; ++kt) {
        const bool has_next = (kt + 1 < kt1);
        if (has_next) load_kv(kt + 1, (kt + 1) & 1);
        if (has_next) CP_WAIT(1); else CP_WAIT(0);
        __syncthreads();

        const uint32_t ksb = qsb + 8192 + (kt & 1) * 16384;
        const uint32_t vsb = ksb + 8192;

        // ---- S = Q K^T ----
        float s[8][4];
        #pragma unroll
        for (int nt = 0; nt < 8; nt++)
            #pragma unroll
            for (int i = 0; i < 4; i++) s[nt][i] = 0.f;

        #pragma unroll
        for (int kk = 0; kk < 4; ++kk) {
            uint32_t a0, a1, a2, a3;
            ldmx4(a0, a1, a2, a3,
                  qsb + swz((uint32_t)((w16 + aRow) * 128 + kk * 32 + aChk * 16)));
            uint32_t bf[8][2];
            #pragma unroll
            for (int n16 = 0; n16 < 4; ++n16) {
                uint32_t t0, t1, t2, t3;
                ldmx4(t0, t1, t2, t3,
                      ksb + swz((uint32_t)((n16 * 16 + bRow) * 128 + kk * 32 + bChk * 16)));
                bf[n16 * 2][0] = t0;     bf[n16 * 2][1] = t1;
                bf[n16 * 2 + 1][0] = t2; bf[n16 * 2 + 1][1] = t3;
            }
            #pragma unroll
            for (int nt = 0; nt < 8; ++nt)
                mma_f16(s[nt][0], s[nt][1], s[nt][2], s[nt][3],
                        a0, a1, a2, a3, bf[nt][0], bf[nt][1]);
        }

        // ---- causal mask: ONLY the diagonal tile has masked elements ----
        if (kt == qb) {
            #pragma unroll
            for (int nt = 0; nt < 8; ++nt) {
                int c0 = kt * 64 + nt * 8 + 2 * tg;
                if (c0     > row0) s[nt][0] = -1e30f;
                if (c0 + 1 > row0) s[nt][1] = -1e30f;
                if (c0     > row1) s[nt][2] = -1e30f;
                if (c0 + 1 > row1) s[nt][3] = -1e30f;
            }
        }

        // ---- raw-domain row max ----
        float mb0 = -1e30f, mb1 = -1e30f;
        #pragma unroll
        for (int nt = 0; nt < 8; ++nt) {
            mb0 = fmaxf(mb0, fmaxf(s[nt][0], s[nt][1]));
            mb1 = fmaxf(mb1, fmaxf(s[nt][2], s[nt][3]));
        }
        mb0 = fmaxf(mb0, __shfl_xor_sync(0xffffffffu, mb0, 1));
        mb0 = fmaxf(mb0, __shfl_xor_sync(0xffffffffu, mb0, 2));
        mb1 = fmaxf(mb1, __shfl_xor_sync(0xffffffffu, mb1, 1));
        mb1 = fmaxf(mb1, __shfl_xor_sync(0xffffffffu, mb1, 2));

        float mn0 = fmaxf(m0, mb0), mn1 = fmaxf(m1, mb1);
        float al0 = fexp2((m0 - mn0) * SC), al1 = fexp2((m1 - mn1) * SC);
        m0 = mn0; m1 = mn1;
        const float ms0 = mn0 * SC, ms1 = mn1 * SC;

        float rs0 = 0.f, rs1 = 0.f;
        #pragma unroll
        for (int nt = 0; nt < 8; ++nt) {
            float p0 = fexp2(fmaf(s[nt][0], SC, -ms0));
            float p1 = fexp2(fmaf(s[nt][1], SC, -ms0));
            float p2 = fexp2(fmaf(s[nt][2], SC, -ms1));
            float p3 = fexp2(fmaf(s[nt][3], SC, -ms1));
            rs0 += p0 + p1; rs1 += p2 + p3;
            s[nt][0] = p0; s[nt][1] = p1; s[nt][2] = p2; s[nt][3] = p3;
        }
        rs0 += __shfl_xor_sync(0xffffffffu, rs0, 1);
        rs0 += __shfl_xor_sync(0xffffffffu, rs0, 2);
        rs1 += __shfl_xor_sync(0xffffffffu, rs1, 1);
        rs1 += __shfl_xor_sync(0xffffffffu, rs1, 2);
        l0 = l0 * al0 + rs0;
        l1 = l1 * al1 + rs1;

        #pragma unroll
        for (int nt = 0; nt < 8; ++nt) {
            O[nt][0] *= al0; O[nt][1] *= al0;
            O[nt][2] *= al1; O[nt][3] *= al1;
        }

        // ---- O += P V ----
        #pragma unroll
        for (int kk = 0; kk < 4; ++kk) {
            uint32_t a0 = packh2(s[2*kk][0],   s[2*kk][1]);
            uint32_t a1 = packh2(s[2*kk][2],   s[2*kk][3]);
            uint32_t a2 = packh2(s[2*kk+1][0], s[2*kk+1][1]);
            uint32_t a3 = packh2(s[2*kk+1][2], s[2*kk+1][3]);
            #pragma unroll
            for (int i = 0; i < 4; ++i) {
                const int key = 16 * kk + vKeyLoc;
                const uint32_t dblk = (uint32_t)(((2 * i + vL16) ^ vL7) * 16);
                uint32_t t0, t1, t2, t3;
                ldmx4t(t0, t1, t2, t3, vsb + (uint32_t)(key * 128) + dblk);
                mma_f16(O[2*i][0], O[2*i][1], O[2*i][2], O[2*i][3],
                        a0, a1, a2, a3, t0, t1);
                mma_f16(O[2*i+1][0], O[2*i+1][1], O[2*i+1][2], O[2*i+1][3],
                        a0, a1, a2, a3, t2, t3);
            }
        }
        if (has_next) __syncthreads();
    }

    if (full) {
        float inv0 = 1.0f / l0, inv1 = 1.0f / l1;
        #pragma unroll
        for (int nt = 0; nt < 8; ++nt) {
            int c = h * HSZ + nt * 8 + 2 * tg;
            __half2 o0 = __floats2half2_rn(O[nt][0] * inv0, O[nt][1] * inv0);
            __half2 o1 = __floats2half2_rn(O[nt][2] * inv1, O[nt][3] * inv1);
            *reinterpret_cast<__half2*>(out + (size_t)row0 * DD + c) = o0;
            *reinterpret_cast<__half2*>(out + (size_t)row1 * DD + c) = o1;
        }
    } else {
        const int p = (h * 16 + (qb - 16)) * 2 + seg;
        float* pb = pO + (size_t)p * 4096;
        const int lr0 = w16 + g, lr1 = lr0 + 8;
        #pragma unroll
        for (int nt = 0; nt < 8; ++nt) {
            int c = nt * 8 + 2 * tg;
            *reinterpret_cast<float2*>(pb + lr0 * 64 + c) = make_float2(O[nt][0], O[nt][1]);
            *reinterpret_cast<float2*>(pb + lr1 * 64 + c) = make_float2(O[nt][2], O[nt][3]);
        }
        if (tg == 0) {
            float* mlb = pml + (size_t)p * 128;
            mlb[lr0 * 2]     = m0;   // raw max
            mlb[lr0 * 2 + 1] = l0;
            mlb[lr1 * 2]     = m1;
            mlb[lr1 * 2 + 1] = l1;
        }
    }
}

// ---------------- split-K merge (raw m; scale applied here) ----------------
__global__ __launch_bounds__(128) void flash_merge(
    const float* __restrict__ pO, const float* __restrict__ pml,
    __half* __restrict__ out)
{
    __shared__ float w0s[64], w1s[64];
    const int qb16 = blockIdx.x;
    const int h    = blockIdx.y;
    const int tid  = threadIdx.x;
    const int p0 = (h * 16 + qb16) * 2;
    const int p1 = p0 + 1;
    const float SC = 0.18033688011112042f;

    if (tid < 64) {
        float m0 = pml[(size_t)p0 * 128 + tid * 2];
        float l0 = pml[(size_t)p0 * 128 + tid * 2 + 1];
        float m1 = pml[(size_t)p1 * 128 + tid * 2];
        float l1 = pml[(size_t)p1 * 128 + tid * 2 + 1];
        float M  = fmaxf(m0, m1);
        float w0 = fexp2((m0 - M) * SC), w1 = fexp2((m1 - M) * SC);
        float inv = 1.0f / (w0 * l0 + w1 * l1);
        w0s[tid] = w0 * inv;
        w1s[tid] = w1 * inv;
    }
    __syncthreads();

    const float* b0 = pO + (size_t)p0 * 4096;
    const float* b1 = pO + (size_t)p1 * 4096;
    const int q0 = (16 + qb16) * 64;
    #pragma unroll
    for (int i = 0; i < 8; ++i) {
        int idx = (i * 128 + tid) * 4;
        int r = idx >> 6, c = idx & 63;
        float4 v0 = *reinterpret_cast<const float4*>(b0 + r * 64 + c);
        float4 v1 = *reinterpret_cast<const float4*>(b1 + r * 64 + c);
        float w0 = w0s[r], w1 = w1s[r];
        union { __half2 h[2]; uint2 u; } pk;
        pk.h[0] = __floats2half2_rn(w0 * v0.x + w1 * v1.x, w0 * v0.y + w1 * v1.y);
        pk.h[1] = __floats2half2_rn(w0 * v0.z + w1 * v1.z, w0 * v0.w + w1 * v1.w);
        *reinterpret_cast<uint2*>(out + (size_t)(q0 + r) * DD + h * HSZ + c) = pk.u;
    }
}

// ---------------- launch ----------------
extern "C" void kernel_launch(void* const* d_in, const int* in_sizes, int n_in,
                              void* d_out, int out_size)
{
    const float* x    = (const float*)d_in[0];
    const float* Wq   = (const float*)d_in[1];
    const float* Wk   = (const float*)d_in[2];
    const float* Wv   = (const float*)d_in[3];
    const float* Wo   = (const float*)d_in[4];
    const float* bo   = (const float*)d_in[5];
    const float* W1   = (const float*)d_in[6];
    const float* b1   = (const float*)d_in[7];
    const float* W2   = (const float*)d_in[8];
    const float* b2   = (const float*)d_in[9];
    const float* ln1s = (const float*)d_in[10];
    const float* ln1b = (const float*)d_in[11];
    const float* ln2s = (const float*)d_in[12];
    const float* ln2b = (const float*)d_in[13];
    float* out = (float*)d_out;

    __half *h, *wqkvT, *woT, *w1T, *w2T, *att, *ff, *qkv;
    float *x2, *pO, *pml;
    cudaGetSymbolAddress((void**)&h,     g_h);
    cudaGetSymbolAddress((void**)&wqkvT, g_wqkvT);
    cudaGetSymbolAddress((void**)&woT,   g_WoT);
    cudaGetSymbolAddress((void**)&w1T,   g_W1T);
    cudaGetSymbolAddress((void**)&w2T,   g_W2T);
    cudaGetSymbolAddress((void**)&qkv,   g_qkv);
    cudaGetSymbolAddress((void**)&att,   g_att);
    cudaGetSymbolAddress((void**)&x2,    g_x2);
    cudaGetSymbolAddress((void**)&ff,    g_ff);
    cudaGetSymbolAddress((void**)&pO,    g_pO);
    cudaGetSymbolAddress((void**)&pml,   g_pml);

    cudaFuncSetAttribute(flash_tc, cudaFuncAttributeMaxDynamicSharedMemorySize, FA_SMEM);
    cudaFuncSetAttribute(tg2<0>, cudaFuncAttributeMaxDynamicSharedMemorySize, TG_SMEM);
    cudaFuncSetAttribute(tg2<1>, cudaFuncAttributeMaxDynamicSharedMemorySize, TG_SMEM);
    cudaFuncSetAttribute(tg2<2>, cudaFuncAttributeMaxDynamicSharedMemorySize, TG_SMEM);

    // 1. prep: weight transposes + LN1 (one launch)
    prep_kernel<<<12288 + 2048, 256>>>(Wq, Wk, Wv, Wo, W1, W2,
                                       wqkvT, woT, w1T, w2T,
                                       x, ln1s, ln1b, h);
    // 2. QKV GEMM (fp16 out)
    tg2<0><<<dim3(3 * DD / 128, TT / 128), 256, TG_SMEM>>>(
        TT, 3 * DD, DD, h, wqkvT, nullptr, nullptr, qkv);
    // 3. flash attention split-K, work-sorted 1D grid
    flash_tc<<<768, 128, FA_SMEM>>>(qkv, att, pO, pml);
    flash_merge<<<dim3(16, HH), 128>>>(pO, pml, att);
    // 4. output proj + bias + residual (fp32 out)
    tg2<1><<<dim3(DD / 128, TT / 128), 256, TG_SMEM>>>(
        TT, DD, DD, att, woT, bo, x, x2);
    // 5. LN2 -> fp16
    ln_kernel<<<TT, 256>>>(x2, ln2s, ln2b, h);
    // 6. FFN1 (relu, fp16 out)
    tg2<2><<<dim3(DFF / 128, TT / 128), 256, TG_SMEM>>>(
        TT, DFF, DD, h, w1T, b1, nullptr, ff);
    // 7. FFN2 (fp32 out)
    tg2<1><<<dim3(DD / 128, TT / 128), 256, TG_SMEM>>>(
        TT, DD, DFF, ff, w2T, b2, x2, out);
}